// round 4
// baseline (speedup 1.0000x reference)
#include <cuda_runtime.h>
#include <cuda_bf16.h>
#include <cstdint>
#include <math.h>

// Problem dims (fixed by the reference)
#define BB    4
#define TSEQ  2048
#define CDIM  1024
#define HEADS 16
#define DHEAD 64
#define MTOT  (BB * TSEQ)     // 8192
#define FDIM  (4 * CDIM)      // 4096

typedef __nv_bfloat16 bf16;
typedef __nv_bfloat162 bf162;

// -------------------- scratch (device globals; no allocs allowed) ---------
__device__ bf16  g_hhi [MTOT * CDIM];   // LN out hi (reused LN1/LN2)
__device__ bf16  g_hlo [MTOT * CDIM];
__device__ float g_q   [MTOT * CDIM];
__device__ float g_k   [MTOT * CDIM];
__device__ float g_v   [MTOT * CDIM];
__device__ bf16  g_ahi [MTOT * CDIM];   // attention out hi/lo
__device__ bf16  g_alo [MTOT * CDIM];
__device__ float g_x1  [MTOT * CDIM];
__device__ bf16  g_ffhi[MTOT * FDIM];
__device__ bf16  g_fflo[MTOT * FDIM];
// split weights (row-major [K][N], same layout as inputs)
__device__ bf16 g_Wqhi[CDIM * CDIM], g_Wqlo[CDIM * CDIM];
__device__ bf16 g_Wkhi[CDIM * CDIM], g_Wklo[CDIM * CDIM];
__device__ bf16 g_Wvhi[CDIM * CDIM], g_Wvlo[CDIM * CDIM];
__device__ bf16 g_Wohi[CDIM * CDIM], g_Wolo[CDIM * CDIM];
__device__ bf16 g_W1hi[CDIM * FDIM], g_W1lo[CDIM * FDIM];
__device__ bf16 g_W2hi[FDIM * CDIM], g_W2lo[FDIM * CDIM];

// ==================== PTX helpers (all plain sm_80+ features) =============
__device__ __forceinline__ uint32_t smem_u32(const void* p) {
    uint32_t a;
    asm("{ .reg .u64 t; cvta.to.shared.u64 t, %1; cvt.u32.u64 %0, t; }"
        : "=r"(a) : "l"(p));
    return a;
}
__device__ __forceinline__ void cp16(uint32_t dst, const void* src) {
    asm volatile("cp.async.cg.shared.global [%0], [%1], 16;"
                 :: "r"(dst), "l"(src));
}
__device__ __forceinline__ void cp_commit() {
    asm volatile("cp.async.commit_group;");
}
template<int N> __device__ __forceinline__ void cp_wait() {
    asm volatile("cp.async.wait_group %0;" :: "n"(N));
}
__device__ __forceinline__ void ldsm_x4(uint32_t* r, uint32_t addr) {
    asm volatile("ldmatrix.sync.aligned.m8n8.x4.shared.b16 {%0,%1,%2,%3}, [%4];"
                 : "=r"(r[0]), "=r"(r[1]), "=r"(r[2]), "=r"(r[3]) : "r"(addr));
}
__device__ __forceinline__ void ldsm_x2t(uint32_t* r, uint32_t addr) {
    asm volatile("ldmatrix.sync.aligned.m8n8.x2.trans.shared.b16 {%0,%1}, [%2];"
                 : "=r"(r[0]), "=r"(r[1]) : "r"(addr));
}
__device__ __forceinline__ void mma_bf16(float* c, const uint32_t* a, const uint32_t* b) {
    asm volatile(
        "mma.sync.aligned.m16n8k16.row.col.f32.bf16.bf16.f32 "
        "{%0,%1,%2,%3}, {%4,%5,%6,%7}, {%8,%9}, {%0,%1,%2,%3};"
        : "+f"(c[0]), "+f"(c[1]), "+f"(c[2]), "+f"(c[3])
        : "r"(a[0]), "r"(a[1]), "r"(a[2]), "r"(a[3]), "r"(b[0]), "r"(b[1]));
}
__device__ __forceinline__ void split1(float v, bf16& h, bf16& l) {
    h = __float2bfloat16_rn(v);
    l = __float2bfloat16_rn(v - __bfloat162float(h));
}

// ==================== bf16x3 mma.sync GEMM =================================
// C[M,N] = A[M,K] @ B[K,N]; A,B pre-split into hi/lo bf16 (row-major).
// 128x128 CTA tile, BK=32, 256 threads (2x4 warps, 64x32 warp tile),
// double-buffered cp.async.
#define GT 256
#define A_TILE 10240   // 128 rows x 80B (32 bf16 + 8 pad)
#define B_TILE 8704    // 32 rows x 272B (128 bf16 + 8 pad)
#define OFF_AL 20480
#define OFF_BH 40960
#define OFF_BL 58368
#define GEMM_SMEM 75776

template<bool BIAS, bool RELU, bool RES, bool SPLIT>
__global__ void __launch_bounds__(GT) mma_gemm_kernel(
    const bf16* __restrict__ Ahi, const bf16* __restrict__ Alo,
    const bf16* __restrict__ Bhi, const bf16* __restrict__ Blo,
    const float* __restrict__ bias, const float* __restrict__ res,
    float* __restrict__ Cf, bf16* __restrict__ Chi, bf16* __restrict__ Clo,
    int N, int K)
{
    extern __shared__ char sm[];
    const uint32_t sb = smem_u32(sm);

    const int tid  = threadIdx.x;
    const int lane = tid & 31;
    const int wid  = tid >> 5;
    const int wm = (wid >> 2) * 64;     // warp M offset in tile
    const int wn = (wid & 3) * 32;      // warp N offset in tile
    const int m0 = blockIdx.y * 128;
    const int n0 = blockIdx.x * 128;

    // cp.async mapping
    const int ar0 = tid >> 1;                 // A: 2 chunks/thread: rows tid/2, segs
    const int as0 = (tid & 1) << 1;           // seg 0/2 then +1
    const int br0 = tid >> 4;                 // B: rows tid/16
    const int bs0 = tid & 15;                 // seg

    auto load_stage = [&](int s, int c) {
        const int kc = c << 5;
        const uint32_t aoff = sb + s * A_TILE;
        const uint32_t boff = sb + OFF_BH + s * B_TILE;
        // A: 128 rows x 64B (4 segs); each thread: row=tid/2, segs {as0, as0+1}
        {
            const size_t g = (size_t)(m0 + ar0) * K + kc + as0 * 8;
            const uint32_t so = aoff + ar0 * 80 + as0 * 16;
            cp16(so,       Ahi + g);
            cp16(so + 16,  Ahi + g + 8);
            cp16(so + OFF_AL,      Alo + g);
            cp16(so + OFF_AL + 16, Alo + g + 8);
        }
        // B: 32 rows x 256B (16 segs); each thread: row=tid/16, seg=tid%16, x2 rows
        {
            const size_t g = (size_t)(kc + br0) * N + n0 + bs0 * 8;
            const uint32_t so = boff + br0 * 272 + bs0 * 16;
            cp16(so, Bhi + g);
            cp16(so + (OFF_BL - OFF_BH), Blo + g);
            const size_t g2 = g + (size_t)16 * N;
            const uint32_t so2 = so + 16 * 272;
            cp16(so2, Bhi + g2);
            cp16(so2 + (OFF_BL - OFF_BH), Blo + g2);
        }
    };

    float acc[4][4][4];
    #pragma unroll
    for (int a = 0; a < 4; a++)
        #pragma unroll
        for (int b = 0; b < 4; b++)
            #pragma unroll
            for (int d = 0; d < 4; d++) acc[a][b][d] = 0.f;

    const int NC = K >> 5;
    load_stage(0, 0);
    cp_commit();

    for (int c = 0; c < NC; c++) {
        const int s = c & 1;
        if (c + 1 < NC) {
            load_stage(s ^ 1, c + 1);
            cp_commit();
            cp_wait<1>();
        } else {
            cp_wait<0>();
        }
        __syncthreads();

        const uint32_t aH = sb + s * A_TILE;
        const uint32_t bH = sb + OFF_BH + s * B_TILE;
        #pragma unroll
        for (int ks = 0; ks < 2; ks++) {
            uint32_t bh[4][2], bl[4][2];
            #pragma unroll
            for (int nt = 0; nt < 4; nt++) {
                const uint32_t ba = bH + (ks * 16 + (lane & 15)) * 272
                                       + (wn + nt * 8) * 2;
                ldsm_x2t(bh[nt], ba);
                ldsm_x2t(bl[nt], ba + (OFF_BL - OFF_BH));
            }
            #pragma unroll
            for (int mt = 0; mt < 4; mt++) {
                uint32_t ah[4], al[4];
                const uint32_t aa = aH + (wm + mt * 16 + (lane & 15)) * 80
                                       + (ks * 16 + (lane >> 4) * 8) * 2;
                ldsm_x4(ah, aa);
                ldsm_x4(al, aa + OFF_AL);
                #pragma unroll
                for (int nt = 0; nt < 4; nt++) {
                    mma_bf16(acc[mt][nt], ah, bh[nt]);
                    mma_bf16(acc[mt][nt], ah, bl[nt]);
                    mma_bf16(acc[mt][nt], al, bh[nt]);
                }
            }
        }
        __syncthreads();
    }

    // ---- epilogue ----
    #pragma unroll
    for (int mt = 0; mt < 4; mt++) {
        #pragma unroll
        for (int nt = 0; nt < 4; nt++) {
            #pragma unroll
            for (int half = 0; half < 2; half++) {
                const int row = m0 + wm + mt * 16 + (lane >> 2) + half * 8;
                const int col = n0 + wn + nt * 8 + (lane & 3) * 2;
                float v0 = acc[mt][nt][half * 2 + 0];
                float v1 = acc[mt][nt][half * 2 + 1];
                if (BIAS) { v0 += bias[col]; v1 += bias[col + 1]; }
                if (RELU) { v0 = fmaxf(v0, 0.f); v1 = fmaxf(v1, 0.f); }
                if (RES) {
                    const float2 rr = *(const float2*)&res[(size_t)row * N + col];
                    v0 += rr.x; v1 += rr.y;
                }
                if (SPLIT) {
                    bf16 h0, l0, h1, l1;
                    split1(v0, h0, l0);
                    split1(v1, h1, l1);
                    const bf162 ph = __halves2bfloat162(h0, h1);
                    const bf162 pl = __halves2bfloat162(l0, l1);
                    *(uint32_t*)&Chi[(size_t)row * N + col] = *(const uint32_t*)&ph;
                    *(uint32_t*)&Clo[(size_t)row * N + col] = *(const uint32_t*)&pl;
                } else {
                    float2 o; o.x = v0; o.y = v1;
                    *(float2*)&Cf[(size_t)row * N + col] = o;
                }
            }
        }
    }
}

// ==================== weight split (fp32 -> bf16 hi/lo) ====================
__global__ void __launch_bounds__(256) wsplit_kernel(
    const float* __restrict__ w, bf16* __restrict__ hi, bf16* __restrict__ lo,
    int n4)
{
    for (int i = blockIdx.x * blockDim.x + threadIdx.x; i < n4;
         i += gridDim.x * blockDim.x) {
        const float4 v = ((const float4*)w)[i];
        bf16 h0, h1, h2, h3, l0, l1, l2, l3;
        split1(v.x, h0, l0); split1(v.y, h1, l1);
        split1(v.z, h2, l2); split1(v.w, h3, l3);
        const bf162 ha = __halves2bfloat162(h0, h1);
        const bf162 hb = __halves2bfloat162(h2, h3);
        const bf162 la = __halves2bfloat162(l0, l1);
        const bf162 lb = __halves2bfloat162(l2, l3);
        uint2 uh, ul;
        uh.x = *(const uint32_t*)&ha; uh.y = *(const uint32_t*)&hb;
        ul.x = *(const uint32_t*)&la; ul.y = *(const uint32_t*)&lb;
        *(uint2*)&hi[(size_t)i * 4] = uh;
        *(uint2*)&lo[(size_t)i * 4] = ul;
    }
}

// ==================== LayerNorm (fp32 in -> bf16 hi/lo out) ================
__inline__ __device__ float warp_sum(float v) {
    #pragma unroll
    for (int m = 16; m > 0; m >>= 1) v += __shfl_xor_sync(0xffffffffu, v, m);
    return v;
}

__global__ void __launch_bounds__(256) layernorm_split_kernel(
    const float* __restrict__ x, const float* __restrict__ g,
    const float* __restrict__ bt, bf16* __restrict__ yhi, bf16* __restrict__ ylo)
{
    const int row = blockIdx.x;
    const int tid = threadIdx.x;
    const float4 v = ((const float4*)(x + (size_t)row * CDIM))[tid];

    float s  = v.x + v.y + v.z + v.w;
    float ss = v.x*v.x + v.y*v.y + v.z*v.z + v.w*v.w;

    __shared__ float sh1[8], sh2[8];
    s = warp_sum(s); ss = warp_sum(ss);
    const int w = tid >> 5, l = tid & 31;
    if (l == 0) { sh1[w] = s; sh2[w] = ss; }
    __syncthreads();
    if (w == 0) {
        float a = (l < 8) ? sh1[l] : 0.f;
        float b = (l < 8) ? sh2[l] : 0.f;
        a = warp_sum(a); b = warp_sum(b);
        if (l == 0) { sh1[0] = a; sh2[0] = b; }
    }
    __syncthreads();

    const float mean = sh1[0] * (1.0f / CDIM);
    const float var  = sh2[0] * (1.0f / CDIM) - mean * mean;
    const float inv  = rsqrtf(var + 1e-5f);

    const float4 gv = ((const float4*)g)[tid];
    const float4 bv = ((const float4*)bt)[tid];
    float o0 = (v.x - mean) * inv * gv.x + bv.x;
    float o1 = (v.y - mean) * inv * gv.y + bv.y;
    float o2 = (v.z - mean) * inv * gv.z + bv.z;
    float o3 = (v.w - mean) * inv * gv.w + bv.w;

    bf16 h0, h1, h2, h3, l0, l1, l2, l3;
    split1(o0, h0, l0); split1(o1, h1, l1);
    split1(o2, h2, l2); split1(o3, h3, l3);
    const bf162 ha = __halves2bfloat162(h0, h1);
    const bf162 hb = __halves2bfloat162(h2, h3);
    const bf162 la = __halves2bfloat162(l0, l1);
    const bf162 lb = __halves2bfloat162(l2, l3);
    uint2 uh, ul;
    uh.x = *(const uint32_t*)&ha; uh.y = *(const uint32_t*)&hb;
    ul.x = *(const uint32_t*)&la; ul.y = *(const uint32_t*)&lb;
    *(uint2*)&yhi[(size_t)row * CDIM + tid * 4] = uh;
    *(uint2*)&ylo[(size_t)row * CDIM + tid * 4] = ul;
}

// ==================== Flash attention (causal, fp32, split output) =========
__global__ void __launch_bounds__(256) flash_attn_kernel(
    const float* __restrict__ Q, const float* __restrict__ K,
    const float* __restrict__ V, bf16* __restrict__ Ohi, bf16* __restrict__ Olo)
{
    __shared__ float Qs [64][64];
    __shared__ float KPs[64][64];
    __shared__ float Vs [64][64];

    const int tid = threadIdx.x;
    const int qt = blockIdx.x, hh = blockIdx.y, bb = blockIdx.z;
    const int ty = tid >> 4, tx = tid & 15;

    const size_t baseQ = ((size_t)(bb * TSEQ + qt * 64)) * CDIM + hh * DHEAD;

    #pragma unroll
    for (int it = 0; it < 4; it++) {
        const int idx = it * 256 + tid;
        const int r = idx >> 4;
        const int c = (idx & 15) << 2;
        float4 t = *(const float4*)&Q[baseQ + (size_t)r * CDIM + c];
        t.x *= 0.125f; t.y *= 0.125f; t.z *= 0.125f; t.w *= 0.125f;
        *(float4*)&Qs[r][c] = t;
    }

    float m[4], lsum[4], o[4][4];
    #pragma unroll
    for (int i = 0; i < 4; i++) {
        m[i] = -1e30f; lsum[i] = 0.f;
        #pragma unroll
        for (int j = 0; j < 4; j++) o[i][j] = 0.f;
    }

    for (int kt = 0; kt <= qt; kt++) {
        __syncthreads();
        const size_t baseK = ((size_t)(bb * TSEQ + kt * 64)) * CDIM + hh * DHEAD;
        #pragma unroll
        for (int it = 0; it < 4; it++) {
            const int idx = it * 256 + tid;
            const int r = idx >> 4;
            const int c = (idx & 15) << 2;
            const float4 tk = *(const float4*)&K[baseK + (size_t)r * CDIM + c];
            KPs[c + 0][r] = tk.x;
            KPs[c + 1][r] = tk.y;
            KPs[c + 2][r] = tk.z;
            KPs[c + 3][r] = tk.w;
            const float4 tv = *(const float4*)&V[baseK + (size_t)r * CDIM + c];
            *(float4*)&Vs[r][c] = tv;
        }
        __syncthreads();

        float s[4][4];
        #pragma unroll
        for (int i = 0; i < 4; i++)
            #pragma unroll
            for (int j = 0; j < 4; j++) s[i][j] = 0.f;

        #pragma unroll 16
        for (int d = 0; d < 64; d++) {
            float a[4], b[4];
            #pragma unroll
            for (int i = 0; i < 4; i++) a[i] = Qs[ty * 4 + i][d];
            #pragma unroll
            for (int j = 0; j < 4; j++) b[j] = KPs[d][tx * 4 + j];
            #pragma unroll
            for (int i = 0; i < 4; i++)
                #pragma unroll
                for (int j = 0; j < 4; j++)
                    s[i][j] = fmaf(a[i], b[j], s[i][j]);
        }

        if (kt == qt) {
            #pragma unroll
            for (int i = 0; i < 4; i++)
                #pragma unroll
                for (int j = 0; j < 4; j++)
                    if (tx * 4 + j > ty * 4 + i) s[i][j] = -1e30f;
        }

        float p[4][4];
        #pragma unroll
        for (int i = 0; i < 4; i++) {
            float mx = fmaxf(fmaxf(s[i][0], s[i][1]), fmaxf(s[i][2], s[i][3]));
            #pragma unroll
            for (int off = 1; off < 16; off <<= 1)
                mx = fmaxf(mx, __shfl_xor_sync(0xffffffffu, mx, off));
            const float mn = fmaxf(m[i], mx);
            const float alpha = __expf(m[i] - mn);
            m[i] = mn;
            float rs = 0.f;
            #pragma unroll
            for (int j = 0; j < 4; j++) {
                p[i][j] = __expf(s[i][j] - mn);
                rs += p[i][j];
            }
            #pragma unroll
            for (int off = 1; off < 16; off <<= 1)
                rs += __shfl_xor_sync(0xffffffffu, rs, off);
            lsum[i] = lsum[i] * alpha + rs;
            #pragma unroll
            for (int j = 0; j < 4; j++) o[i][j] *= alpha;
        }

        __syncthreads();
        #pragma unroll
        for (int i = 0; i < 4; i++)
            #pragma unroll
            for (int j = 0; j < 4; j++)
                KPs[ty * 4 + i][tx * 4 + j] = p[i][j];
        __syncthreads();

        #pragma unroll 16
        for (int kk = 0; kk < 64; kk++) {
            float a[4], b[4];
            #pragma unroll
            for (int i = 0; i < 4; i++) a[i] = KPs[ty * 4 + i][kk];
            #pragma unroll
            for (int j = 0; j < 4; j++) b[j] = Vs[kk][tx * 4 + j];
            #pragma unroll
            for (int i = 0; i < 4; i++)
                #pragma unroll
                for (int j = 0; j < 4; j++)
                    o[i][j] = fmaf(a[i], b[j], o[i][j]);
        }
    }

    #pragma unroll
    for (int i = 0; i < 4; i++) {
        const float invl = 1.0f / lsum[i];
        const float v0 = o[i][0] * invl, v1 = o[i][1] * invl;
        const float v2 = o[i][2] * invl, v3 = o[i][3] * invl;
        bf16 h0, h1, h2, h3, l0, l1, l2, l3;
        split1(v0, h0, l0); split1(v1, h1, l1);
        split1(v2, h2, l2); split1(v3, h3, l3);
        const bf162 ha = __halves2bfloat162(h0, h1);
        const bf162 hb = __halves2bfloat162(h2, h3);
        const bf162 la = __halves2bfloat162(l0, l1);
        const bf162 lb = __halves2bfloat162(l2, l3);
        uint2 uh, ul;
        uh.x = *(const uint32_t*)&ha; uh.y = *(const uint32_t*)&hb;
        ul.x = *(const uint32_t*)&la; ul.y = *(const uint32_t*)&lb;
        const size_t off = baseQ + (size_t)(ty * 4 + i) * CDIM + tx * 4;
        *(uint2*)&Ohi[off] = uh;
        *(uint2*)&Olo[off] = ul;
    }
}

// ==================== launch ===============================================
extern "C" void kernel_launch(void* const* d_in, const int* in_sizes, int n_in,
                              void* d_out, int out_size)
{
    (void)in_sizes; (void)n_in; (void)out_size;
    const float* x    = (const float*)d_in[0];
    const float* Wq   = (const float*)d_in[1];
    const float* Wk   = (const float*)d_in[2];
    const float* Wv   = (const float*)d_in[3];
    const float* Wo   = (const float*)d_in[4];
    const float* bo   = (const float*)d_in[5];
    const float* ln1g = (const float*)d_in[6];
    const float* ln1b = (const float*)d_in[7];
    const float* ln2g = (const float*)d_in[8];
    const float* ln2b = (const float*)d_in[9];
    const float* W1   = (const float*)d_in[10];
    const float* b1   = (const float*)d_in[11];
    const float* W2   = (const float*)d_in[12];
    const float* b2   = (const float*)d_in[13];
    float* out = (float*)d_out;

    bf16 *hhi, *hlo, *ahi, *alo, *ffhi, *fflo;
    float *q, *k, *v, *x1;
    bf16 *Wqhi, *Wqlo, *Wkhi, *Wklo, *Wvhi, *Wvlo, *Wohi, *Wolo;
    bf16 *W1hi, *W1lo, *W2hi, *W2lo;
    cudaGetSymbolAddress((void**)&hhi,  g_hhi);
    cudaGetSymbolAddress((void**)&hlo,  g_hlo);
    cudaGetSymbolAddress((void**)&q,    g_q);
    cudaGetSymbolAddress((void**)&k,    g_k);
    cudaGetSymbolAddress((void**)&v,    g_v);
    cudaGetSymbolAddress((void**)&ahi,  g_ahi);
    cudaGetSymbolAddress((void**)&alo,  g_alo);
    cudaGetSymbolAddress((void**)&x1,   g_x1);
    cudaGetSymbolAddress((void**)&ffhi, g_ffhi);
    cudaGetSymbolAddress((void**)&fflo, g_fflo);
    cudaGetSymbolAddress((void**)&Wqhi, g_Wqhi);
    cudaGetSymbolAddress((void**)&Wqlo, g_Wqlo);
    cudaGetSymbolAddress((void**)&Wkhi, g_Wkhi);
    cudaGetSymbolAddress((void**)&Wklo, g_Wklo);
    cudaGetSymbolAddress((void**)&Wvhi, g_Wvhi);
    cudaGetSymbolAddress((void**)&Wvlo, g_Wvlo);
    cudaGetSymbolAddress((void**)&Wohi, g_Wohi);
    cudaGetSymbolAddress((void**)&Wolo, g_Wolo);
    cudaGetSymbolAddress((void**)&W1hi, g_W1hi);
    cudaGetSymbolAddress((void**)&W1lo, g_W1lo);
    cudaGetSymbolAddress((void**)&W2hi, g_W2hi);
    cudaGetSymbolAddress((void**)&W2lo, g_W2lo);

    cudaFuncSetAttribute(mma_gemm_kernel<false, false, false, false>,
                         cudaFuncAttributeMaxDynamicSharedMemorySize, GEMM_SMEM);
    cudaFuncSetAttribute(mma_gemm_kernel<true, false, true, false>,
                         cudaFuncAttributeMaxDynamicSharedMemorySize, GEMM_SMEM);
    cudaFuncSetAttribute(mma_gemm_kernel<true, true, false, true>,
                         cudaFuncAttributeMaxDynamicSharedMemorySize, GEMM_SMEM);

    // 0) split weights to bf16 hi/lo
    wsplit_kernel<<<512, 256>>>(Wq, Wqhi, Wqlo, CDIM * CDIM / 4);
    wsplit_kernel<<<512, 256>>>(Wk, Wkhi, Wklo, CDIM * CDIM / 4);
    wsplit_kernel<<<512, 256>>>(Wv, Wvhi, Wvlo, CDIM * CDIM / 4);
    wsplit_kernel<<<512, 256>>>(Wo, Wohi, Wolo, CDIM * CDIM / 4);
    wsplit_kernel<<<1024, 256>>>(W1, W1hi, W1lo, CDIM * FDIM / 4);
    wsplit_kernel<<<1024, 256>>>(W2, W2hi, W2lo, FDIM * CDIM / 4);

    const dim3 gc(CDIM / 128, MTOT / 128);   // (8, 64)
    const dim3 gf(FDIM / 128, MTOT / 128);   // (32, 64)

    // 1) h = LN1(x), split
    layernorm_split_kernel<<<MTOT, 256>>>(x, ln1g, ln1b, hhi, hlo);
    // 2) q,k,v = h @ W{q,k,v}  (bf16x3 mma.sync, fp32 out)
    mma_gemm_kernel<false, false, false, false><<<gc, GT, GEMM_SMEM>>>(
        hhi, hlo, Wqhi, Wqlo, nullptr, nullptr, q, nullptr, nullptr, CDIM, CDIM);
    mma_gemm_kernel<false, false, false, false><<<gc, GT, GEMM_SMEM>>>(
        hhi, hlo, Wkhi, Wklo, nullptr, nullptr, k, nullptr, nullptr, CDIM, CDIM);
    mma_gemm_kernel<false, false, false, false><<<gc, GT, GEMM_SMEM>>>(
        hhi, hlo, Wvhi, Wvlo, nullptr, nullptr, v, nullptr, nullptr, CDIM, CDIM);
    // 3) causal attention (fp32 compute, split output)
    flash_attn_kernel<<<dim3(TSEQ / 64, HEADS, BB), 256>>>(q, k, v, ahi, alo);
    // 4) x1 = x + attn @ Wo + bo
    mma_gemm_kernel<true, false, true, false><<<gc, GT, GEMM_SMEM>>>(
        ahi, alo, Wohi, Wolo, bo, x, x1, nullptr, nullptr, CDIM, CDIM);
    // 5) h = LN2(x1), split
    layernorm_split_kernel<<<MTOT, 256>>>(x1, ln2g, ln2b, hhi, hlo);
    // 6) ff = relu(h @ W1 + b1), split output
    mma_gemm_kernel<true, true, false, true><<<gf, GT, GEMM_SMEM>>>(
        hhi, hlo, W1hi, W1lo, b1, nullptr, nullptr, ffhi, fflo, FDIM, CDIM);
    // 7) out = x1 + ff @ W2 + b2
    mma_gemm_kernel<true, false, true, false><<<gc, GT, GEMM_SMEM>>>(
        ffhi, fflo, W2hi, W2lo, b2, x1, out, nullptr, nullptr, CDIM, FDIM);
}

// round 5
// speedup vs baseline: 1.9500x; 1.9500x over previous
#include <cuda_runtime.h>
#include <cuda_fp16.h>
#include <cstdint>
#include <math.h>

#define BB    4
#define TSEQ  2048
#define CDIM  1024
#define HEADS 16
#define DHEAD 64
#define MTOT  (BB * TSEQ)
#define FDIM  (4 * CDIM)

// -------- scratch (device globals) --------
__device__ __half g_hhi [MTOT * CDIM], g_hlo [MTOT * CDIM];
__device__ __half g_qhi [MTOT * CDIM], g_qlo [MTOT * CDIM];
__device__ __half g_khi [MTOT * CDIM], g_klo [MTOT * CDIM];
__device__ __half g_vhi [MTOT * CDIM], g_vlo [MTOT * CDIM];
__device__ __half g_ahi [MTOT * CDIM], g_alo [MTOT * CDIM];
__device__ float  g_x1  [MTOT * CDIM];
__device__ __half g_ffhi[MTOT * FDIM], g_fflo[MTOT * FDIM];
__device__ __half g_Wq[CDIM * CDIM], g_Wk[CDIM * CDIM], g_Wv[CDIM * CDIM];
__device__ __half g_Wo[CDIM * CDIM];
__device__ __half g_W1[CDIM * FDIM], g_W2[FDIM * CDIM];

// -------- PTX helpers (plain sm_80+ only) --------
__device__ __forceinline__ uint32_t smem_u32(const void* p) {
    uint32_t a;
    asm("{ .reg .u64 t; cvta.to.shared.u64 t, %1; cvt.u32.u64 %0, t; }" : "=r"(a) : "l"(p));
    return a;
}
__device__ __forceinline__ void cp16(uint32_t dst, const void* src) {
    asm volatile("cp.async.cg.shared.global [%0], [%1], 16;" :: "r"(dst), "l"(src));
}
__device__ __forceinline__ void cp_commit() { asm volatile("cp.async.commit_group;"); }
template<int N> __device__ __forceinline__ void cp_wait() {
    asm volatile("cp.async.wait_group %0;" :: "n"(N));
}
__device__ __forceinline__ void ldsm_x4(uint32_t* r, uint32_t a) {
    asm volatile("ldmatrix.sync.aligned.m8n8.x4.shared.b16 {%0,%1,%2,%3}, [%4];"
                 : "=r"(r[0]), "=r"(r[1]), "=r"(r[2]), "=r"(r[3]) : "r"(a));
}
__device__ __forceinline__ void ldsm_x4t(uint32_t* r, uint32_t a) {
    asm volatile("ldmatrix.sync.aligned.m8n8.x4.trans.shared.b16 {%0,%1,%2,%3}, [%4];"
                 : "=r"(r[0]), "=r"(r[1]), "=r"(r[2]), "=r"(r[3]) : "r"(a));
}
__device__ __forceinline__ void mma_f16(float* c, const uint32_t* a, const uint32_t* b) {
    asm volatile(
        "mma.sync.aligned.m16n8k16.row.col.f32.f16.f16.f32 "
        "{%0,%1,%2,%3}, {%4,%5,%6,%7}, {%8,%9}, {%0,%1,%2,%3};"
        : "+f"(c[0]), "+f"(c[1]), "+f"(c[2]), "+f"(c[3])
        : "r"(a[0]), "r"(a[1]), "r"(a[2]), "r"(a[3]), "r"(b[0]), "r"(b[1]));
}
__device__ __forceinline__ void splith(float v, __half& h, __half& l) {
    h = __float2half_rn(v);
    l = __float2half_rn(v - __half2float(h));
}
__device__ __forceinline__ uint32_t packh2(float a, float b) {
    __half2 h = __floats2half2_rn(a, b);
    return *(uint32_t*)&h;
}
// fast 2^t (t <= 0, clamped)
__device__ __forceinline__ float fexp2(float t) {
    t = fmaxf(t, -126.0f);
    const float mag = 12582912.0f;
    float r = t + mag;
    uint32_t ui = __float_as_uint(r);
    float f = t - (r - mag);
    float p = 1.3333558146e-3f;
    p = fmaf(p, f, 9.6181291076e-3f);
    p = fmaf(p, f, 5.5504108664e-2f);
    p = fmaf(p, f, 2.4022650696e-1f);
    p = fmaf(p, f, 6.9314718056e-1f);
    p = fmaf(p, f, 1.0f);
    return __uint_as_float(__float_as_uint(p) + (ui << 23));
}

// ==================== fp16-x2 GEMM ====================
// C = (Ahi+Alo) @ B;  128x128 tile, BK=32, 256 thr, 3-stage cp.async
#define GT        256
#define GA_TILE   10240   // 128 x 80B
#define GSTAGE    29184   // 2*GA_TILE + 8704
#define GEMM_SMEM (3 * GSTAGE)

template<bool BIAS, bool RELU, bool RES, bool SPLIT>
__global__ void __launch_bounds__(GT) gemm16(
    const __half* __restrict__ Ahi, const __half* __restrict__ Alo,
    const __half* __restrict__ B,
    const float* __restrict__ bias, const float* __restrict__ res,
    float* __restrict__ Cf, __half* __restrict__ Chi, __half* __restrict__ Clo,
    int N, int K)
{
    extern __shared__ char sm[];
    const uint32_t sb = smem_u32(sm);
    const int tid = threadIdx.x, lane = tid & 31, wid = tid >> 5;
    const int wm = (wid >> 2) * 64, wn = (wid & 3) * 32;
    const int m0 = blockIdx.y * 128, n0 = blockIdx.x * 128;

    auto load_stage = [&](int s, int c) {
        const int kc = c << 5;
        const uint32_t st = sb + (uint32_t)s * GSTAGE;
        const int row = tid >> 1, s0 = (tid & 1) << 1;
        const size_t g = (size_t)(m0 + row) * K + kc + s0 * 8;
        const uint32_t so = st + row * 80 + s0 * 16;
        cp16(so,      Ahi + g);
        cp16(so + 16, Ahi + g + 8);
        cp16(so + GA_TILE,      Alo + g);
        cp16(so + GA_TILE + 16, Alo + g + 8);
        const int br = tid >> 4, seg = tid & 15;
        const size_t gb = (size_t)(kc + br) * N + n0 + seg * 8;
        const uint32_t sob = st + 2 * GA_TILE + br * 272 + seg * 16;
        cp16(sob, B + gb);
        cp16(sob + 16 * 272, B + gb + (size_t)16 * N);
    };

    float acc[4][4][4];
    #pragma unroll
    for (int a = 0; a < 4; a++)
        #pragma unroll
        for (int b = 0; b < 4; b++)
            #pragma unroll
            for (int d = 0; d < 4; d++) acc[a][b][d] = 0.f;

    const int NC = K >> 5;
    load_stage(0, 0); cp_commit();
    load_stage(1, 1); cp_commit();
    load_stage(2, 2); cp_commit();

    for (int c = 0; c < NC; c++) {
        const int s = c % 3;
        if (c + 2 < NC)      cp_wait<2>();
        else if (c + 1 < NC) cp_wait<1>();
        else                 cp_wait<0>();
        __syncthreads();

        const uint32_t aoff = sb + (uint32_t)s * GSTAGE;
        const uint32_t boff = aoff + 2 * GA_TILE;
        #pragma unroll
        for (int ks = 0; ks < 2; ks++) {
            uint32_t bfr[4][2];
            #pragma unroll
            for (int ntp = 0; ntp < 2; ntp++) {
                uint32_t r[4];
                ldsm_x4t(r, boff + (ks * 16 + (lane & 15)) * 272
                              + (wn + ntp * 16 + ((lane >> 4) << 3)) * 2);
                bfr[2*ntp][0] = r[0]; bfr[2*ntp][1] = r[1];
                bfr[2*ntp+1][0] = r[2]; bfr[2*ntp+1][1] = r[3];
            }
            #pragma unroll
            for (int mt = 0; mt < 4; mt++) {
                uint32_t ah[4], al[4];
                const uint32_t aa = aoff + (wm + mt * 16 + (lane & 15)) * 80
                                        + (ks * 16 + ((lane >> 4) << 3)) * 2;
                ldsm_x4(ah, aa);
                ldsm_x4(al, aa + GA_TILE);
                #pragma unroll
                for (int nt = 0; nt < 4; nt++) {
                    mma_f16(acc[mt][nt], ah, bfr[nt]);
                    mma_f16(acc[mt][nt], al, bfr[nt]);
                }
            }
        }
        __syncthreads();
        if (c + 3 < NC) { load_stage(s, c + 3); cp_commit(); }
    }

    #pragma unroll
    for (int mt = 0; mt < 4; mt++)
        #pragma unroll
        for (int nt = 0; nt < 4; nt++)
            #pragma unroll
            for (int hf = 0; hf < 2; hf++) {
                const int row = m0 + wm + mt * 16 + (lane >> 2) + hf * 8;
                const int col = n0 + wn + nt * 8 + (lane & 3) * 2;
                float v0 = acc[mt][nt][hf * 2 + 0];
                float v1 = acc[mt][nt][hf * 2 + 1];
                if (BIAS) { v0 += bias[col]; v1 += bias[col + 1]; }
                if (RELU) { v0 = fmaxf(v0, 0.f); v1 = fmaxf(v1, 0.f); }
                if (RES) {
                    const float2 rr = *(const float2*)&res[(size_t)row * N + col];
                    v0 += rr.x; v1 += rr.y;
                }
                if (SPLIT) {
                    __half h0, l0, h1, l1;
                    splith(v0, h0, l0); splith(v1, h1, l1);
                    const __half2 hp = __halves2half2(h0, h1);
                    const __half2 lp = __halves2half2(l0, l1);
                    *(uint32_t*)&Chi[(size_t)row * N + col] = *(const uint32_t*)&hp;
                    *(uint32_t*)&Clo[(size_t)row * N + col] = *(const uint32_t*)&lp;
                } else {
                    float2 o; o.x = v0; o.y = v1;
                    *(float2*)&Cf[(size_t)row * N + col] = o;
                }
            }
}

// ==================== weight convert fp32 -> fp16 ====================
__global__ void __launch_bounds__(256) wconv_kernel(
    const float* __restrict__ w, __half* __restrict__ o, int n4)
{
    for (int i = blockIdx.x * blockDim.x + threadIdx.x; i < n4;
         i += gridDim.x * blockDim.x) {
        const float4 v = ((const float4*)w)[i];
        const __half2 a = __floats2half2_rn(v.x, v.y);
        const __half2 b = __floats2half2_rn(v.z, v.w);
        uint2 u; u.x = *(const uint32_t*)&a; u.y = *(const uint32_t*)&b;
        *(uint2*)&o[(size_t)i * 4] = u;
    }
}

// ==================== LayerNorm -> fp16 hi/lo ====================
__inline__ __device__ float warp_sum(float v) {
    #pragma unroll
    for (int m = 16; m > 0; m >>= 1) v += __shfl_xor_sync(0xffffffffu, v, m);
    return v;
}
__global__ void __launch_bounds__(256) layernorm_split_kernel(
    const float* __restrict__ x, const float* __restrict__ g,
    const float* __restrict__ bt, __half* __restrict__ yhi, __half* __restrict__ ylo)
{
    const int row = blockIdx.x, tid = threadIdx.x;
    const float4 v = ((const float4*)(x + (size_t)row * CDIM))[tid];
    float s  = v.x + v.y + v.z + v.w;
    float ss = v.x*v.x + v.y*v.y + v.z*v.z + v.w*v.w;
    __shared__ float sh1[8], sh2[8];
    s = warp_sum(s); ss = warp_sum(ss);
    const int w = tid >> 5, l = tid & 31;
    if (l == 0) { sh1[w] = s; sh2[w] = ss; }
    __syncthreads();
    if (w == 0) {
        float a = (l < 8) ? sh1[l] : 0.f;
        float b = (l < 8) ? sh2[l] : 0.f;
        a = warp_sum(a); b = warp_sum(b);
        if (l == 0) { sh1[0] = a; sh2[0] = b; }
    }
    __syncthreads();
    const float mean = sh1[0] * (1.0f / CDIM);
    const float var  = sh2[0] * (1.0f / CDIM) - mean * mean;
    const float inv  = rsqrtf(var + 1e-5f);
    const float4 gv = ((const float4*)g)[tid];
    const float4 bv = ((const float4*)bt)[tid];
    const float o0 = (v.x - mean) * inv * gv.x + bv.x;
    const float o1 = (v.y - mean) * inv * gv.y + bv.y;
    const float o2 = (v.z - mean) * inv * gv.z + bv.z;
    const float o3 = (v.w - mean) * inv * gv.w + bv.w;
    __half h0, h1, h2, h3, l0, l1, l2, l3;
    splith(o0, h0, l0); splith(o1, h1, l1);
    splith(o2, h2, l2); splith(o3, h3, l3);
    const __half2 ha = __halves2half2(h0, h1), hb = __halves2half2(h2, h3);
    const __half2 la = __halves2half2(l0, l1), lb = __halves2half2(l2, l3);
    uint2 uh, ul;
    uh.x = *(const uint32_t*)&ha; uh.y = *(const uint32_t*)&hb;
    ul.x = *(const uint32_t*)&la; ul.y = *(const uint32_t*)&lb;
    *(uint2*)&yhi[(size_t)row * CDIM + tid * 4] = uh;
    *(uint2*)&ylo[(size_t)row * CDIM + tid * 4] = ul;
}

// ==================== tensor-core flash attention ====================
// Q tile 128 rows (8 warps x 16), K/V tile 64. QK^T: fp16 x3. PV: fp16 x2.
#define FA_QS     18432                 // 128 x 144B
#define FA_KV     9216                  // 64 x 144B
#define FA_STAGE  36864                 // 4 arrays (Kh,Kl,Vh,Vl)
#define FA_SMEM   (2 * FA_QS + 2 * FA_STAGE)   // 110592

__global__ void __launch_bounds__(256, 1) flash16_kernel(
    const __half* __restrict__ Qhi, const __half* __restrict__ Qlo,
    const __half* __restrict__ Khi, const __half* __restrict__ Klo,
    const __half* __restrict__ Vhi, const __half* __restrict__ Vlo,
    __half* __restrict__ Ohi, __half* __restrict__ Olo)
{
    extern __shared__ char sm[];
    const uint32_t sb = smem_u32(sm);
    const int tid = threadIdx.x, lane = tid & 31, wid = tid >> 5;
    const int qt = gridDim.x - 1 - blockIdx.x;    // longest blocks first
    const int hh = blockIdx.y, bb = blockIdx.z;
    const int rowbase = bb * TSEQ + qt * 128;
    const int colC = hh * DHEAD;

    auto loadKV = [&](int s, int kt) {
        #pragma unroll
        for (int i = 0; i < 8; i++) {
            const int c = tid + i * 256;
            const int arr = c >> 9;
            const int r = (c >> 3) & 63;
            const int seg = c & 7;
            const __half* src =
                (arr == 0 ? Khi : arr == 1 ? Klo : arr == 2 ? Vhi : Vlo)
                + (size_t)(bb * TSEQ + kt * 64 + r) * CDIM + colC + seg * 8;
            cp16(sb + 2 * FA_QS + (uint32_t)s * FA_STAGE + arr * FA_KV
                 + r * 144 + seg * 16, src);
        }
    };

    #pragma unroll
    for (int i = 0; i < 8; i++) {
        const int c = tid + i * 256;
        const int arr = c >> 10;
        const int r = (c >> 3) & 127;
        const int seg = c & 7;
        const __half* src = (arr ? Qlo : Qhi)
            + (size_t)(rowbase + r) * CDIM + colC + seg * 8;
        cp16(sb + (uint32_t)arr * FA_QS + r * 144 + seg * 16, src);
    }
    cp_commit();
    loadKV(0, 0);
    cp_commit();
    cp_wait<0>();
    __syncthreads();

    uint32_t qh[4][4], ql[4][4];
    #pragma unroll
    for (int kf = 0; kf < 4; kf++) {
        const uint32_t qa = sb + (wid * 16 + (lane & 15)) * 144
                               + (kf * 16 + ((lane >> 4) << 3)) * 2;
        ldsm_x4(qh[kf], qa);
        ldsm_x4(ql[kf], qa + FA_QS);
    }

    float o[8][4];
    #pragma unroll
    for (int i = 0; i < 8; i++)
        #pragma unroll
        for (int j = 0; j < 4; j++) o[i][j] = 0.f;
    float m0 = -1e30f, m1 = -1e30f, l0 = 0.f, l1 = 0.f;

    const int ktlast = 2 * qt + 1;
    const float SCALE = 0.18033688011112042f;   // 0.125 * log2(e)

    for (int kt = 0; kt <= ktlast; kt++) {
        const int s = kt & 1;
        if (kt < ktlast) { loadKV(s ^ 1, kt + 1); cp_commit(); cp_wait<1>(); }
        else             cp_wait<0>();
        __syncthreads();

        const uint32_t kbh = sb + 2 * FA_QS + (uint32_t)s * FA_STAGE;
        const uint32_t kbl = kbh + FA_KV;
        const uint32_t vbh = kbh + 2 * FA_KV;
        const uint32_t vbl = kbh + 3 * FA_KV;

        float c[8][4];
        #pragma unroll
        for (int i = 0; i < 8; i++)
            #pragma unroll
            for (int j = 0; j < 4; j++) c[i][j] = 0.f;

        #pragma unroll
        for (int kf = 0; kf < 4; kf++)
            #pragma unroll
            for (int ntp = 0; ntp < 4; ntp++) {
                uint32_t bh[4], bl[4];
                const uint32_t ka = (ntp * 16 + (lane & 7) + ((lane >> 4) << 3)) * 144
                                  + (kf * 16 + ((lane >> 3) & 1) * 8) * 2;
                ldsm_x4(bh, kbh + ka);
                ldsm_x4(bl, kbl + ka);
                mma_f16(c[2*ntp],   qh[kf], &bh[0]);
                mma_f16(c[2*ntp],   qh[kf], &bl[0]);
                mma_f16(c[2*ntp],   ql[kf], &bh[0]);
                mma_f16(c[2*ntp+1], qh[kf], &bh[2]);
                mma_f16(c[2*ntp+1], qh[kf], &bl[2]);
                mma_f16(c[2*ntp+1], ql[kf], &bh[2]);
            }

        if (kt >= 2 * qt) {
            const int rg0 = qt * 128 + wid * 16 + (lane >> 2);
            const int cg0 = kt * 64 + (lane & 3) * 2;
            #pragma unroll
            for (int nt = 0; nt < 8; nt++) {
                const int cg = cg0 + nt * 8;
                #pragma unroll
                for (int j = 0; j < 4; j++) {
                    const int r  = rg0 + ((j >> 1) << 3);
                    const int cc = cg + (j & 1);
                    if (cc > r) c[nt][j] = -1e30f;
                }
            }
        }

        float mx0 = -1e30f, mx1 = -1e30f;
        #pragma unroll
        for (int nt = 0; nt < 8; nt++) {
            mx0 = fmaxf(mx0, fmaxf(c[nt][0], c[nt][1]));
            mx1 = fmaxf(mx1, fmaxf(c[nt][2], c[nt][3]));
        }
        mx0 = fmaxf(mx0, __shfl_xor_sync(0xffffffffu, mx0, 1));
        mx0 = fmaxf(mx0, __shfl_xor_sync(0xffffffffu, mx0, 2));
        mx1 = fmaxf(mx1, __shfl_xor_sync(0xffffffffu, mx1, 1));
        mx1 = fmaxf(mx1, __shfl_xor_sync(0xffffffffu, mx1, 2));

        const float nm0 = fmaxf(m0, mx0 * SCALE);
        const float nm1 = fmaxf(m1, mx1 * SCALE);
        const float al0 = fexp2(m0 - nm0);
        const float al1 = fexp2(m1 - nm1);
        m0 = nm0; m1 = nm1;

        float rs0 = 0.f, rs1 = 0.f;
        #pragma unroll
        for (int nt = 0; nt < 8; nt++) {
            float p0 = fexp2(fmaf(c[nt][0], SCALE, -nm0));
            float p1 = fexp2(fmaf(c[nt][1], SCALE, -nm0));
            float p2 = fexp2(fmaf(c[nt][2], SCALE, -nm1));
            float p3 = fexp2(fmaf(c[nt][3], SCALE, -nm1));
            c[nt][0] = p0; c[nt][1] = p1; c[nt][2] = p2; c[nt][3] = p3;
            rs0 += p0 + p1; rs1 += p2 + p3;
        }
        rs0 += __shfl_xor_sync(0xffffffffu, rs0, 1);
        rs0 += __shfl_xor_sync(0xffffffffu, rs0, 2);
        rs1 += __shfl_xor_sync(0xffffffffu, rs1, 1);
        rs1 += __shfl_xor_sync(0xffffffffu, rs1, 2);
        l0 = l0 * al0 + rs0;
        l1 = l1 * al1 + rs1;
        #pragma unroll
        for (int nt = 0; nt < 8; nt++) {
            o[nt][0] *= al0; o[nt][1] *= al0;
            o[nt][2] *= al1; o[nt][3] *= al1;
        }

        #pragma unroll
        for (int kf = 0; kf < 4; kf++) {
            uint32_t ph[4];
            ph[0] = packh2(c[2*kf][0],   c[2*kf][1]);
            ph[1] = packh2(c[2*kf][2],   c[2*kf][3]);
            ph[2] = packh2(c[2*kf+1][0], c[2*kf+1][1]);
            ph[3] = packh2(c[2*kf+1][2], c[2*kf+1][3]);
            #pragma unroll
            for (int ntp = 0; ntp < 4; ntp++) {
                uint32_t vh[4], vl[4];
                const uint32_t va = (kf * 16 + (lane & 15)) * 144
                                  + (ntp * 16 + ((lane >> 4) << 3)) * 2;
                ldsm_x4t(vh, vbh + va);
                ldsm_x4t(vl, vbl + va);
                mma_f16(o[2*ntp],   ph, &vh[0]);
                mma_f16(o[2*ntp],   ph, &vl[0]);
                mma_f16(o[2*ntp+1], ph, &vh[2]);
                mma_f16(o[2*ntp+1], ph, &vl[2]);
            }
        }
        __syncthreads();
    }

    const float il0 = 1.f / l0, il1 = 1.f / l1;
    const int rg = rowbase + wid * 16 + (lane >> 2);
    #pragma unroll
    for (int nt = 0; nt < 8; nt++) {
        const int col = colC + nt * 8 + (lane & 3) * 2;
        __half h0, h1, p0, p1;
        splith(o[nt][0] * il0, h0, p0);
        splith(o[nt][1] * il0, h1, p1);
        __half2 hp = __halves2half2(h0, h1), lp = __halves2half2(p0, p1);
        *(uint32_t*)&Ohi[(size_t)rg * CDIM + col] = *(const uint32_t*)&hp;
        *(uint32_t*)&Olo[(size_t)rg * CDIM + col] = *(const uint32_t*)&lp;
        splith(o[nt][2] * il1, h0, p0);
        splith(o[nt][3] * il1, h1, p1);
        hp = __halves2half2(h0, h1); lp = __halves2half2(p0, p1);
        *(uint32_t*)&Ohi[(size_t)(rg + 8) * CDIM + col] = *(const uint32_t*)&hp;
        *(uint32_t*)&Olo[(size_t)(rg + 8) * CDIM + col] = *(const uint32_t*)&lp;
    }
}

// ==================== launch ====================
extern "C" void kernel_launch(void* const* d_in, const int* in_sizes, int n_in,
                              void* d_out, int out_size)
{
    (void)in_sizes; (void)n_in; (void)out_size;
    const float* x    = (const float*)d_in[0];
    const float* Wq   = (const float*)d_in[1];
    const float* Wk   = (const float*)d_in[2];
    const float* Wv   = (const float*)d_in[3];
    const float* Wo   = (const float*)d_in[4];
    const float* bo   = (const float*)d_in[5];
    const float* ln1g = (const float*)d_in[6];
    const float* ln1b = (const float*)d_in[7];
    const float* ln2g = (const float*)d_in[8];
    const float* ln2b = (const float*)d_in[9];
    const float* W1   = (const float*)d_in[10];
    const float* b1   = (const float*)d_in[11];
    const float* W2   = (const float*)d_in[12];
    const float* b2   = (const float*)d_in[13];
    float* out = (float*)d_out;

    __half *hhi, *hlo, *qhi, *qlo, *khi, *klo, *vhi, *vlo, *ahi, *alo, *ffhi, *fflo;
    float* x1;
    __half *Wqh, *Wkh, *Wvh, *Woh, *W1h, *W2h;
    cudaGetSymbolAddress((void**)&hhi,  g_hhi);  cudaGetSymbolAddress((void**)&hlo,  g_hlo);
    cudaGetSymbolAddress((void**)&qhi,  g_qhi);  cudaGetSymbolAddress((void**)&qlo,  g_qlo);
    cudaGetSymbolAddress((void**)&khi,  g_khi);  cudaGetSymbolAddress((void**)&klo,  g_klo);
    cudaGetSymbolAddress((void**)&vhi,  g_vhi);  cudaGetSymbolAddress((void**)&vlo,  g_vlo);
    cudaGetSymbolAddress((void**)&ahi,  g_ahi);  cudaGetSymbolAddress((void**)&alo,  g_alo);
    cudaGetSymbolAddress((void**)&x1,   g_x1);
    cudaGetSymbolAddress((void**)&ffhi, g_ffhi); cudaGetSymbolAddress((void**)&fflo, g_fflo);
    cudaGetSymbolAddress((void**)&Wqh,  g_Wq);   cudaGetSymbolAddress((void**)&Wkh,  g_Wk);
    cudaGetSymbolAddress((void**)&Wvh,  g_Wv);   cudaGetSymbolAddress((void**)&Woh,  g_Wo);
    cudaGetSymbolAddress((void**)&W1h,  g_W1);   cudaGetSymbolAddress((void**)&W2h,  g_W2);

    cudaFuncSetAttribute(gemm16<false, false, false, true>,
                         cudaFuncAttributeMaxDynamicSharedMemorySize, GEMM_SMEM);
    cudaFuncSetAttribute(gemm16<true, false, true, false>,
                         cudaFuncAttributeMaxDynamicSharedMemorySize, GEMM_SMEM);
    cudaFuncSetAttribute(gemm16<true, true, false, true>,
                         cudaFuncAttributeMaxDynamicSharedMemorySize, GEMM_SMEM);
    cudaFuncSetAttribute(flash16_kernel,
                         cudaFuncAttributeMaxDynamicSharedMemorySize, FA_SMEM);

    wconv_kernel<<<512, 256>>>(Wq, Wqh, CDIM * CDIM / 4);
    wconv_kernel<<<512, 256>>>(Wk, Wkh, CDIM * CDIM / 4);
    wconv_kernel<<<512, 256>>>(Wv, Wvh, CDIM * CDIM / 4);
    wconv_kernel<<<512, 256>>>(Wo, Woh, CDIM * CDIM / 4);
    wconv_kernel<<<1024, 256>>>(W1, W1h, CDIM * FDIM / 4);
    wconv_kernel<<<1024, 256>>>(W2, W2h, FDIM * CDIM / 4);

    const dim3 gc(CDIM / 128, MTOT / 128);
    const dim3 gf(FDIM / 128, MTOT / 128);

    layernorm_split_kernel<<<MTOT, 256>>>(x, ln1g, ln1b, hhi, hlo);
    gemm16<false, false, false, true><<<gc, GT, GEMM_SMEM>>>(
        hhi, hlo, Wqh, nullptr, nullptr, nullptr, qhi, qlo, CDIM, CDIM);
    gemm16<false, false, false, true><<<gc, GT, GEMM_SMEM>>>(
        hhi, hlo, Wkh, nullptr, nullptr, nullptr, khi, klo, CDIM, CDIM);
    gemm16<false, false, false, true><<<gc, GT, GEMM_SMEM>>>(
        hhi, hlo, Wvh, nullptr, nullptr, nullptr, vhi, vlo, CDIM, CDIM);
    flash16_kernel<<<dim3(TSEQ / 128, HEADS, BB), 256, FA_SMEM>>>(
        qhi, qlo, khi, klo, vhi, vlo, ahi, alo);
    gemm16<true, false, true, false><<<gc, GT, GEMM_SMEM>>>(
        ahi, alo, Woh, bo, x, x1, nullptr, nullptr, CDIM, CDIM);
    layernorm_split_kernel<<<MTOT, 256>>>(x1, ln2g, ln2b, hhi, hlo);
    gemm16<true, true, false, true><<<gf, GT, GEMM_SMEM>>>(
        hhi, hlo, W1h, b1, nullptr, nullptr, ffhi, fflo, FDIM, CDIM);
    gemm16<true, false, true, false><<<gc, GT, GEMM_SMEM>>>(
        ffhi, fflo, W2h, b2, x1, out, nullptr, nullptr, CDIM, FDIM);
}

// round 6
// speedup vs baseline: 2.5578x; 1.3117x over previous
#include <cuda_runtime.h>
#include <cuda_fp16.h>
#include <cstdint>
#include <math.h>

#define BB    4
#define TSEQ  2048
#define CDIM  1024
#define HEADS 16
#define DHEAD 64
#define MTOT  (BB * TSEQ)
#define FDIM  (4 * CDIM)
#define C3    (3 * CDIM)    // fused QKV width

// -------- scratch (device globals) --------
__device__ __half g_hhi  [MTOT * CDIM], g_hlo [MTOT * CDIM];
__device__ __half g_qkvhi[MTOT * C3],   g_qkvlo[MTOT * C3];
__device__ __half g_ahi  [MTOT * CDIM], g_alo [MTOT * CDIM];
__device__ float  g_x1   [MTOT * CDIM];
__device__ __half g_ff   [MTOT * FDIM];
__device__ __half g_Wqkv[CDIM * C3];
__device__ __half g_Wo[CDIM * CDIM];
__device__ __half g_W1[CDIM * FDIM], g_W2[FDIM * CDIM];

// -------- PTX helpers (plain sm_80+ only) --------
__device__ __forceinline__ uint32_t smem_u32(const void* p) {
    uint32_t a;
    asm("{ .reg .u64 t; cvta.to.shared.u64 t, %1; cvt.u32.u64 %0, t; }" : "=r"(a) : "l"(p));
    return a;
}
__device__ __forceinline__ void cp16(uint32_t dst, const void* src) {
    asm volatile("cp.async.cg.shared.global [%0], [%1], 16;" :: "r"(dst), "l"(src));
}
__device__ __forceinline__ void cp_commit() { asm volatile("cp.async.commit_group;"); }
template<int N> __device__ __forceinline__ void cp_wait() {
    asm volatile("cp.async.wait_group %0;" :: "n"(N));
}
__device__ __forceinline__ void ldsm_x4(uint32_t* r, uint32_t a) {
    asm volatile("ldmatrix.sync.aligned.m8n8.x4.shared.b16 {%0,%1,%2,%3}, [%4];"
                 : "=r"(r[0]), "=r"(r[1]), "=r"(r[2]), "=r"(r[3]) : "r"(a));
}
__device__ __forceinline__ void ldsm_x4t(uint32_t* r, uint32_t a) {
    asm volatile("ldmatrix.sync.aligned.m8n8.x4.trans.shared.b16 {%0,%1,%2,%3}, [%4];"
                 : "=r"(r[0]), "=r"(r[1]), "=r"(r[2]), "=r"(r[3]) : "r"(a));
}
__device__ __forceinline__ void mma_f16(float* c, const uint32_t* a, const uint32_t* b) {
    asm volatile(
        "mma.sync.aligned.m16n8k16.row.col.f32.f16.f16.f32 "
        "{%0,%1,%2,%3}, {%4,%5,%6,%7}, {%8,%9}, {%0,%1,%2,%3};"
        : "+f"(c[0]), "+f"(c[1]), "+f"(c[2]), "+f"(c[3])
        : "r"(a[0]), "r"(a[1]), "r"(a[2]), "r"(a[3]), "r"(b[0]), "r"(b[1]));
}
__device__ __forceinline__ void splith(float v, __half& h, __half& l) {
    h = __float2half_rn(v);
    l = __float2half_rn(v - __half2float(h));
}
__device__ __forceinline__ uint32_t packh2(float a, float b) {
    __half2 h = __floats2half2_rn(a, b);
    return *(uint32_t*)&h;
}
__device__ __forceinline__ float fexp2(float t) {   // fast 2^t, t<=0
    t = fmaxf(t, -126.0f);
    const float mag = 12582912.0f;
    float r = t + mag;
    uint32_t ui = __float_as_uint(r);
    float f = t - (r - mag);
    float p = 1.3333558146e-3f;
    p = fmaf(p, f, 9.6181291076e-3f);
    p = fmaf(p, f, 5.5504108664e-2f);
    p = fmaf(p, f, 2.4022650696e-1f);
    p = fmaf(p, f, 6.9314718056e-1f);
    p = fmaf(p, f, 1.0f);
    return __uint_as_float(__float_as_uint(p) + (ui << 23));
}

// ==================== fp16 GEMM (1 or 2 A-limbs) ====================
// C = (Ahi[+Alo]) @ B; 128x128 tile, BK=32, 256 thr, 3-stage cp.async.
// OUT: 0 = fp32, 1 = split fp16 hi/lo, 2 = single fp16.
#define GT      256
#define GA_TILE 10240   // 128 x 80B

template<int LIMBS, bool BIAS, bool RELU, bool RES, int OUT>
__global__ void __launch_bounds__(GT) gemm16(
    const __half* __restrict__ Ahi, const __half* __restrict__ Alo,
    const __half* __restrict__ B,
    const float* __restrict__ bias, const float* __restrict__ res,
    float* __restrict__ Cf, __half* __restrict__ Chi, __half* __restrict__ Clo,
    int N, int K)
{
    constexpr uint32_t BOFF  = LIMBS * GA_TILE;
    constexpr uint32_t STAGE = BOFF + 8704;
    extern __shared__ char sm[];
    const uint32_t sb = smem_u32(sm);
    const int tid = threadIdx.x, lane = tid & 31, wid = tid >> 5;
    const int wm = (wid >> 2) * 64, wn = (wid & 3) * 32;
    const int m0 = blockIdx.y * 128, n0 = blockIdx.x * 128;

    auto load_stage = [&](int s, int c) {
        const int kc = c << 5;
        const uint32_t st = sb + (uint32_t)s * STAGE;
        const int row = tid >> 1, s0 = (tid & 1) << 1;
        const size_t g = (size_t)(m0 + row) * K + kc + s0 * 8;
        const uint32_t so = st + row * 80 + s0 * 16;
        cp16(so,      Ahi + g);
        cp16(so + 16, Ahi + g + 8);
        if (LIMBS == 2) {
            cp16(so + GA_TILE,      Alo + g);
            cp16(so + GA_TILE + 16, Alo + g + 8);
        }
        const int br = tid >> 4, seg = tid & 15;
        const size_t gb = (size_t)(kc + br) * N + n0 + seg * 8;
        const uint32_t sob = st + BOFF + br * 272 + seg * 16;
        cp16(sob, B + gb);
        cp16(sob + 16 * 272, B + gb + (size_t)16 * N);
    };

    float acc[4][4][4];
    #pragma unroll
    for (int a = 0; a < 4; a++)
        #pragma unroll
        for (int b = 0; b < 4; b++)
            #pragma unroll
            for (int d = 0; d < 4; d++) acc[a][b][d] = 0.f;

    const int NC = K >> 5;
    load_stage(0, 0); cp_commit();
    load_stage(1, 1); cp_commit();
    load_stage(2, 2); cp_commit();

    for (int c = 0; c < NC; c++) {
        const int s = c % 3;
        if (c + 2 < NC)      cp_wait<2>();
        else if (c + 1 < NC) cp_wait<1>();
        else                 cp_wait<0>();
        __syncthreads();

        const uint32_t aoff = sb + (uint32_t)s * STAGE;
        const uint32_t boff = aoff + BOFF;
        #pragma unroll
        for (int ks = 0; ks < 2; ks++) {
            uint32_t bfr[4][2];
            #pragma unroll
            for (int ntp = 0; ntp < 2; ntp++) {
                uint32_t r[4];
                ldsm_x4t(r, boff + (ks * 16 + (lane & 15)) * 272
                              + (wn + ntp * 16 + ((lane >> 4) << 3)) * 2);
                bfr[2*ntp][0] = r[0]; bfr[2*ntp][1] = r[1];
                bfr[2*ntp+1][0] = r[2]; bfr[2*ntp+1][1] = r[3];
            }
            #pragma unroll
            for (int mt = 0; mt < 4; mt++) {
                uint32_t ah[4], al[4];
                const uint32_t aa = aoff + (wm + mt * 16 + (lane & 15)) * 80
                                        + (ks * 16 + ((lane >> 4) << 3)) * 2;
                ldsm_x4(ah, aa);
                if (LIMBS == 2) ldsm_x4(al, aa + GA_TILE);
                #pragma unroll
                for (int nt = 0; nt < 4; nt++) {
                    mma_f16(acc[mt][nt], ah, bfr[nt]);
                    if (LIMBS == 2) mma_f16(acc[mt][nt], al, bfr[nt]);
                }
            }
        }
        __syncthreads();
        if (c + 3 < NC) { load_stage(s, c + 3); cp_commit(); }
    }

    #pragma unroll
    for (int mt = 0; mt < 4; mt++)
        #pragma unroll
        for (int nt = 0; nt < 4; nt++)
            #pragma unroll
            for (int hf = 0; hf < 2; hf++) {
                const int row = m0 + wm + mt * 16 + (lane >> 2) + hf * 8;
                const int col = n0 + wn + nt * 8 + (lane & 3) * 2;
                float v0 = acc[mt][nt][hf * 2 + 0];
                float v1 = acc[mt][nt][hf * 2 + 1];
                if (BIAS) { v0 += bias[col]; v1 += bias[col + 1]; }
                if (RELU) { v0 = fmaxf(v0, 0.f); v1 = fmaxf(v1, 0.f); }
                if (RES) {
                    const float2 rr = *(const float2*)&res[(size_t)row * N + col];
                    v0 += rr.x; v1 += rr.y;
                }
                if (OUT == 1) {
                    __half h0, l0, h1, l1;
                    splith(v0, h0, l0); splith(v1, h1, l1);
                    const __half2 hp = __halves2half2(h0, h1);
                    const __half2 lp = __halves2half2(l0, l1);
                    *(uint32_t*)&Chi[(size_t)row * N + col] = *(const uint32_t*)&hp;
                    *(uint32_t*)&Clo[(size_t)row * N + col] = *(const uint32_t*)&lp;
                } else if (OUT == 2) {
                    *(uint32_t*)&Chi[(size_t)row * N + col] = packh2(v0, v1);
                } else {
                    float2 o; o.x = v0; o.y = v1;
                    *(float2*)&Cf[(size_t)row * N + col] = o;
                }
            }
}

// ==================== weight converts ====================
__global__ void __launch_bounds__(256) wconv_kernel(
    const float* __restrict__ w, __half* __restrict__ o, int n4)
{
    for (int i = blockIdx.x * blockDim.x + threadIdx.x; i < n4;
         i += gridDim.x * blockDim.x) {
        const float4 v = ((const float4*)w)[i];
        const __half2 a = __floats2half2_rn(v.x, v.y);
        const __half2 b = __floats2half2_rn(v.z, v.w);
        uint2 u; u.x = *(const uint32_t*)&a; u.y = *(const uint32_t*)&b;
        *(uint2*)&o[(size_t)i * 4] = u;
    }
}
// convert [CDIM x CDIM] fp32 into fused [CDIM x C3] fp16 at column offset
__global__ void __launch_bounds__(256) wconv_off_kernel(
    const float* __restrict__ w, __half* __restrict__ dst, int coff)
{
    const int idx = blockIdx.x * blockDim.x + threadIdx.x;  // 131072 total
    const int row = idx >> 7;
    const int g8  = idx & 127;
    const float4 v0 = *(const float4*)&w[(size_t)row * CDIM + g8 * 8];
    const float4 v1 = *(const float4*)&w[(size_t)row * CDIM + g8 * 8 + 4];
    uint4 u;
    u.x = packh2(v0.x, v0.y); u.y = packh2(v0.z, v0.w);
    u.z = packh2(v1.x, v1.y); u.w = packh2(v1.z, v1.w);
    *(uint4*)&dst[(size_t)row * C3 + coff + g8 * 8] = u;
}

// ==================== LayerNorm -> fp16 hi/lo ====================
__inline__ __device__ float warp_sum(float v) {
    #pragma unroll
    for (int m = 16; m > 0; m >>= 1) v += __shfl_xor_sync(0xffffffffu, v, m);
    return v;
}
__global__ void __launch_bounds__(256) layernorm_split_kernel(
    const float* __restrict__ x, const float* __restrict__ g,
    const float* __restrict__ bt, __half* __restrict__ yhi, __half* __restrict__ ylo)
{
    const int row = blockIdx.x, tid = threadIdx.x;
    const float4 v = ((const float4*)(x + (size_t)row * CDIM))[tid];
    float s  = v.x + v.y + v.z + v.w;
    float ss = v.x*v.x + v.y*v.y + v.z*v.z + v.w*v.w;
    __shared__ float sh1[8], sh2[8];
    s = warp_sum(s); ss = warp_sum(ss);
    const int w = tid >> 5, l = tid & 31;
    if (l == 0) { sh1[w] = s; sh2[w] = ss; }
    __syncthreads();
    if (w == 0) {
        float a = (l < 8) ? sh1[l] : 0.f;
        float b = (l < 8) ? sh2[l] : 0.f;
        a = warp_sum(a); b = warp_sum(b);
        if (l == 0) { sh1[0] = a; sh2[0] = b; }
    }
    __syncthreads();
    const float mean = sh1[0] * (1.0f / CDIM);
    const float var  = sh2[0] * (1.0f / CDIM) - mean * mean;
    const float inv  = rsqrtf(var + 1e-5f);
    const float4 gv = ((const float4*)g)[tid];
    const float4 bv = ((const float4*)bt)[tid];
    const float o0 = (v.x - mean) * inv * gv.x + bv.x;
    const float o1 = (v.y - mean) * inv * gv.y + bv.y;
    const float o2 = (v.z - mean) * inv * gv.z + bv.z;
    const float o3 = (v.w - mean) * inv * gv.w + bv.w;
    __half h0, h1, h2, h3, l0, l1, l2, l3;
    splith(o0, h0, l0); splith(o1, h1, l1);
    splith(o2, h2, l2); splith(o3, h3, l3);
    const __half2 ha = __halves2half2(h0, h1), hb = __halves2half2(h2, h3);
    const __half2 la = __halves2half2(l0, l1), lb = __halves2half2(l2, l3);
    uint2 uh, ul;
    uh.x = *(const uint32_t*)&ha; uh.y = *(const uint32_t*)&hb;
    ul.x = *(const uint32_t*)&la; ul.y = *(const uint32_t*)&lb;
    *(uint2*)&yhi[(size_t)row * CDIM + tid * 4] = uh;
    *(uint2*)&ylo[(size_t)row * CDIM + tid * 4] = ul;
}

// ==================== tensor-core flash attention ====================
// Reads fused qkv (stride C3): Q at col 0, K at 1024, V at 2048.
#define FA_QS     18432                 // 128 x 144B
#define FA_KV     9216                  // 64 x 144B
#define FA_STAGE  36864
#define FA_SMEM   (2 * FA_QS + 2 * FA_STAGE)

__global__ void __launch_bounds__(256, 1) flash16_kernel(
    const __half* __restrict__ QKVhi, const __half* __restrict__ QKVlo,
    __half* __restrict__ Ohi, __half* __restrict__ Olo)
{
    extern __shared__ char sm[];
    const uint32_t sb = smem_u32(sm);
    const int tid = threadIdx.x, lane = tid & 31, wid = tid >> 5;
    const int qt = gridDim.x - 1 - blockIdx.x;
    const int hh = blockIdx.y, bb = blockIdx.z;
    const int rowbase = bb * TSEQ + qt * 128;
    const int colC = hh * DHEAD;

    auto loadKV = [&](int s, int kt) {
        #pragma unroll
        for (int i = 0; i < 8; i++) {
            const int c = tid + i * 256;
            const int arr = c >> 9;          // 0 Kh, 1 Kl, 2 Vh, 3 Vl
            const int r = (c >> 3) & 63;
            const int seg = c & 7;
            const __half* src = ((arr & 1) ? QKVlo : QKVhi)
                + (size_t)(bb * TSEQ + kt * 64 + r) * C3
                + (arr < 2 ? CDIM : 2 * CDIM) + colC + seg * 8;
            cp16(sb + 2 * FA_QS + (uint32_t)s * FA_STAGE + arr * FA_KV
                 + r * 144 + seg * 16, src);
        }
    };

    #pragma unroll
    for (int i = 0; i < 8; i++) {
        const int c = tid + i * 256;
        const int arr = c >> 10;
        const int r = (c >> 3) & 127;
        const int seg = c & 7;
        const __half* src = (arr ? QKVlo : QKVhi)
            + (size_t)(rowbase + r) * C3 + colC + seg * 8;
        cp16(sb + (uint32_t)arr * FA_QS + r * 144 + seg * 16, src);
    }
    cp_commit();
    loadKV(0, 0);
    cp_commit();
    cp_wait<0>();
    __syncthreads();

    uint32_t qh[4][4], ql[4][4];
    #pragma unroll
    for (int kf = 0; kf < 4; kf++) {
        const uint32_t qa = sb + (wid * 16 + (lane & 15)) * 144
                               + (kf * 16 + ((lane >> 4) << 3)) * 2;
        ldsm_x4(qh[kf], qa);
        ldsm_x4(ql[kf], qa + FA_QS);
    }

    float o[8][4];
    #pragma unroll
    for (int i = 0; i < 8; i++)
        #pragma unroll
        for (int j = 0; j < 4; j++) o[i][j] = 0.f;
    float m0 = -1e30f, m1 = -1e30f, l0 = 0.f, l1 = 0.f;

    const int ktlast = 2 * qt + 1;
    const float SCALE = 0.18033688011112042f;   // 0.125 * log2(e)

    for (int kt = 0; kt <= ktlast; kt++) {
        const int s = kt & 1;
        if (kt < ktlast) { loadKV(s ^ 1, kt + 1); cp_commit(); cp_wait<1>(); }
        else             cp_wait<0>();
        __syncthreads();

        const uint32_t kbh = sb + 2 * FA_QS + (uint32_t)s * FA_STAGE;
        const uint32_t kbl = kbh + FA_KV;
        const uint32_t vbh = kbh + 2 * FA_KV;
        const uint32_t vbl = kbh + 3 * FA_KV;

        float c[8][4];
        #pragma unroll
        for (int i = 0; i < 8; i++)
            #pragma unroll
            for (int j = 0; j < 4; j++) c[i][j] = 0.f;

        #pragma unroll
        for (int kf = 0; kf < 4; kf++)
            #pragma unroll
            for (int ntp = 0; ntp < 4; ntp++) {
                uint32_t bh[4], bl[4];
                const uint32_t ka = (ntp * 16 + (lane & 7) + ((lane >> 4) << 3)) * 144
                                  + (kf * 16 + ((lane >> 3) & 1) * 8) * 2;
                ldsm_x4(bh, kbh + ka);
                ldsm_x4(bl, kbl + ka);
                mma_f16(c[2*ntp],   qh[kf], &bh[0]);
                mma_f16(c[2*ntp],   qh[kf], &bl[0]);
                mma_f16(c[2*ntp],   ql[kf], &bh[0]);
                mma_f16(c[2*ntp+1], qh[kf], &bh[2]);
                mma_f16(c[2*ntp+1], qh[kf], &bl[2]);
                mma_f16(c[2*ntp+1], ql[kf], &bh[2]);
            }

        if (kt >= 2 * qt) {
            const int rg0 = qt * 128 + wid * 16 + (lane >> 2);
            const int cg0 = kt * 64 + (lane & 3) * 2;
            #pragma unroll
            for (int nt = 0; nt < 8; nt++) {
                const int cg = cg0 + nt * 8;
                #pragma unroll
                for (int j = 0; j < 4; j++) {
                    const int r  = rg0 + ((j >> 1) << 3);
                    const int cc = cg + (j & 1);
                    if (cc > r) c[nt][j] = -1e30f;
                }
            }
        }

        float mx0 = -1e30f, mx1 = -1e30f;
        #pragma unroll
        for (int nt = 0; nt < 8; nt++) {
            mx0 = fmaxf(mx0, fmaxf(c[nt][0], c[nt][1]));
            mx1 = fmaxf(mx1, fmaxf(c[nt][2], c[nt][3]));
        }
        mx0 = fmaxf(mx0, __shfl_xor_sync(0xffffffffu, mx0, 1));
        mx0 = fmaxf(mx0, __shfl_xor_sync(0xffffffffu, mx0, 2));
        mx1 = fmaxf(mx1, __shfl_xor_sync(0xffffffffu, mx1, 1));
        mx1 = fmaxf(mx1, __shfl_xor_sync(0xffffffffu, mx1, 2));

        const float nm0 = fmaxf(m0, mx0 * SCALE);
        const float nm1 = fmaxf(m1, mx1 * SCALE);
        const float al0 = fexp2(m0 - nm0);
        const float al1 = fexp2(m1 - nm1);
        m0 = nm0; m1 = nm1;

        float rs0 = 0.f, rs1 = 0.f;
        #pragma unroll
        for (int nt = 0; nt < 8; nt++) {
            float p0 = fexp2(fmaf(c[nt][0], SCALE, -nm0));
            float p1 = fexp2(fmaf(c[nt][1], SCALE, -nm0));
            float p2 = fexp2(fmaf(c[nt][2], SCALE, -nm1));
            float p3 = fexp2(fmaf(c[nt][3], SCALE, -nm1));
            c[nt][0] = p0; c[nt][1] = p1; c[nt][2] = p2; c[nt][3] = p3;
            rs0 += p0 + p1; rs1 += p2 + p3;
        }
        rs0 += __shfl_xor_sync(0xffffffffu, rs0, 1);
        rs0 += __shfl_xor_sync(0xffffffffu, rs0, 2);
        rs1 += __shfl_xor_sync(0xffffffffu, rs1, 1);
        rs1 += __shfl_xor_sync(0xffffffffu, rs1, 2);
        l0 = l0 * al0 + rs0;
        l1 = l1 * al1 + rs1;
        #pragma unroll
        for (int nt = 0; nt < 8; nt++) {
            o[nt][0] *= al0; o[nt][1] *= al0;
            o[nt][2] *= al1; o[nt][3] *= al1;
        }

        #pragma unroll
        for (int kf = 0; kf < 4; kf++) {
            uint32_t ph[4];
            ph[0] = packh2(c[2*kf][0],   c[2*kf][1]);
            ph[1] = packh2(c[2*kf][2],   c[2*kf][3]);
            ph[2] = packh2(c[2*kf+1][0], c[2*kf+1][1]);
            ph[3] = packh2(c[2*kf+1][2], c[2*kf+1][3]);
            #pragma unroll
            for (int ntp = 0; ntp < 4; ntp++) {
                uint32_t vh[4], vl[4];
                const uint32_t va = (kf * 16 + (lane & 15)) * 144
                                  + (ntp * 16 + ((lane >> 4) << 3)) * 2;
                ldsm_x4t(vh, vbh + va);
                ldsm_x4t(vl, vbl + va);
                mma_f16(o[2*ntp],   ph, &vh[0]);
                mma_f16(o[2*ntp],   ph, &vl[0]);
                mma_f16(o[2*ntp+1], ph, &vh[2]);
                mma_f16(o[2*ntp+1], ph, &vl[2]);
            }
        }
        __syncthreads();
    }

    const float il0 = 1.f / l0, il1 = 1.f / l1;
    const int rg = rowbase + wid * 16 + (lane >> 2);
    #pragma unroll
    for (int nt = 0; nt < 8; nt++) {
        const int col = colC + nt * 8 + (lane & 3) * 2;
        __half h0, h1, p0, p1;
        splith(o[nt][0] * il0, h0, p0);
        splith(o[nt][1] * il0, h1, p1);
        __half2 hp = __halves2half2(h0, h1), lp = __halves2half2(p0, p1);
        *(uint32_t*)&Ohi[(size_t)rg * CDIM + col] = *(const uint32_t*)&hp;
        *(uint32_t*)&Olo[(size_t)rg * CDIM + col] = *(const uint32_t*)&lp;
        splith(o[nt][2] * il1, h0, p0);
        splith(o[nt][3] * il1, h1, p1);
        hp = __halves2half2(h0, h1); lp = __halves2half2(p0, p1);
        *(uint32_t*)&Ohi[(size_t)(rg + 8) * CDIM + col] = *(const uint32_t*)&hp;
        *(uint32_t*)&Olo[(size_t)(rg + 8) * CDIM + col] = *(const uint32_t*)&lp;
    }
}

// ==================== launch ====================
extern "C" void kernel_launch(void* const* d_in, const int* in_sizes, int n_in,
                              void* d_out, int out_size)
{
    (void)in_sizes; (void)n_in; (void)out_size;
    const float* x    = (const float*)d_in[0];
    const float* Wq   = (const float*)d_in[1];
    const float* Wk   = (const float*)d_in[2];
    const float* Wv   = (const float*)d_in[3];
    const float* Wo   = (const float*)d_in[4];
    const float* bo   = (const float*)d_in[5];
    const float* ln1g = (const float*)d_in[6];
    const float* ln1b = (const float*)d_in[7];
    const float* ln2g = (const float*)d_in[8];
    const float* ln2b = (const float*)d_in[9];
    const float* W1   = (const float*)d_in[10];
    const float* b1   = (const float*)d_in[11];
    const float* W2   = (const float*)d_in[12];
    const float* b2   = (const float*)d_in[13];
    float* out = (float*)d_out;

    __half *hhi, *hlo, *qkvhi, *qkvlo, *ahi, *alo, *ff;
    float* x1;
    __half *Wqkvh, *Woh, *W1h, *W2h;
    cudaGetSymbolAddress((void**)&hhi,   g_hhi);   cudaGetSymbolAddress((void**)&hlo,   g_hlo);
    cudaGetSymbolAddress((void**)&qkvhi, g_qkvhi); cudaGetSymbolAddress((void**)&qkvlo, g_qkvlo);
    cudaGetSymbolAddress((void**)&ahi,   g_ahi);   cudaGetSymbolAddress((void**)&alo,   g_alo);
    cudaGetSymbolAddress((void**)&x1,    g_x1);
    cudaGetSymbolAddress((void**)&ff,    g_ff);
    cudaGetSymbolAddress((void**)&Wqkvh, g_Wqkv);  cudaGetSymbolAddress((void**)&Woh,   g_Wo);
    cudaGetSymbolAddress((void**)&W1h,   g_W1);    cudaGetSymbolAddress((void**)&W2h,   g_W2);

    const int SM2 = 3 * (2 * GA_TILE + 8704);   // 87552
    const int SM1 = 3 * (1 * GA_TILE + 8704);   // 56832
    cudaFuncSetAttribute(gemm16<2, false, false, false, 1>,
                         cudaFuncAttributeMaxDynamicSharedMemorySize, SM2);
    cudaFuncSetAttribute(gemm16<2, true, false, true, 0>,
                         cudaFuncAttributeMaxDynamicSharedMemorySize, SM2);
    cudaFuncSetAttribute(gemm16<1, true, true, false, 2>,
                         cudaFuncAttributeMaxDynamicSharedMemorySize, SM1);
    cudaFuncSetAttribute(gemm16<1, true, false, true, 0>,
                         cudaFuncAttributeMaxDynamicSharedMemorySize, SM1);
    cudaFuncSetAttribute(flash16_kernel,
                         cudaFuncAttributeMaxDynamicSharedMemorySize, FA_SMEM);

    // launches 0-4 (so ncu -s 5 profiles the fused QKV GEMM at index 5)
    wconv_off_kernel<<<512, 256>>>(Wq, Wqkvh, 0);
    wconv_off_kernel<<<512, 256>>>(Wk, Wqkvh, CDIM);
    wconv_off_kernel<<<512, 256>>>(Wv, Wqkvh, 2 * CDIM);
    wconv_kernel<<<512, 256>>>(Wo, Woh, CDIM * CDIM / 4);
    layernorm_split_kernel<<<MTOT, 256>>>(x, ln1g, ln1b, hhi, hlo);

    // 5: fused QKV GEMM  [MTOT x C3]
    gemm16<2, false, false, false, 1><<<dim3(C3 / 128, MTOT / 128), GT, SM2>>>(
        hhi, hlo, Wqkvh, nullptr, nullptr, nullptr, qkvhi, qkvlo, C3, CDIM);
    // 6: attention
    flash16_kernel<<<dim3(TSEQ / 128, HEADS, BB), 256, FA_SMEM>>>(
        qkvhi, qkvlo, ahi, alo);
    // 7-8: FFN weight converts (independent; placed here to keep idx 5 = GEMM)
    wconv_kernel<<<1024, 256>>>(W1, W1h, CDIM * FDIM / 4);
    wconv_kernel<<<1024, 256>>>(W2, W2h, FDIM * CDIM / 4);
    // 9: x1 = x + attn @ Wo + bo
    gemm16<2, true, false, true, 0><<<dim3(CDIM / 128, MTOT / 128), GT, SM2>>>(
        ahi, alo, Woh, bo, x, x1, nullptr, nullptr, CDIM, CDIM);
    // 10: LN2
    layernorm_split_kernel<<<MTOT, 256>>>(x1, ln2g, ln2b, hhi, hlo);
    // 11: ff = relu(h @ W1 + b1)  (single-limb A, single fp16 out)
    gemm16<1, true, true, false, 2><<<dim3(FDIM / 128, MTOT / 128), GT, SM1>>>(
        hhi, nullptr, W1h, b1, nullptr, nullptr, ff, nullptr, FDIM, CDIM);
    // 12: out = x1 + ff @ W2 + b2  (single-limb A)
    gemm16<1, true, false, true, 0><<<dim3(CDIM / 128, MTOT / 128), GT, SM1>>>(
        ff, nullptr, W2h, b2, x1, out, nullptr, nullptr, CDIM, FDIM);
}

// round 7
// speedup vs baseline: 3.0322x; 1.1855x over previous
#include <cuda_runtime.h>
#include <cuda_fp16.h>
#include <cstdint>
#include <math.h>

#define BB    4
#define TSEQ  2048
#define CDIM  1024
#define HEADS 16
#define DHEAD 64
#define MTOT  (BB * TSEQ)
#define FDIM  (4 * CDIM)
#define C3    (3 * CDIM)

// -------- scratch (device globals) --------
__device__ __half g_h    [MTOT * CDIM];              // LN out (single limb)
__device__ __half g_qkvhi[MTOT * C3], g_qkvlo[MTOT * C3];
__device__ __half g_a    [MTOT * CDIM];              // attention out (single)
__device__ float  g_x1   [MTOT * CDIM];
__device__ __half g_ff   [MTOT * FDIM];
__device__ __half g_Wqkv[CDIM * C3];
__device__ __half g_Wo[CDIM * CDIM];
__device__ __half g_W1[CDIM * FDIM], g_W2[FDIM * CDIM];

// -------- PTX helpers (plain sm_80+ only) --------
__device__ __forceinline__ uint32_t smem_u32(const void* p) {
    uint32_t a;
    asm("{ .reg .u64 t; cvta.to.shared.u64 t, %1; cvt.u32.u64 %0, t; }" : "=r"(a) : "l"(p));
    return a;
}
__device__ __forceinline__ void cp16(uint32_t dst, const void* src) {
    asm volatile("cp.async.cg.shared.global [%0], [%1], 16;" :: "r"(dst), "l"(src));
}
__device__ __forceinline__ void cp_commit() { asm volatile("cp.async.commit_group;"); }
template<int N> __device__ __forceinline__ void cp_wait() {
    asm volatile("cp.async.wait_group %0;" :: "n"(N));
}
__device__ __forceinline__ void ldsm_x4(uint32_t* r, uint32_t a) {
    asm volatile("ldmatrix.sync.aligned.m8n8.x4.shared.b16 {%0,%1,%2,%3}, [%4];"
                 : "=r"(r[0]), "=r"(r[1]), "=r"(r[2]), "=r"(r[3]) : "r"(a));
}
__device__ __forceinline__ void ldsm_x4t(uint32_t* r, uint32_t a) {
    asm volatile("ldmatrix.sync.aligned.m8n8.x4.trans.shared.b16 {%0,%1,%2,%3}, [%4];"
                 : "=r"(r[0]), "=r"(r[1]), "=r"(r[2]), "=r"(r[3]) : "r"(a));
}
__device__ __forceinline__ void mma_f16(float* c, const uint32_t* a, const uint32_t* b) {
    asm volatile(
        "mma.sync.aligned.m16n8k16.row.col.f32.f16.f16.f32 "
        "{%0,%1,%2,%3}, {%4,%5,%6,%7}, {%8,%9}, {%0,%1,%2,%3};"
        : "+f"(c[0]), "+f"(c[1]), "+f"(c[2]), "+f"(c[3])
        : "r"(a[0]), "r"(a[1]), "r"(a[2]), "r"(a[3]), "r"(b[0]), "r"(b[1]));
}
__device__ __forceinline__ void splith(float v, __half& h, __half& l) {
    h = __float2half_rn(v);
    l = __float2half_rn(v - __half2float(h));
}
__device__ __forceinline__ uint32_t packh2(float a, float b) {
    __half2 h = __floats2half2_rn(a, b);
    return *(uint32_t*)&h;
}
__device__ __forceinline__ float fexp2(float t) {   // fast 2^t, t<=0
    t = fmaxf(t, -126.0f);
    const float mag = 12582912.0f;
    float r = t + mag;
    uint32_t ui = __float_as_uint(r);
    float f = t - (r - mag);
    float p = 1.3333558146e-3f;
    p = fmaf(p, f, 9.6181291076e-3f);
    p = fmaf(p, f, 5.5504108664e-2f);
    p = fmaf(p, f, 2.4022650696e-1f);
    p = fmaf(p, f, 6.9314718056e-1f);
    p = fmaf(p, f, 1.0f);
    return __uint_as_float(__float_as_uint(p) + (ui << 23));
}

// ==================== fp16 GEMM (1 or 2 A-limbs) ====================
// C = (Ahi[+Alo]) @ B; 128x128 tile, BK=32, 256 thr, 3-stage cp.async.
// OUT: 0 = fp32, 1 = split fp16 hi/lo, 2 = single fp16.
#define GT      256
#define GA_TILE 10240   // 128 x 80B

template<int LIMBS, bool BIAS, bool RELU, bool RES, int OUT>
__global__ void __launch_bounds__(GT) gemm16(
    const __half* __restrict__ Ahi, const __half* __restrict__ Alo,
    const __half* __restrict__ B,
    const float* __restrict__ bias, const float* __restrict__ res,
    float* __restrict__ Cf, __half* __restrict__ Chi, __half* __restrict__ Clo,
    int N, int K)
{
    constexpr uint32_t BOFF  = LIMBS * GA_TILE;
    constexpr uint32_t STAGE = BOFF + 8704;
    extern __shared__ char sm[];
    const uint32_t sb = smem_u32(sm);
    const int tid = threadIdx.x, lane = tid & 31, wid = tid >> 5;
    const int wm = (wid >> 2) * 64, wn = (wid & 3) * 32;
    const int m0 = blockIdx.y * 128, n0 = blockIdx.x * 128;

    auto load_stage = [&](int s, int c) {
        const int kc = c << 5;
        const uint32_t st = sb + (uint32_t)s * STAGE;
        const int row = tid >> 1, s0 = (tid & 1) << 1;
        const size_t g = (size_t)(m0 + row) * K + kc + s0 * 8;
        const uint32_t so = st + row * 80 + s0 * 16;
        cp16(so,      Ahi + g);
        cp16(so + 16, Ahi + g + 8);
        if (LIMBS == 2) {
            cp16(so + GA_TILE,      Alo + g);
            cp16(so + GA_TILE + 16, Alo + g + 8);
        }
        const int br = tid >> 4, seg = tid & 15;
        const size_t gb = (size_t)(kc + br) * N + n0 + seg * 8;
        const uint32_t sob = st + BOFF + br * 272 + seg * 16;
        cp16(sob, B + gb);
        cp16(sob + 16 * 272, B + gb + (size_t)16 * N);
    };

    float acc[4][4][4];
    #pragma unroll
    for (int a = 0; a < 4; a++)
        #pragma unroll
        for (int b = 0; b < 4; b++)
            #pragma unroll
            for (int d = 0; d < 4; d++) acc[a][b][d] = 0.f;

    const int NC = K >> 5;
    load_stage(0, 0); cp_commit();
    load_stage(1, 1); cp_commit();
    load_stage(2, 2); cp_commit();

    for (int c = 0; c < NC; c++) {
        const int s = c % 3;
        if (c + 2 < NC)      cp_wait<2>();
        else if (c + 1 < NC) cp_wait<1>();
        else                 cp_wait<0>();
        __syncthreads();

        const uint32_t aoff = sb + (uint32_t)s * STAGE;
        const uint32_t boff = aoff + BOFF;
        #pragma unroll
        for (int ks = 0; ks < 2; ks++) {
            uint32_t bfr[4][2];
            #pragma unroll
            for (int ntp = 0; ntp < 2; ntp++) {
                uint32_t r[4];
                ldsm_x4t(r, boff + (ks * 16 + (lane & 15)) * 272
                              + (wn + ntp * 16 + ((lane >> 4) << 3)) * 2);
                bfr[2*ntp][0] = r[0]; bfr[2*ntp][1] = r[1];
                bfr[2*ntp+1][0] = r[2]; bfr[2*ntp+1][1] = r[3];
            }
            #pragma unroll
            for (int mt = 0; mt < 4; mt++) {
                uint32_t ah[4], al[4];
                const uint32_t aa = aoff + (wm + mt * 16 + (lane & 15)) * 80
                                        + (ks * 16 + ((lane >> 4) << 3)) * 2;
                ldsm_x4(ah, aa);
                if (LIMBS == 2) ldsm_x4(al, aa + GA_TILE);
                #pragma unroll
                for (int nt = 0; nt < 4; nt++) {
                    mma_f16(acc[mt][nt], ah, bfr[nt]);
                    if (LIMBS == 2) mma_f16(acc[mt][nt], al, bfr[nt]);
                }
            }
        }
        __syncthreads();
        if (c + 3 < NC) { load_stage(s, c + 3); cp_commit(); }
    }

    #pragma unroll
    for (int mt = 0; mt < 4; mt++)
        #pragma unroll
        for (int nt = 0; nt < 4; nt++)
            #pragma unroll
            for (int hf = 0; hf < 2; hf++) {
                const int row = m0 + wm + mt * 16 + (lane >> 2) + hf * 8;
                const int col = n0 + wn + nt * 8 + (lane & 3) * 2;
                float v0 = acc[mt][nt][hf * 2 + 0];
                float v1 = acc[mt][nt][hf * 2 + 1];
                if (BIAS) { v0 += bias[col]; v1 += bias[col + 1]; }
                if (RELU) { v0 = fmaxf(v0, 0.f); v1 = fmaxf(v1, 0.f); }
                if (RES) {
                    const float2 rr = *(const float2*)&res[(size_t)row * N + col];
                    v0 += rr.x; v1 += rr.y;
                }
                if (OUT == 1) {
                    __half h0, l0, h1, l1;
                    splith(v0, h0, l0); splith(v1, h1, l1);
                    const __half2 hp = __halves2half2(h0, h1);
                    const __half2 lp = __halves2half2(l0, l1);
                    *(uint32_t*)&Chi[(size_t)row * N + col] = *(const uint32_t*)&hp;
                    *(uint32_t*)&Clo[(size_t)row * N + col] = *(const uint32_t*)&lp;
                } else if (OUT == 2) {
                    *(uint32_t*)&Chi[(size_t)row * N + col] = packh2(v0, v1);
                } else {
                    float2 o; o.x = v0; o.y = v1;
                    *(float2*)&Cf[(size_t)row * N + col] = o;
                }
            }
}

// ==================== weight converts ====================
__global__ void __launch_bounds__(256) wconv_kernel(
    const float* __restrict__ w, __half* __restrict__ o, int n4)
{
    for (int i = blockIdx.x * blockDim.x + threadIdx.x; i < n4;
         i += gridDim.x * blockDim.x) {
        const float4 v = ((const float4*)w)[i];
        const __half2 a = __floats2half2_rn(v.x, v.y);
        const __half2 b = __floats2half2_rn(v.z, v.w);
        uint2 u; u.x = *(const uint32_t*)&a; u.y = *(const uint32_t*)&b;
        *(uint2*)&o[(size_t)i * 4] = u;
    }
}
__global__ void __launch_bounds__(256) wconv_off_kernel(
    const float* __restrict__ w, __half* __restrict__ dst, int coff)
{
    const int idx = blockIdx.x * blockDim.x + threadIdx.x;
    const int row = idx >> 7;
    const int g8  = idx & 127;
    const float4 v0 = *(const float4*)&w[(size_t)row * CDIM + g8 * 8];
    const float4 v1 = *(const float4*)&w[(size_t)row * CDIM + g8 * 8 + 4];
    uint4 u;
    u.x = packh2(v0.x, v0.y); u.y = packh2(v0.z, v0.w);
    u.z = packh2(v1.x, v1.y); u.w = packh2(v1.z, v1.w);
    *(uint4*)&dst[(size_t)row * C3 + coff + g8 * 8] = u;
}

// ==================== LayerNorm -> single fp16 ====================
__inline__ __device__ float warp_sum(float v) {
    #pragma unroll
    for (int m = 16; m > 0; m >>= 1) v += __shfl_xor_sync(0xffffffffu, v, m);
    return v;
}
__global__ void __launch_bounds__(256) layernorm_h_kernel(
    const float* __restrict__ x, const float* __restrict__ g,
    const float* __restrict__ bt, __half* __restrict__ y)
{
    const int row = blockIdx.x, tid = threadIdx.x;
    const float4 v = ((const float4*)(x + (size_t)row * CDIM))[tid];
    float s  = v.x + v.y + v.z + v.w;
    float ss = v.x*v.x + v.y*v.y + v.z*v.z + v.w*v.w;
    __shared__ float sh1[8], sh2[8];
    s = warp_sum(s); ss = warp_sum(ss);
    const int w = tid >> 5, l = tid & 31;
    if (l == 0) { sh1[w] = s; sh2[w] = ss; }
    __syncthreads();
    if (w == 0) {
        float a = (l < 8) ? sh1[l] : 0.f;
        float b = (l < 8) ? sh2[l] : 0.f;
        a = warp_sum(a); b = warp_sum(b);
        if (l == 0) { sh1[0] = a; sh2[0] = b; }
    }
    __syncthreads();
    const float mean = sh1[0] * (1.0f / CDIM);
    const float var  = sh2[0] * (1.0f / CDIM) - mean * mean;
    const float inv  = rsqrtf(var + 1e-5f);
    const float4 gv = ((const float4*)g)[tid];
    const float4 bv = ((const float4*)bt)[tid];
    uint2 u;
    u.x = packh2((v.x - mean) * inv * gv.x + bv.x,
                 (v.y - mean) * inv * gv.y + bv.y);
    u.y = packh2((v.z - mean) * inv * gv.z + bv.z,
                 (v.w - mean) * inv * gv.w + bv.w);
    *(uint2*)&y[(size_t)row * CDIM + tid * 4] = u;
}

// ==================== tensor-core flash attention ====================
// qkv fused (stride C3): Q col 0, K col 1024, V col 2048.
// QK^T: q hi-limb x (k hi + k lo) = 2 mmas. PV: P x (v hi + v lo) = 2 mmas.
#define FA_QS     18432                 // 128 x 144B (q hi only)
#define FA_KV     9216                  // 64 x 144B
#define FA_STAGE  36864                 // Kh, Kl, Vh, Vl
#define FA_SMEM   (FA_QS + 2 * FA_STAGE)   // 92160

__global__ void __launch_bounds__(256, 1) flash16_kernel(
    const __half* __restrict__ QKVhi, const __half* __restrict__ QKVlo,
    __half* __restrict__ O)
{
    extern __shared__ char sm[];
    const uint32_t sb = smem_u32(sm);
    const int tid = threadIdx.x, lane = tid & 31, wid = tid >> 5;
    const int qt = gridDim.x - 1 - blockIdx.x;
    const int hh = blockIdx.y, bb = blockIdx.z;
    const int rowbase = bb * TSEQ + qt * 128;
    const int colC = hh * DHEAD;

    auto loadKV = [&](int s, int kt) {
        #pragma unroll
        for (int i = 0; i < 8; i++) {
            const int c = tid + i * 256;
            const int arr = c >> 9;          // 0 Kh, 1 Kl, 2 Vh, 3 Vl
            const int r = (c >> 3) & 63;
            const int seg = c & 7;
            const __half* src = ((arr & 1) ? QKVlo : QKVhi)
                + (size_t)(bb * TSEQ + kt * 64 + r) * C3
                + (arr < 2 ? CDIM : 2 * CDIM) + colC + seg * 8;
            cp16(sb + FA_QS + (uint32_t)s * FA_STAGE + arr * FA_KV
                 + r * 144 + seg * 16, src);
        }
    };

    // Q hi tile: 128 rows x 64B = 512 cp16 / 256 threads
    #pragma unroll
    for (int i = 0; i < 2; i++) {
        const int c = tid + i * 256;
        const int r = c >> 2;
        const int seg = c & 3;
        const __half* src = QKVhi + (size_t)(rowbase + r) * C3 + colC + seg * 16;
        cp16(sb + r * 144 + seg * 32, src);
        cp16(sb + r * 144 + seg * 32 + 16, src + 8);
    }
    cp_commit();
    loadKV(0, 0);
    cp_commit();
    cp_wait<0>();
    __syncthreads();

    uint32_t qh[4][4];
    #pragma unroll
    for (int kf = 0; kf < 4; kf++) {
        const uint32_t qa = sb + (wid * 16 + (lane & 15)) * 144
                               + (kf * 16 + ((lane >> 4) << 3)) * 2;
        ldsm_x4(qh[kf], qa);
    }

    float o[8][4];
    #pragma unroll
    for (int i = 0; i < 8; i++)
        #pragma unroll
        for (int j = 0; j < 4; j++) o[i][j] = 0.f;
    float m0 = -1e30f, m1 = -1e30f, l0 = 0.f, l1 = 0.f;

    const int ktlast = 2 * qt + 1;
    const float SCALE = 0.18033688011112042f;   // 0.125 * log2(e)

    for (int kt = 0; kt <= ktlast; kt++) {
        const int s = kt & 1;
        if (kt < ktlast) { loadKV(s ^ 1, kt + 1); cp_commit(); cp_wait<1>(); }
        else             cp_wait<0>();
        __syncthreads();

        const uint32_t kbh = sb + FA_QS + (uint32_t)s * FA_STAGE;
        const uint32_t kbl = kbh + FA_KV;
        const uint32_t vbh = kbh + 2 * FA_KV;
        const uint32_t vbl = kbh + 3 * FA_KV;

        float c[8][4];
        #pragma unroll
        for (int i = 0; i < 8; i++)
            #pragma unroll
            for (int j = 0; j < 4; j++) c[i][j] = 0.f;

        #pragma unroll
        for (int kf = 0; kf < 4; kf++)
            #pragma unroll
            for (int ntp = 0; ntp < 4; ntp++) {
                uint32_t bh[4], bl[4];
                const uint32_t ka = (ntp * 16 + (lane & 7) + ((lane >> 4) << 3)) * 144
                                  + (kf * 16 + ((lane >> 3) & 1) * 8) * 2;
                ldsm_x4(bh, kbh + ka);
                ldsm_x4(bl, kbl + ka);
                mma_f16(c[2*ntp],   qh[kf], &bh[0]);
                mma_f16(c[2*ntp],   qh[kf], &bl[0]);
                mma_f16(c[2*ntp+1], qh[kf], &bh[2]);
                mma_f16(c[2*ntp+1], qh[kf], &bl[2]);
            }

        if (kt >= 2 * qt) {
            const int rg0 = qt * 128 + wid * 16 + (lane >> 2);
            const int cg0 = kt * 64 + (lane & 3) * 2;
            #pragma unroll
            for (int nt = 0; nt < 8; nt++) {
                const int cg = cg0 + nt * 8;
                #pragma unroll
                for (int j = 0; j < 4; j++) {
                    const int r  = rg0 + ((j >> 1) << 3);
                    const int cc = cg + (j & 1);
                    if (cc > r) c[nt][j] = -1e30f;
                }
            }
        }

        float mx0 = -1e30f, mx1 = -1e30f;
        #pragma unroll
        for (int nt = 0; nt < 8; nt++) {
            mx0 = fmaxf(mx0, fmaxf(c[nt][0], c[nt][1]));
            mx1 = fmaxf(mx1, fmaxf(c[nt][2], c[nt][3]));
        }
        mx0 = fmaxf(mx0, __shfl_xor_sync(0xffffffffu, mx0, 1));
        mx0 = fmaxf(mx0, __shfl_xor_sync(0xffffffffu, mx0, 2));
        mx1 = fmaxf(mx1, __shfl_xor_sync(0xffffffffu, mx1, 1));
        mx1 = fmaxf(mx1, __shfl_xor_sync(0xffffffffu, mx1, 2));

        const float nm0 = fmaxf(m0, mx0 * SCALE);
        const float nm1 = fmaxf(m1, mx1 * SCALE);
        const float al0 = fexp2(m0 - nm0);
        const float al1 = fexp2(m1 - nm1);
        m0 = nm0; m1 = nm1;

        float rs0 = 0.f, rs1 = 0.f;
        #pragma unroll
        for (int nt = 0; nt < 8; nt++) {
            float p0 = fexp2(fmaf(c[nt][0], SCALE, -nm0));
            float p1 = fexp2(fmaf(c[nt][1], SCALE, -nm0));
            float p2 = fexp2(fmaf(c[nt][2], SCALE, -nm1));
            float p3 = fexp2(fmaf(c[nt][3], SCALE, -nm1));
            c[nt][0] = p0; c[nt][1] = p1; c[nt][2] = p2; c[nt][3] = p3;
            rs0 += p0 + p1; rs1 += p2 + p3;
        }
        rs0 += __shfl_xor_sync(0xffffffffu, rs0, 1);
        rs0 += __shfl_xor_sync(0xffffffffu, rs0, 2);
        rs1 += __shfl_xor_sync(0xffffffffu, rs1, 1);
        rs1 += __shfl_xor_sync(0xffffffffu, rs1, 2);
        l0 = l0 * al0 + rs0;
        l1 = l1 * al1 + rs1;
        #pragma unroll
        for (int nt = 0; nt < 8; nt++) {
            o[nt][0] *= al0; o[nt][1] *= al0;
            o[nt][2] *= al1; o[nt][3] *= al1;
        }

        #pragma unroll
        for (int kf = 0; kf < 4; kf++) {
            uint32_t ph[4];
            ph[0] = packh2(c[2*kf][0],   c[2*kf][1]);
            ph[1] = packh2(c[2*kf][2],   c[2*kf][3]);
            ph[2] = packh2(c[2*kf+1][0], c[2*kf+1][1]);
            ph[3] = packh2(c[2*kf+1][2], c[2*kf+1][3]);
            #pragma unroll
            for (int ntp = 0; ntp < 4; ntp++) {
                uint32_t vh[4], vl[4];
                const uint32_t va = (kf * 16 + (lane & 15)) * 144
                                  + (ntp * 16 + ((lane >> 4) << 3)) * 2;
                ldsm_x4t(vh, vbh + va);
                ldsm_x4t(vl, vbl + va);
                mma_f16(o[2*ntp],   ph, &vh[0]);
                mma_f16(o[2*ntp],   ph, &vl[0]);
                mma_f16(o[2*ntp+1], ph, &vh[2]);
                mma_f16(o[2*ntp+1], ph, &vl[2]);
            }
        }
        __syncthreads();
    }

    const float il0 = 1.f / l0, il1 = 1.f / l1;
    const int rg = rowbase + wid * 16 + (lane >> 2);
    #pragma unroll
    for (int nt = 0; nt < 8; nt++) {
        const int col = colC + nt * 8 + (lane & 3) * 2;
        *(uint32_t*)&O[(size_t)rg * CDIM + col] =
            packh2(o[nt][0] * il0, o[nt][1] * il0);
        *(uint32_t*)&O[(size_t)(rg + 8) * CDIM + col] =
            packh2(o[nt][2] * il1, o[nt][3] * il1);
    }
}

// ==================== launch ====================
extern "C" void kernel_launch(void* const* d_in, const int* in_sizes, int n_in,
                              void* d_out, int out_size)
{
    (void)in_sizes; (void)n_in; (void)out_size;
    const float* x    = (const float*)d_in[0];
    const float* Wq   = (const float*)d_in[1];
    const float* Wk   = (const float*)d_in[2];
    const float* Wv   = (const float*)d_in[3];
    const float* Wo   = (const float*)d_in[4];
    const float* bo   = (const float*)d_in[5];
    const float* ln1g = (const float*)d_in[6];
    const float* ln1b = (const float*)d_in[7];
    const float* ln2g = (const float*)d_in[8];
    const float* ln2b = (const float*)d_in[9];
    const float* W1   = (const float*)d_in[10];
    const float* b1   = (const float*)d_in[11];
    const float* W2   = (const float*)d_in[12];
    const float* b2   = (const float*)d_in[13];
    float* out = (float*)d_out;

    __half *h, *qkvhi, *qkvlo, *a, *ff;
    float* x1;
    __half *Wqkvh, *Woh, *W1h, *W2h;
    cudaGetSymbolAddress((void**)&h,     g_h);
    cudaGetSymbolAddress((void**)&qkvhi, g_qkvhi);
    cudaGetSymbolAddress((void**)&qkvlo, g_qkvlo);
    cudaGetSymbolAddress((void**)&a,     g_a);
    cudaGetSymbolAddress((void**)&x1,    g_x1);
    cudaGetSymbolAddress((void**)&ff,    g_ff);
    cudaGetSymbolAddress((void**)&Wqkvh, g_Wqkv);
    cudaGetSymbolAddress((void**)&Woh,   g_Wo);
    cudaGetSymbolAddress((void**)&W1h,   g_W1);
    cudaGetSymbolAddress((void**)&W2h,   g_W2);

    const int SM1 = 3 * (1 * GA_TILE + 8704);   // 56832
    cudaFuncSetAttribute(gemm16<1, false, false, false, 1>,
                         cudaFuncAttributeMaxDynamicSharedMemorySize, SM1);
    cudaFuncSetAttribute(gemm16<1, true, false, true, 0>,
                         cudaFuncAttributeMaxDynamicSharedMemorySize, SM1);
    cudaFuncSetAttribute(gemm16<1, true, true, false, 2>,
                         cudaFuncAttributeMaxDynamicSharedMemorySize, SM1);
    cudaFuncSetAttribute(flash16_kernel,
                         cudaFuncAttributeMaxDynamicSharedMemorySize, FA_SMEM);

    wconv_off_kernel<<<512, 256>>>(Wq, Wqkvh, 0);
    wconv_off_kernel<<<512, 256>>>(Wk, Wqkvh, CDIM);
    wconv_off_kernel<<<512, 256>>>(Wv, Wqkvh, 2 * CDIM);
    wconv_kernel<<<512, 256>>>(Wo, Woh, CDIM * CDIM / 4);
    layernorm_h_kernel<<<MTOT, 256>>>(x, ln1g, ln1b, h);

    // fused QKV GEMM (single-limb A, split hi/lo out)
    gemm16<1, false, false, false, 1><<<dim3(C3 / 128, MTOT / 128), GT, SM1>>>(
        h, nullptr, Wqkvh, nullptr, nullptr, nullptr, qkvhi, qkvlo, C3, CDIM);
    // attention (q hi-limb, k/v 2-limb)
    flash16_kernel<<<dim3(TSEQ / 128, HEADS, BB), 256, FA_SMEM>>>(
        qkvhi, qkvlo, a);
    // FFN weight converts (independent)
    wconv_kernel<<<1024, 256>>>(W1, W1h, CDIM * FDIM / 4);
    wconv_kernel<<<1024, 256>>>(W2, W2h, FDIM * CDIM / 4);
    // x1 = x + attn @ Wo + bo  (single-limb A)
    gemm16<1, true, false, true, 0><<<dim3(CDIM / 128, MTOT / 128), GT, SM1>>>(
        a, nullptr, Woh, bo, x, x1, nullptr, nullptr, CDIM, CDIM);
    // LN2
    layernorm_h_kernel<<<MTOT, 256>>>(x1, ln2g, ln2b, h);
    // ff = relu(h @ W1 + b1)
    gemm16<1, true, true, false, 2><<<dim3(FDIM / 128, MTOT / 128), GT, SM1>>>(
        h, nullptr, W1h, b1, nullptr, nullptr, ff, nullptr, FDIM, CDIM);
    // out = x1 + ff @ W2 + b2
    gemm16<1, true, false, true, 0><<<dim3(CDIM / 128, MTOT / 128), GT, SM1>>>(
        ff, nullptr, W2h, b2, x1, out, nullptr, nullptr, CDIM, FDIM);
}

// round 8
// speedup vs baseline: 3.0819x; 1.0164x over previous
#include <cuda_runtime.h>
#include <cuda_fp16.h>
#include <cstdint>
#include <math.h>

#define BB    4
#define TSEQ  2048
#define CDIM  1024
#define HEADS 16
#define DHEAD 64
#define MTOT  (BB * TSEQ)
#define FDIM  (4 * CDIM)
#define C3    (3 * CDIM)

// -------- scratch (device globals) --------
__device__ __half g_h    [MTOT * CDIM];
__device__ __half g_qkvhi[MTOT * C3], g_qkvlo[MTOT * C3];
__device__ __half g_a    [MTOT * CDIM];
__device__ float  g_x1   [MTOT * CDIM];
__device__ __half g_ff   [MTOT * FDIM];
__device__ __half g_Wqkv[CDIM * C3];
__device__ __half g_Wo[CDIM * CDIM];
__device__ __half g_W1[CDIM * FDIM], g_W2[FDIM * CDIM];

// -------- PTX helpers (plain sm_80+ only) --------
__device__ __forceinline__ uint32_t smem_u32(const void* p) {
    uint32_t a;
    asm("{ .reg .u64 t; cvta.to.shared.u64 t, %1; cvt.u32.u64 %0, t; }" : "=r"(a) : "l"(p));
    return a;
}
__device__ __forceinline__ void cp16(uint32_t dst, const void* src) {
    asm volatile("cp.async.cg.shared.global [%0], [%1], 16;" :: "r"(dst), "l"(src));
}
__device__ __forceinline__ void cp_commit() { asm volatile("cp.async.commit_group;"); }
template<int N> __device__ __forceinline__ void cp_wait() {
    asm volatile("cp.async.wait_group %0;" :: "n"(N));
}
__device__ __forceinline__ void ldsm_x4(uint32_t* r, uint32_t a) {
    asm volatile("ldmatrix.sync.aligned.m8n8.x4.shared.b16 {%0,%1,%2,%3}, [%4];"
                 : "=r"(r[0]), "=r"(r[1]), "=r"(r[2]), "=r"(r[3]) : "r"(a));
}
__device__ __forceinline__ void ldsm_x4t(uint32_t* r, uint32_t a) {
    asm volatile("ldmatrix.sync.aligned.m8n8.x4.trans.shared.b16 {%0,%1,%2,%3}, [%4];"
                 : "=r"(r[0]), "=r"(r[1]), "=r"(r[2]), "=r"(r[3]) : "r"(a));
}
__device__ __forceinline__ void mma_f16(float* c, const uint32_t* a, const uint32_t* b) {
    asm volatile(
        "mma.sync.aligned.m16n8k16.row.col.f32.f16.f16.f32 "
        "{%0,%1,%2,%3}, {%4,%5,%6,%7}, {%8,%9}, {%0,%1,%2,%3};"
        : "+f"(c[0]), "+f"(c[1]), "+f"(c[2]), "+f"(c[3])
        : "r"(a[0]), "r"(a[1]), "r"(a[2]), "r"(a[3]), "r"(b[0]), "r"(b[1]));
}
__device__ __forceinline__ void splith(float v, __half& h, __half& l) {
    h = __float2half_rn(v);
    l = __float2half_rn(v - __half2float(h));
}
__device__ __forceinline__ uint32_t packh2(float a, float b) {
    __half2 h = __floats2half2_rn(a, b);
    return *(uint32_t*)&h;
}
__device__ __forceinline__ float fexp2(float t) {   // fast 2^t, t<=0
    t = fmaxf(t, -126.0f);
    const float mag = 12582912.0f;
    float r = t + mag;
    uint32_t ui = __float_as_uint(r);
    float f = t - (r - mag);
    float p = 1.3333558146e-3f;
    p = fmaf(p, f, 9.6181291076e-3f);
    p = fmaf(p, f, 5.5504108664e-2f);
    p = fmaf(p, f, 2.4022650696e-1f);
    p = fmaf(p, f, 6.9314718056e-1f);
    p = fmaf(p, f, 1.0f);
    return __uint_as_float(__float_as_uint(p) + (ui << 23));
}

// ==================== fp16 GEMM (single-limb A, BK=64, 2-stage) ==========
// C = A @ B; 128x128 tile, 256 thr (2x4 warps, 64x32 warp tiles).
// OUT: 0 = fp32, 1 = split fp16 hi/lo, 2 = single fp16.
#define GT       256
#define GA2      18432   // 128 rows x 144B (64 fp16 + pad)
#define GB2      17408   // 64 rows x 272B (128 fp16 + pad)
#define GSTG     (GA2 + GB2)        // 35840
#define GEMM_SMEM (2 * GSTG)        // 71680

template<bool BIAS, bool RELU, bool RES, int OUT>
__global__ void __launch_bounds__(GT) gemm16(
    const __half* __restrict__ A, const __half* __restrict__ B,
    const float* __restrict__ bias, const float* __restrict__ res,
    float* __restrict__ Cf, __half* __restrict__ Chi, __half* __restrict__ Clo,
    int N, int K)
{
    extern __shared__ char sm[];
    const uint32_t sb = smem_u32(sm);
    const int tid = threadIdx.x, lane = tid & 31, wid = tid >> 5;
    const int wm = (wid >> 2) * 64, wn = (wid & 3) * 32;
    const int m0 = blockIdx.y * 128, n0 = blockIdx.x * 128;

    auto load_stage = [&](int s, int c) {
        const int kc = c << 6;
        const uint32_t st = sb + (uint32_t)s * GSTG;
        // A: 128 rows x 128B; thread: row = tid/2, 4 consecutive 16B segs
        const int row = tid >> 1, sg0 = (tid & 1) << 2;
        const size_t g = (size_t)(m0 + row) * K + kc + sg0 * 8;
        const uint32_t so = st + row * 144 + sg0 * 16;
        cp16(so,      A + g);
        cp16(so + 16, A + g + 8);
        cp16(so + 32, A + g + 16);
        cp16(so + 48, A + g + 24);
        // B: 64 rows x 256B; thread: rows {tid/16 + 16j}, seg tid%16
        const int br = tid >> 4, seg = tid & 15;
        #pragma unroll
        for (int j = 0; j < 4; j++) {
            const size_t gb = (size_t)(kc + br + 16 * j) * N + n0 + seg * 8;
            cp16(st + GA2 + (br + 16 * j) * 272 + seg * 16, B + gb);
        }
    };

    float acc[4][4][4];
    #pragma unroll
    for (int a = 0; a < 4; a++)
        #pragma unroll
        for (int b = 0; b < 4; b++)
            #pragma unroll
            for (int d = 0; d < 4; d++) acc[a][b][d] = 0.f;

    const int NC = K >> 6;
    load_stage(0, 0); cp_commit();
    load_stage(1, 1); cp_commit();

    for (int c = 0; c < NC; c++) {
        const int s = c & 1;
        if (c + 1 < NC) cp_wait<1>();
        else            cp_wait<0>();
        __syncthreads();

        const uint32_t aoff = sb + (uint32_t)s * GSTG;
        const uint32_t boff = aoff + GA2;
        #pragma unroll
        for (int ks = 0; ks < 4; ks++) {
            uint32_t bfr[4][2];
            #pragma unroll
            for (int ntp = 0; ntp < 2; ntp++) {
                uint32_t r[4];
                ldsm_x4t(r, boff + (ks * 16 + (lane & 15)) * 272
                              + (wn + ntp * 16 + ((lane >> 4) << 3)) * 2);
                bfr[2*ntp][0] = r[0]; bfr[2*ntp][1] = r[1];
                bfr[2*ntp+1][0] = r[2]; bfr[2*ntp+1][1] = r[3];
            }
            #pragma unroll
            for (int mt = 0; mt < 4; mt++) {
                uint32_t ah[4];
                ldsm_x4(ah, aoff + (wm + mt * 16 + (lane & 15)) * 144
                              + (ks * 16 + ((lane >> 4) << 3)) * 2);
                #pragma unroll
                for (int nt = 0; nt < 4; nt++)
                    mma_f16(acc[mt][nt], ah, bfr[nt]);
            }
        }
        __syncthreads();
        if (c + 2 < NC) { load_stage(s, c + 2); cp_commit(); }
    }

    #pragma unroll
    for (int mt = 0; mt < 4; mt++)
        #pragma unroll
        for (int nt = 0; nt < 4; nt++)
            #pragma unroll
            for (int hf = 0; hf < 2; hf++) {
                const int row = m0 + wm + mt * 16 + (lane >> 2) + hf * 8;
                const int col = n0 + wn + nt * 8 + (lane & 3) * 2;
                float v0 = acc[mt][nt][hf * 2 + 0];
                float v1 = acc[mt][nt][hf * 2 + 1];
                if (BIAS) { v0 += bias[col]; v1 += bias[col + 1]; }
                if (RELU) { v0 = fmaxf(v0, 0.f); v1 = fmaxf(v1, 0.f); }
                if (RES) {
                    const float2 rr = *(const float2*)&res[(size_t)row * N + col];
                    v0 += rr.x; v1 += rr.y;
                }
                if (OUT == 1) {
                    __half h0, l0, h1, l1;
                    splith(v0, h0, l0); splith(v1, h1, l1);
                    const __half2 hp = __halves2half2(h0, h1);
                    const __half2 lp = __halves2half2(l0, l1);
                    *(uint32_t*)&Chi[(size_t)row * N + col] = *(const uint32_t*)&hp;
                    *(uint32_t*)&Clo[(size_t)row * N + col] = *(const uint32_t*)&lp;
                } else if (OUT == 2) {
                    *(uint32_t*)&Chi[(size_t)row * N + col] = packh2(v0, v1);
                } else {
                    float2 o; o.x = v0; o.y = v1;
                    *(float2*)&Cf[(size_t)row * N + col] = o;
                }
            }
}

// ==================== weight converts ====================
__global__ void __launch_bounds__(256) wconv_kernel(
    const float* __restrict__ w, __half* __restrict__ o, int n4)
{
    for (int i = blockIdx.x * blockDim.x + threadIdx.x; i < n4;
         i += gridDim.x * blockDim.x) {
        const float4 v = ((const float4*)w)[i];
        const __half2 a = __floats2half2_rn(v.x, v.y);
        const __half2 b = __floats2half2_rn(v.z, v.w);
        uint2 u; u.x = *(const uint32_t*)&a; u.y = *(const uint32_t*)&b;
        *(uint2*)&o[(size_t)i * 4] = u;
    }
}
__global__ void __launch_bounds__(256) wconv_off_kernel(
    const float* __restrict__ w, __half* __restrict__ dst, int coff)
{
    const int idx = blockIdx.x * blockDim.x + threadIdx.x;
    const int row = idx >> 7;
    const int g8  = idx & 127;
    const float4 v0 = *(const float4*)&w[(size_t)row * CDIM + g8 * 8];
    const float4 v1 = *(const float4*)&w[(size_t)row * CDIM + g8 * 8 + 4];
    uint4 u;
    u.x = packh2(v0.x, v0.y); u.y = packh2(v0.z, v0.w);
    u.z = packh2(v1.x, v1.y); u.w = packh2(v1.z, v1.w);
    *(uint4*)&dst[(size_t)row * C3 + coff + g8 * 8] = u;
}

// ==================== LayerNorm -> single fp16 ====================
__inline__ __device__ float warp_sum(float v) {
    #pragma unroll
    for (int m = 16; m > 0; m >>= 1) v += __shfl_xor_sync(0xffffffffu, v, m);
    return v;
}
__global__ void __launch_bounds__(256) layernorm_h_kernel(
    const float* __restrict__ x, const float* __restrict__ g,
    const float* __restrict__ bt, __half* __restrict__ y)
{
    const int row = blockIdx.x, tid = threadIdx.x;
    const float4 v = ((const float4*)(x + (size_t)row * CDIM))[tid];
    float s  = v.x + v.y + v.z + v.w;
    float ss = v.x*v.x + v.y*v.y + v.z*v.z + v.w*v.w;
    __shared__ float sh1[8], sh2[8];
    s = warp_sum(s); ss = warp_sum(ss);
    const int w = tid >> 5, l = tid & 31;
    if (l == 0) { sh1[w] = s; sh2[w] = ss; }
    __syncthreads();
    if (w == 0) {
        float a = (l < 8) ? sh1[l] : 0.f;
        float b = (l < 8) ? sh2[l] : 0.f;
        a = warp_sum(a); b = warp_sum(b);
        if (l == 0) { sh1[0] = a; sh2[0] = b; }
    }
    __syncthreads();
    const float mean = sh1[0] * (1.0f / CDIM);
    const float var  = sh2[0] * (1.0f / CDIM) - mean * mean;
    const float inv  = rsqrtf(var + 1e-5f);
    const float4 gv = ((const float4*)g)[tid];
    const float4 bv = ((const float4*)bt)[tid];
    uint2 u;
    u.x = packh2((v.x - mean) * inv * gv.x + bv.x,
                 (v.y - mean) * inv * gv.y + bv.y);
    u.y = packh2((v.z - mean) * inv * gv.z + bv.z,
                 (v.w - mean) * inv * gv.w + bv.w);
    *(uint2*)&y[(size_t)row * CDIM + tid * 4] = u;
}

// ==================== tensor-core flash attention ====================
// qkv fused (stride C3). QK^T: q hi x (k hi + k lo). PV: P x v hi only.
#define FA_QS     18432                 // 128 x 144B
#define FA_KV     9216                  // 64 x 144B
#define FA_STAGE  27648                 // Kh, Kl, Vh
#define FA_SMEM   (FA_QS + 2 * FA_STAGE)   // 73728

__global__ void __launch_bounds__(256, 1) flash16_kernel(
    const __half* __restrict__ QKVhi, const __half* __restrict__ QKVlo,
    __half* __restrict__ O)
{
    extern __shared__ char sm[];
    const uint32_t sb = smem_u32(sm);
    const int tid = threadIdx.x, lane = tid & 31, wid = tid >> 5;
    const int qt = gridDim.x - 1 - blockIdx.x;
    const int hh = blockIdx.y, bb = blockIdx.z;
    const int rowbase = bb * TSEQ + qt * 128;
    const int colC = hh * DHEAD;

    auto loadKV = [&](int s, int kt) {
        #pragma unroll
        for (int i = 0; i < 6; i++) {
            const int c = tid + i * 256;
            const int arr = c / 512;         // 0 Kh, 1 Kl, 2 Vh
            const int r = (c >> 3) & 63;
            const int seg = c & 7;
            const __half* src = ((arr == 1) ? QKVlo : QKVhi)
                + (size_t)(bb * TSEQ + kt * 64 + r) * C3
                + (arr < 2 ? CDIM : 2 * CDIM) + colC + seg * 8;
            cp16(sb + FA_QS + (uint32_t)s * FA_STAGE + arr * FA_KV
                 + r * 144 + seg * 16, src);
        }
    };

    #pragma unroll
    for (int i = 0; i < 2; i++) {
        const int c = tid + i * 256;
        const int r = c >> 2;
        const int seg = c & 3;
        const __half* src = QKVhi + (size_t)(rowbase + r) * C3 + colC + seg * 16;
        cp16(sb + r * 144 + seg * 32, src);
        cp16(sb + r * 144 + seg * 32 + 16, src + 8);
    }
    cp_commit();
    loadKV(0, 0);
    cp_commit();
    cp_wait<0>();
    __syncthreads();

    uint32_t qh[4][4];
    #pragma unroll
    for (int kf = 0; kf < 4; kf++) {
        const uint32_t qa = sb + (wid * 16 + (lane & 15)) * 144
                               + (kf * 16 + ((lane >> 4) << 3)) * 2;
        ldsm_x4(qh[kf], qa);
    }

    float o[8][4];
    #pragma unroll
    for (int i = 0; i < 8; i++)
        #pragma unroll
        for (int j = 0; j < 4; j++) o[i][j] = 0.f;
    float m0 = -1e30f, m1 = -1e30f, l0 = 0.f, l1 = 0.f;

    const int ktlast = 2 * qt + 1;
    const float SCALE = 0.18033688011112042f;   // 0.125 * log2(e)

    for (int kt = 0; kt <= ktlast; kt++) {
        const int s = kt & 1;
        if (kt < ktlast) { loadKV(s ^ 1, kt + 1); cp_commit(); cp_wait<1>(); }
        else             cp_wait<0>();
        __syncthreads();

        const uint32_t kbh = sb + FA_QS + (uint32_t)s * FA_STAGE;
        const uint32_t kbl = kbh + FA_KV;
        const uint32_t vbh = kbh + 2 * FA_KV;

        float c[8][4];
        #pragma unroll
        for (int i = 0; i < 8; i++)
            #pragma unroll
            for (int j = 0; j < 4; j++) c[i][j] = 0.f;

        #pragma unroll
        for (int kf = 0; kf < 4; kf++)
            #pragma unroll
            for (int ntp = 0; ntp < 4; ntp++) {
                uint32_t bh[4], bl[4];
                const uint32_t ka = (ntp * 16 + (lane & 7) + ((lane >> 4) << 3)) * 144
                                  + (kf * 16 + ((lane >> 3) & 1) * 8) * 2;
                ldsm_x4(bh, kbh + ka);
                ldsm_x4(bl, kbl + ka);
                mma_f16(c[2*ntp],   qh[kf], &bh[0]);
                mma_f16(c[2*ntp],   qh[kf], &bl[0]);
                mma_f16(c[2*ntp+1], qh[kf], &bh[2]);
                mma_f16(c[2*ntp+1], qh[kf], &bl[2]);
            }

        if (kt >= 2 * qt) {
            const int rg0 = qt * 128 + wid * 16 + (lane >> 2);
            const int cg0 = kt * 64 + (lane & 3) * 2;
            #pragma unroll
            for (int nt = 0; nt < 8; nt++) {
                const int cg = cg0 + nt * 8;
                #pragma unroll
                for (int j = 0; j < 4; j++) {
                    const int r  = rg0 + ((j >> 1) << 3);
                    const int cc = cg + (j & 1);
                    if (cc > r) c[nt][j] = -1e30f;
                }
            }
        }

        float mx0 = -1e30f, mx1 = -1e30f;
        #pragma unroll
        for (int nt = 0; nt < 8; nt++) {
            mx0 = fmaxf(mx0, fmaxf(c[nt][0], c[nt][1]));
            mx1 = fmaxf(mx1, fmaxf(c[nt][2], c[nt][3]));
        }
        mx0 = fmaxf(mx0, __shfl_xor_sync(0xffffffffu, mx0, 1));
        mx0 = fmaxf(mx0, __shfl_xor_sync(0xffffffffu, mx0, 2));
        mx1 = fmaxf(mx1, __shfl_xor_sync(0xffffffffu, mx1, 1));
        mx1 = fmaxf(mx1, __shfl_xor_sync(0xffffffffu, mx1, 2));

        const float nm0 = fmaxf(m0, mx0 * SCALE);
        const float nm1 = fmaxf(m1, mx1 * SCALE);
        const float al0 = fexp2(m0 - nm0);
        const float al1 = fexp2(m1 - nm1);
        m0 = nm0; m1 = nm1;

        float rs0 = 0.f, rs1 = 0.f;
        #pragma unroll
        for (int nt = 0; nt < 8; nt++) {
            float p0 = fexp2(fmaf(c[nt][0], SCALE, -nm0));
            float p1 = fexp2(fmaf(c[nt][1], SCALE, -nm0));
            float p2 = fexp2(fmaf(c[nt][2], SCALE, -nm1));
            float p3 = fexp2(fmaf(c[nt][3], SCALE, -nm1));
            c[nt][0] = p0; c[nt][1] = p1; c[nt][2] = p2; c[nt][3] = p3;
            rs0 += p0 + p1; rs1 += p2 + p3;
        }
        rs0 += __shfl_xor_sync(0xffffffffu, rs0, 1);
        rs0 += __shfl_xor_sync(0xffffffffu, rs0, 2);
        rs1 += __shfl_xor_sync(0xffffffffu, rs1, 1);
        rs1 += __shfl_xor_sync(0xffffffffu, rs1, 2);
        l0 = l0 * al0 + rs0;
        l1 = l1 * al1 + rs1;
        #pragma unroll
        for (int nt = 0; nt < 8; nt++) {
            o[nt][0] *= al0; o[nt][1] *= al0;
            o[nt][2] *= al1; o[nt][3] *= al1;
        }

        #pragma unroll
        for (int kf = 0; kf < 4; kf++) {
            uint32_t ph[4];
            ph[0] = packh2(c[2*kf][0],   c[2*kf][1]);
            ph[1] = packh2(c[2*kf][2],   c[2*kf][3]);
            ph[2] = packh2(c[2*kf+1][0], c[2*kf+1][1]);
            ph[3] = packh2(c[2*kf+1][2], c[2*kf+1][3]);
            #pragma unroll
            for (int ntp = 0; ntp < 4; ntp++) {
                uint32_t vh[4];
                const uint32_t va = (kf * 16 + (lane & 15)) * 144
                                  + (ntp * 16 + ((lane >> 4) << 3)) * 2;
                ldsm_x4t(vh, vbh + va);
                mma_f16(o[2*ntp],   ph, &vh[0]);
                mma_f16(o[2*ntp+1], ph, &vh[2]);
            }
        }
        __syncthreads();
    }

    const float il0 = 1.f / l0, il1 = 1.f / l1;
    const int rg = rowbase + wid * 16 + (lane >> 2);
    #pragma unroll
    for (int nt = 0; nt < 8; nt++) {
        const int col = colC + nt * 8 + (lane & 3) * 2;
        *(uint32_t*)&O[(size_t)rg * CDIM + col] =
            packh2(o[nt][0] * il0, o[nt][1] * il0);
        *(uint32_t*)&O[(size_t)(rg + 8) * CDIM + col] =
            packh2(o[nt][2] * il1, o[nt][3] * il1);
    }
}

// ==================== launch ====================
extern "C" void kernel_launch(void* const* d_in, const int* in_sizes, int n_in,
                              void* d_out, int out_size)
{
    (void)in_sizes; (void)n_in; (void)out_size;
    const float* x    = (const float*)d_in[0];
    const float* Wq   = (const float*)d_in[1];
    const float* Wk   = (const float*)d_in[2];
    const float* Wv   = (const float*)d_in[3];
    const float* Wo   = (const float*)d_in[4];
    const float* bo   = (const float*)d_in[5];
    const float* ln1g = (const float*)d_in[6];
    const float* ln1b = (const float*)d_in[7];
    const float* ln2g = (const float*)d_in[8];
    const float* ln2b = (const float*)d_in[9];
    const float* W1   = (const float*)d_in[10];
    const float* b1   = (const float*)d_in[11];
    const float* W2   = (const float*)d_in[12];
    const float* b2   = (const float*)d_in[13];
    float* out = (float*)d_out;

    __half *h, *qkvhi, *qkvlo, *a, *ff;
    float* x1;
    __half *Wqkvh, *Woh, *W1h, *W2h;
    cudaGetSymbolAddress((void**)&h,     g_h);
    cudaGetSymbolAddress((void**)&qkvhi, g_qkvhi);
    cudaGetSymbolAddress((void**)&qkvlo, g_qkvlo);
    cudaGetSymbolAddress((void**)&a,     g_a);
    cudaGetSymbolAddress((void**)&x1,    g_x1);
    cudaGetSymbolAddress((void**)&ff,    g_ff);
    cudaGetSymbolAddress((void**)&Wqkvh, g_Wqkv);
    cudaGetSymbolAddress((void**)&Woh,   g_Wo);
    cudaGetSymbolAddress((void**)&W1h,   g_W1);
    cudaGetSymbolAddress((void**)&W2h,   g_W2);

    cudaFuncSetAttribute(gemm16<false, false, false, 1>,
                         cudaFuncAttributeMaxDynamicSharedMemorySize, GEMM_SMEM);
    cudaFuncSetAttribute(gemm16<true, false, true, 0>,
                         cudaFuncAttributeMaxDynamicSharedMemorySize, GEMM_SMEM);
    cudaFuncSetAttribute(gemm16<true, true, false, 2>,
                         cudaFuncAttributeMaxDynamicSharedMemorySize, GEMM_SMEM);
    cudaFuncSetAttribute(flash16_kernel,
                         cudaFuncAttributeMaxDynamicSharedMemorySize, FA_SMEM);

    wconv_off_kernel<<<512, 256>>>(Wq, Wqkvh, 0);
    wconv_off_kernel<<<512, 256>>>(Wk, Wqkvh, CDIM);
    wconv_off_kernel<<<512, 256>>>(Wv, Wqkvh, 2 * CDIM);
    wconv_kernel<<<512, 256>>>(Wo, Woh, CDIM * CDIM / 4);
    layernorm_h_kernel<<<MTOT, 256>>>(x, ln1g, ln1b, h);

    // fused QKV GEMM (split hi/lo out for attention)
    gemm16<false, false, false, 1><<<dim3(C3 / 128, MTOT / 128), GT, GEMM_SMEM>>>(
        h, Wqkvh, nullptr, nullptr, nullptr, qkvhi, qkvlo, C3, CDIM);
    // attention (q hi, k hi+lo, v hi)
    flash16_kernel<<<dim3(TSEQ / 128, HEADS, BB), 256, FA_SMEM>>>(
        qkvhi, qkvlo, a);
    // FFN weight converts
    wconv_kernel<<<1024, 256>>>(W1, W1h, CDIM * FDIM / 4);
    wconv_kernel<<<1024, 256>>>(W2, W2h, FDIM * CDIM / 4);
    // x1 = x + attn @ Wo + bo
    gemm16<true, false, true, 0><<<dim3(CDIM / 128, MTOT / 128), GT, GEMM_SMEM>>>(
        a, Woh, bo, x, x1, nullptr, nullptr, CDIM, CDIM);
    // LN2
    layernorm_h_kernel<<<MTOT, 256>>>(x1, ln2g, ln2b, h);
    // ff = relu(h @ W1 + b1)
    gemm16<true, true, false, 2><<<dim3(FDIM / 128, MTOT / 128), GT, GEMM_SMEM>>>(
        h, W1h, b1, nullptr, nullptr, ff, nullptr, FDIM, CDIM);
    // out = x1 + ff @ W2 + b2
    gemm16<true, false, true, 0><<<dim3(CDIM / 128, MTOT / 128), GT, GEMM_SMEM>>>(
        ff, W2h, b2, x1, out, nullptr, nullptr, CDIM, FDIM);
}

// round 9
// speedup vs baseline: 3.1777x; 1.0311x over previous
#include <cuda_runtime.h>
#include <cuda_fp16.h>
#include <cstdint>
#include <math.h>

#define BB    4
#define TSEQ  2048
#define CDIM  1024
#define HEADS 16
#define DHEAD 64
#define MTOT  (BB * TSEQ)
#define FDIM  (4 * CDIM)
#define C3    (3 * CDIM)

// -------- scratch (device globals) --------
__device__ __half g_h    [MTOT * CDIM];
__device__ __half g_qkvhi[MTOT * C3], g_qkvlo[MTOT * C3];
__device__ __half g_a    [MTOT * CDIM];
__device__ float  g_x1   [MTOT * CDIM];
__device__ __half g_ff   [MTOT * FDIM];
__device__ __half g_Wqkv[CDIM * C3];
__device__ __half g_Wo[CDIM * CDIM];
__device__ __half g_W1[CDIM * FDIM], g_W2[FDIM * CDIM];

// -------- PTX helpers (plain sm_80+ only) --------
__device__ __forceinline__ uint32_t smem_u32(const void* p) {
    uint32_t a;
    asm("{ .reg .u64 t; cvta.to.shared.u64 t, %1; cvt.u32.u64 %0, t; }" : "=r"(a) : "l"(p));
    return a;
}
__device__ __forceinline__ void cp16(uint32_t dst, const void* src) {
    asm volatile("cp.async.cg.shared.global [%0], [%1], 16;" :: "r"(dst), "l"(src));
}
__device__ __forceinline__ void cp_commit() { asm volatile("cp.async.commit_group;"); }
template<int N> __device__ __forceinline__ void cp_wait() {
    asm volatile("cp.async.wait_group %0;" :: "n"(N));
}
__device__ __forceinline__ void ldsm_x4(uint32_t* r, uint32_t a) {
    asm volatile("ldmatrix.sync.aligned.m8n8.x4.shared.b16 {%0,%1,%2,%3}, [%4];"
                 : "=r"(r[0]), "=r"(r[1]), "=r"(r[2]), "=r"(r[3]) : "r"(a));
}
__device__ __forceinline__ void ldsm_x4t(uint32_t* r, uint32_t a) {
    asm volatile("ldmatrix.sync.aligned.m8n8.x4.trans.shared.b16 {%0,%1,%2,%3}, [%4];"
                 : "=r"(r[0]), "=r"(r[1]), "=r"(r[2]), "=r"(r[3]) : "r"(a));
}
__device__ __forceinline__ void mma_f16(float* c, const uint32_t* a, const uint32_t* b) {
    asm volatile(
        "mma.sync.aligned.m16n8k16.row.col.f32.f16.f16.f32 "
        "{%0,%1,%2,%3}, {%4,%5,%6,%7}, {%8,%9}, {%0,%1,%2,%3};"
        : "+f"(c[0]), "+f"(c[1]), "+f"(c[2]), "+f"(c[3])
        : "r"(a[0]), "r"(a[1]), "r"(a[2]), "r"(a[3]), "r"(b[0]), "r"(b[1]));
}
__device__ __forceinline__ void splith(float v, __half& h, __half& l) {
    h = __float2half_rn(v);
    l = __float2half_rn(v - __half2float(h));
}
__device__ __forceinline__ uint32_t packh2(float a, float b) {
    __half2 h = __floats2half2_rn(a, b);
    return *(uint32_t*)&h;
}
__device__ __forceinline__ float fexp2(float t) {   // fast 2^t, t<=0
    t = fmaxf(t, -126.0f);
    const float mag = 12582912.0f;
    float r = t + mag;
    uint32_t ui = __float_as_uint(r);
    float f = t - (r - mag);
    float p = 1.3333558146e-3f;
    p = fmaf(p, f, 9.6181291076e-3f);
    p = fmaf(p, f, 5.5504108664e-2f);
    p = fmaf(p, f, 2.4022650696e-1f);
    p = fmaf(p, f, 6.9314718056e-1f);
    p = fmaf(p, f, 1.0f);
    return __uint_as_float(__float_as_uint(p) + (ui << 23));
}

// ==================== fp16 GEMM: 128x256 CTA, 64x64 warp tile =============
// 8 warps (2x4), BK=32, 3-stage cp.async. smem/stage: A 128x80B + B 32x528B.
// OUT: 0 = fp32, 2 = single fp16, 3 = QKV (hi always; lo only K columns).
#define GT       256
#define GA3      10240               // 128 x 80B
#define GB3      16896               // 32 x 528B
#define GSTG     (GA3 + GB3)         // 27136
#define GEMM_SMEM (3 * GSTG)         // 81408

template<bool BIAS, bool RELU, bool RES, int OUT>
__global__ void __launch_bounds__(GT) gemm16(
    const __half* __restrict__ A, const __half* __restrict__ B,
    const float* __restrict__ bias, const float* __restrict__ res,
    float* __restrict__ Cf, __half* __restrict__ Chi, __half* __restrict__ Clo,
    int N, int K)
{
    extern __shared__ char sm[];
    const uint32_t sb = smem_u32(sm);
    const int tid = threadIdx.x, lane = tid & 31, wid = tid >> 5;
    const int wm = (wid >> 2) * 64, wn = (wid & 3) * 64;
    const int m0 = blockIdx.y * 128, n0 = blockIdx.x * 256;

    auto load_stage = [&](int s, int c) {
        const int kc = c << 5;
        const uint32_t st = sb + (uint32_t)s * GSTG;
        // A: 128 rows x 64B = 512 cp16; thread: row=tid/2, segs {2*(tid&1), +1}
        const int row = tid >> 1, sg0 = (tid & 1) << 1;
        const size_t g = (size_t)(m0 + row) * K + kc + sg0 * 8;
        const uint32_t so = st + row * 80 + sg0 * 16;
        cp16(so,      A + g);
        cp16(so + 16, A + g + 8);
        // B: 32 rows x 512B = 1024 cp16; thread: idx = tid + 256i
        #pragma unroll
        for (int i = 0; i < 4; i++) {
            const int idx = tid + (i << 8);
            const int br = idx >> 5, seg = idx & 31;
            const size_t gb = (size_t)(kc + br) * N + n0 + seg * 8;
            cp16(st + GA3 + br * 528 + seg * 16, B + gb);
        }
    };

    float acc[4][8][4];
    #pragma unroll
    for (int a = 0; a < 4; a++)
        #pragma unroll
        for (int b = 0; b < 8; b++)
            #pragma unroll
            for (int d = 0; d < 4; d++) acc[a][b][d] = 0.f;

    const int NC = K >> 5;
    load_stage(0, 0); cp_commit();
    load_stage(1, 1); cp_commit();
    load_stage(2, 2); cp_commit();

    for (int c = 0; c < NC; c++) {
        const int s = c % 3;
        if (c + 2 < NC)      cp_wait<2>();
        else if (c + 1 < NC) cp_wait<1>();
        else                 cp_wait<0>();
        __syncthreads();

        const uint32_t aoff = sb + (uint32_t)s * GSTG;
        const uint32_t boff = aoff + GA3;
        #pragma unroll
        for (int ks = 0; ks < 2; ks++) {
            uint32_t bfr[8][2];
            #pragma unroll
            for (int ntp = 0; ntp < 4; ntp++) {
                uint32_t r[4];
                ldsm_x4t(r, boff + (ks * 16 + (lane & 15)) * 528
                              + (wn + ntp * 16 + ((lane >> 4) << 3)) * 2);
                bfr[2*ntp][0] = r[0]; bfr[2*ntp][1] = r[1];
                bfr[2*ntp+1][0] = r[2]; bfr[2*ntp+1][1] = r[3];
            }
            #pragma unroll
            for (int mt = 0; mt < 4; mt++) {
                uint32_t ah[4];
                ldsm_x4(ah, aoff + (wm + mt * 16 + (lane & 15)) * 80
                              + ks * 32 + ((lane >> 4) << 4));
                #pragma unroll
                for (int nt = 0; nt < 8; nt++)
                    mma_f16(acc[mt][nt], ah, bfr[nt]);
            }
        }
        __syncthreads();
        if (c + 3 < NC) { load_stage(s, c + 3); cp_commit(); }
    }

    #pragma unroll
    for (int mt = 0; mt < 4; mt++)
        #pragma unroll
        for (int nt = 0; nt < 8; nt++)
            #pragma unroll
            for (int hf = 0; hf < 2; hf++) {
                const int row = m0 + wm + mt * 16 + (lane >> 2) + hf * 8;
                const int col = n0 + wn + nt * 8 + (lane & 3) * 2;
                float v0 = acc[mt][nt][hf * 2 + 0];
                float v1 = acc[mt][nt][hf * 2 + 1];
                if (BIAS) { v0 += bias[col]; v1 += bias[col + 1]; }
                if (RELU) { v0 = fmaxf(v0, 0.f); v1 = fmaxf(v1, 0.f); }
                if (RES) {
                    const float2 rr = *(const float2*)&res[(size_t)row * N + col];
                    v0 += rr.x; v1 += rr.y;
                }
                if (OUT == 3) {
                    __half h0, l0, h1, l1;
                    splith(v0, h0, l0); splith(v1, h1, l1);
                    const __half2 hp = __halves2half2(h0, h1);
                    *(uint32_t*)&Chi[(size_t)row * N + col] = *(const uint32_t*)&hp;
                    if (col >= CDIM && col < 2 * CDIM) {   // lo only for K
                        const __half2 lp = __halves2half2(l0, l1);
                        *(uint32_t*)&Clo[(size_t)row * N + col] = *(const uint32_t*)&lp;
                    }
                } else if (OUT == 2) {
                    *(uint32_t*)&Chi[(size_t)row * N + col] = packh2(v0, v1);
                } else {
                    float2 o; o.x = v0; o.y = v1;
                    *(float2*)&Cf[(size_t)row * N + col] = o;
                }
            }
}

// ==================== weight converts ====================
__global__ void __launch_bounds__(256) wconv_kernel(
    const float* __restrict__ w, __half* __restrict__ o, int n4)
{
    for (int i = blockIdx.x * blockDim.x + threadIdx.x; i < n4;
         i += gridDim.x * blockDim.x) {
        const float4 v = ((const float4*)w)[i];
        const __half2 a = __floats2half2_rn(v.x, v.y);
        const __half2 b = __floats2half2_rn(v.z, v.w);
        uint2 u; u.x = *(const uint32_t*)&a; u.y = *(const uint32_t*)&b;
        *(uint2*)&o[(size_t)i * 4] = u;
    }
}
__global__ void __launch_bounds__(256) wconv_off_kernel(
    const float* __restrict__ w, __half* __restrict__ dst, int coff)
{
    const int idx = blockIdx.x * blockDim.x + threadIdx.x;
    const int row = idx >> 7;
    const int g8  = idx & 127;
    const float4 v0 = *(const float4*)&w[(size_t)row * CDIM + g8 * 8];
    const float4 v1 = *(const float4*)&w[(size_t)row * CDIM + g8 * 8 + 4];
    uint4 u;
    u.x = packh2(v0.x, v0.y); u.y = packh2(v0.z, v0.w);
    u.z = packh2(v1.x, v1.y); u.w = packh2(v1.z, v1.w);
    *(uint4*)&dst[(size_t)row * C3 + coff + g8 * 8] = u;
}

// ==================== LayerNorm -> single fp16 ====================
__inline__ __device__ float warp_sum(float v) {
    #pragma unroll
    for (int m = 16; m > 0; m >>= 1) v += __shfl_xor_sync(0xffffffffu, v, m);
    return v;
}
__global__ void __launch_bounds__(256) layernorm_h_kernel(
    const float* __restrict__ x, const float* __restrict__ g,
    const float* __restrict__ bt, __half* __restrict__ y)
{
    const int row = blockIdx.x, tid = threadIdx.x;
    const float4 v = ((const float4*)(x + (size_t)row * CDIM))[tid];
    float s  = v.x + v.y + v.z + v.w;
    float ss = v.x*v.x + v.y*v.y + v.z*v.z + v.w*v.w;
    __shared__ float sh1[8], sh2[8];
    s = warp_sum(s); ss = warp_sum(ss);
    const int w = tid >> 5, l = tid & 31;
    if (l == 0) { sh1[w] = s; sh2[w] = ss; }
    __syncthreads();
    if (w == 0) {
        float a = (l < 8) ? sh1[l] : 0.f;
        float b = (l < 8) ? sh2[l] : 0.f;
        a = warp_sum(a); b = warp_sum(b);
        if (l == 0) { sh1[0] = a; sh2[0] = b; }
    }
    __syncthreads();
    const float mean = sh1[0] * (1.0f / CDIM);
    const float var  = sh2[0] * (1.0f / CDIM) - mean * mean;
    const float inv  = rsqrtf(var + 1e-5f);
    const float4 gv = ((const float4*)g)[tid];
    const float4 bv = ((const float4*)bt)[tid];
    uint2 u;
    u.x = packh2((v.x - mean) * inv * gv.x + bv.x,
                 (v.y - mean) * inv * gv.y + bv.y);
    u.y = packh2((v.z - mean) * inv * gv.z + bv.z,
                 (v.w - mean) * inv * gv.w + bv.w);
    *(uint2*)&y[(size_t)row * CDIM + tid * 4] = u;
}

// ==================== tensor-core flash attention ====================
// qkv fused (stride C3). QK^T: q hi x (k hi + k lo). PV: P x v hi only.
#define FA_QS     18432                 // 128 x 144B
#define FA_KV     9216                  // 64 x 144B
#define FA_STAGE  27648                 // Kh, Kl, Vh
#define FA_SMEM   (FA_QS + 2 * FA_STAGE)   // 73728

__global__ void __launch_bounds__(256, 1) flash16_kernel(
    const __half* __restrict__ QKVhi, const __half* __restrict__ QKVlo,
    __half* __restrict__ O)
{
    extern __shared__ char sm[];
    const uint32_t sb = smem_u32(sm);
    const int tid = threadIdx.x, lane = tid & 31, wid = tid >> 5;
    const int qt = gridDim.x - 1 - blockIdx.x;
    const int hh = blockIdx.y, bb = blockIdx.z;
    const int rowbase = bb * TSEQ + qt * 128;
    const int colC = hh * DHEAD;

    auto loadKV = [&](int s, int kt) {
        #pragma unroll
        for (int i = 0; i < 6; i++) {
            const int c = tid + i * 256;
            const int arr = c / 512;         // 0 Kh, 1 Kl, 2 Vh
            const int r = (c >> 3) & 63;
            const int seg = c & 7;
            const __half* src = ((arr == 1) ? QKVlo : QKVhi)
                + (size_t)(bb * TSEQ + kt * 64 + r) * C3
                + (arr < 2 ? CDIM : 2 * CDIM) + colC + seg * 8;
            cp16(sb + FA_QS + (uint32_t)s * FA_STAGE + arr * FA_KV
                 + r * 144 + seg * 16, src);
        }
    };

    #pragma unroll
    for (int i = 0; i < 2; i++) {
        const int c = tid + i * 256;
        const int r = c >> 2;
        const int seg = c & 3;
        const __half* src = QKVhi + (size_t)(rowbase + r) * C3 + colC + seg * 16;
        cp16(sb + r * 144 + seg * 32, src);
        cp16(sb + r * 144 + seg * 32 + 16, src + 8);
    }
    cp_commit();
    loadKV(0, 0);
    cp_commit();
    cp_wait<0>();
    __syncthreads();

    uint32_t qh[4][4];
    #pragma unroll
    for (int kf = 0; kf < 4; kf++) {
        const uint32_t qa = sb + (wid * 16 + (lane & 15)) * 144
                               + (kf * 16 + ((lane >> 4) << 3)) * 2;
        ldsm_x4(qh[kf], qa);
    }

    float o[8][4];
    #pragma unroll
    for (int i = 0; i < 8; i++)
        #pragma unroll
        for (int j = 0; j < 4; j++) o[i][j] = 0.f;
    float m0 = -1e30f, m1 = -1e30f, l0 = 0.f, l1 = 0.f;

    const int ktlast = 2 * qt + 1;
    const float SCALE = 0.18033688011112042f;   // 0.125 * log2(e)

    for (int kt = 0; kt <= ktlast; kt++) {
        const int s = kt & 1;
        if (kt < ktlast) { loadKV(s ^ 1, kt + 1); cp_commit(); cp_wait<1>(); }
        else             cp_wait<0>();
        __syncthreads();

        const uint32_t kbh = sb + FA_QS + (uint32_t)s * FA_STAGE;
        const uint32_t kbl = kbh + FA_KV;
        const uint32_t vbh = kbh + 2 * FA_KV;

        float c[8][4];
        #pragma unroll
        for (int i = 0; i < 8; i++)
            #pragma unroll
            for (int j = 0; j < 4; j++) c[i][j] = 0.f;

        #pragma unroll
        for (int kf = 0; kf < 4; kf++)
            #pragma unroll
            for (int ntp = 0; ntp < 4; ntp++) {
                uint32_t bh[4], bl[4];
                const uint32_t ka = (ntp * 16 + (lane & 7) + ((lane >> 4) << 3)) * 144
                                  + (kf * 16 + ((lane >> 3) & 1) * 8) * 2;
                ldsm_x4(bh, kbh + ka);
                ldsm_x4(bl, kbl + ka);
                mma_f16(c[2*ntp],   qh[kf], &bh[0]);
                mma_f16(c[2*ntp],   qh[kf], &bl[0]);
                mma_f16(c[2*ntp+1], qh[kf], &bh[2]);
                mma_f16(c[2*ntp+1], qh[kf], &bl[2]);
            }

        if (kt >= 2 * qt) {
            const int rg0 = qt * 128 + wid * 16 + (lane >> 2);
            const int cg0 = kt * 64 + (lane & 3) * 2;
            #pragma unroll
            for (int nt = 0; nt < 8; nt++) {
                const int cg = cg0 + nt * 8;
                #pragma unroll
                for (int j = 0; j < 4; j++) {
                    const int r  = rg0 + ((j >> 1) << 3);
                    const int cc = cg + (j & 1);
                    if (cc > r) c[nt][j] = -1e30f;
                }
            }
        }

        float mx0 = -1e30f, mx1 = -1e30f;
        #pragma unroll
        for (int nt = 0; nt < 8; nt++) {
            mx0 = fmaxf(mx0, fmaxf(c[nt][0], c[nt][1]));
            mx1 = fmaxf(mx1, fmaxf(c[nt][2], c[nt][3]));
        }
        mx0 = fmaxf(mx0, __shfl_xor_sync(0xffffffffu, mx0, 1));
        mx0 = fmaxf(mx0, __shfl_xor_sync(0xffffffffu, mx0, 2));
        mx1 = fmaxf(mx1, __shfl_xor_sync(0xffffffffu, mx1, 1));
        mx1 = fmaxf(mx1, __shfl_xor_sync(0xffffffffu, mx1, 2));

        const float nm0 = fmaxf(m0, mx0 * SCALE);
        const float nm1 = fmaxf(m1, mx1 * SCALE);
        const float al0 = fexp2(m0 - nm0);
        const float al1 = fexp2(m1 - nm1);
        m0 = nm0; m1 = nm1;

        float rs0 = 0.f, rs1 = 0.f;
        #pragma unroll
        for (int nt = 0; nt < 8; nt++) {
            float p0 = fexp2(fmaf(c[nt][0], SCALE, -nm0));
            float p1 = fexp2(fmaf(c[nt][1], SCALE, -nm0));
            float p2 = fexp2(fmaf(c[nt][2], SCALE, -nm1));
            float p3 = fexp2(fmaf(c[nt][3], SCALE, -nm1));
            c[nt][0] = p0; c[nt][1] = p1; c[nt][2] = p2; c[nt][3] = p3;
            rs0 += p0 + p1; rs1 += p2 + p3;
        }
        rs0 += __shfl_xor_sync(0xffffffffu, rs0, 1);
        rs0 += __shfl_xor_sync(0xffffffffu, rs0, 2);
        rs1 += __shfl_xor_sync(0xffffffffu, rs1, 1);
        rs1 += __shfl_xor_sync(0xffffffffu, rs1, 2);
        l0 = l0 * al0 + rs0;
        l1 = l1 * al1 + rs1;
        #pragma unroll
        for (int nt = 0; nt < 8; nt++) {
            o[nt][0] *= al0; o[nt][1] *= al0;
            o[nt][2] *= al1; o[nt][3] *= al1;
        }

        #pragma unroll
        for (int kf = 0; kf < 4; kf++) {
            uint32_t ph[4];
            ph[0] = packh2(c[2*kf][0],   c[2*kf][1]);
            ph[1] = packh2(c[2*kf][2],   c[2*kf][3]);
            ph[2] = packh2(c[2*kf+1][0], c[2*kf+1][1]);
            ph[3] = packh2(c[2*kf+1][2], c[2*kf+1][3]);
            #pragma unroll
            for (int ntp = 0; ntp < 4; ntp++) {
                uint32_t vh[4];
                const uint32_t va = (kf * 16 + (lane & 15)) * 144
                                  + (ntp * 16 + ((lane >> 4) << 3)) * 2;
                ldsm_x4t(vh, vbh + va);
                mma_f16(o[2*ntp],   ph, &vh[0]);
                mma_f16(o[2*ntp+1], ph, &vh[2]);
            }
        }
        __syncthreads();
    }

    const float il0 = 1.f / l0, il1 = 1.f / l1;
    const int rg = rowbase + wid * 16 + (lane >> 2);
    #pragma unroll
    for (int nt = 0; nt < 8; nt++) {
        const int col = colC + nt * 8 + (lane & 3) * 2;
        *(uint32_t*)&O[(size_t)rg * CDIM + col] =
            packh2(o[nt][0] * il0, o[nt][1] * il0);
        *(uint32_t*)&O[(size_t)(rg + 8) * CDIM + col] =
            packh2(o[nt][2] * il1, o[nt][3] * il1);
    }
}

// ==================== launch ====================
extern "C" void kernel_launch(void* const* d_in, const int* in_sizes, int n_in,
                              void* d_out, int out_size)
{
    (void)in_sizes; (void)n_in; (void)out_size;
    const float* x    = (const float*)d_in[0];
    const float* Wq   = (const float*)d_in[1];
    const float* Wk   = (const float*)d_in[2];
    const float* Wv   = (const float*)d_in[3];
    const float* Wo   = (const float*)d_in[4];
    const float* bo   = (const float*)d_in[5];
    const float* ln1g = (const float*)d_in[6];
    const float* ln1b = (const float*)d_in[7];
    const float* ln2g = (const float*)d_in[8];
    const float* ln2b = (const float*)d_in[9];
    const float* W1   = (const float*)d_in[10];
    const float* b1   = (const float*)d_in[11];
    const float* W2   = (const float*)d_in[12];
    const float* b2   = (const float*)d_in[13];
    float* out = (float*)d_out;

    __half *h, *qkvhi, *qkvlo, *a, *ff;
    float* x1;
    __half *Wqkvh, *Woh, *W1h, *W2h;
    cudaGetSymbolAddress((void**)&h,     g_h);
    cudaGetSymbolAddress((void**)&qkvhi, g_qkvhi);
    cudaGetSymbolAddress((void**)&qkvlo, g_qkvlo);
    cudaGetSymbolAddress((void**)&a,     g_a);
    cudaGetSymbolAddress((void**)&x1,    g_x1);
    cudaGetSymbolAddress((void**)&ff,    g_ff);
    cudaGetSymbolAddress((void**)&Wqkvh, g_Wqkv);
    cudaGetSymbolAddress((void**)&Woh,   g_Wo);
    cudaGetSymbolAddress((void**)&W1h,   g_W1);
    cudaGetSymbolAddress((void**)&W2h,   g_W2);

    cudaFuncSetAttribute(gemm16<false, false, false, 3>,
                         cudaFuncAttributeMaxDynamicSharedMemorySize, GEMM_SMEM);
    cudaFuncSetAttribute(gemm16<true, false, true, 0>,
                         cudaFuncAttributeMaxDynamicSharedMemorySize, GEMM_SMEM);
    cudaFuncSetAttribute(gemm16<true, true, false, 2>,
                         cudaFuncAttributeMaxDynamicSharedMemorySize, GEMM_SMEM);
    cudaFuncSetAttribute(flash16_kernel,
                         cudaFuncAttributeMaxDynamicSharedMemorySize, FA_SMEM);

    wconv_off_kernel<<<512, 256>>>(Wq, Wqkvh, 0);
    wconv_off_kernel<<<512, 256>>>(Wk, Wqkvh, CDIM);
    wconv_off_kernel<<<512, 256>>>(Wv, Wqkvh, 2 * CDIM);
    wconv_kernel<<<512, 256>>>(Wo, Woh, CDIM * CDIM / 4);
    layernorm_h_kernel<<<MTOT, 256>>>(x, ln1g, ln1b, h);

    // fused QKV GEMM (hi out everywhere; lo out only for K columns)
    gemm16<false, false, false, 3><<<dim3(C3 / 256, MTOT / 128), GT, GEMM_SMEM>>>(
        h, Wqkvh, nullptr, nullptr, nullptr, qkvhi, qkvlo, C3, CDIM);
    // attention (q hi, k hi+lo, v hi)
    flash16_kernel<<<dim3(TSEQ / 128, HEADS, BB), 256, FA_SMEM>>>(
        qkvhi, qkvlo, a);
    // FFN weight converts
    wconv_kernel<<<1024, 256>>>(W1, W1h, CDIM * FDIM / 4);
    wconv_kernel<<<1024, 256>>>(W2, W2h, FDIM * CDIM / 4);
    // x1 = x + attn @ Wo + bo
    gemm16<true, false, true, 0><<<dim3(CDIM / 256, MTOT / 128), GT, GEMM_SMEM>>>(
        a, Woh, bo, x, x1, nullptr, nullptr, CDIM, CDIM);
    // LN2
    layernorm_h_kernel<<<MTOT, 256>>>(x1, ln2g, ln2b, h);
    // ff = relu(h @ W1 + b1)
    gemm16<true, true, false, 2><<<dim3(FDIM / 256, MTOT / 128), GT, GEMM_SMEM>>>(
        h, W1h, b1, nullptr, nullptr, ff, nullptr, FDIM, CDIM);
    // out = x1 + ff @ W2 + b2
    gemm16<true, false, true, 0><<<dim3(CDIM / 256, MTOT / 128), GT, GEMM_SMEM>>>(
        ff, W2h, b2, x1, out, nullptr, nullptr, CDIM, FDIM);
}

// round 10
// speedup vs baseline: 3.3474x; 1.0534x over previous
#include <cuda_runtime.h>
#include <cuda_fp16.h>
#include <cstdint>
#include <math.h>

#define BB    4
#define TSEQ  2048
#define CDIM  1024
#define HEADS 16
#define DHEAD 64
#define MTOT  (BB * TSEQ)
#define FDIM  (4 * CDIM)
#define C3    (3 * CDIM)

// -------- scratch (device globals) --------
__device__ __half g_h   [MTOT * CDIM];
__device__ __half g_qkv [MTOT * C3];
__device__ __half g_a   [MTOT * CDIM];
__device__ float  g_x1  [MTOT * CDIM];
__device__ __half g_ff  [MTOT * FDIM];
__device__ __half g_Wqkv[CDIM * C3];
__device__ __half g_Wo[CDIM * CDIM];
__device__ __half g_W1[CDIM * FDIM], g_W2[FDIM * CDIM];

// -------- PTX helpers (plain sm_80+ only) --------
__device__ __forceinline__ uint32_t smem_u32(const void* p) {
    uint32_t a;
    asm("{ .reg .u64 t; cvta.to.shared.u64 t, %1; cvt.u32.u64 %0, t; }" : "=r"(a) : "l"(p));
    return a;
}
__device__ __forceinline__ void cp16(uint32_t dst, const void* src) {
    asm volatile("cp.async.cg.shared.global [%0], [%1], 16;" :: "r"(dst), "l"(src));
}
__device__ __forceinline__ void cp_commit() { asm volatile("cp.async.commit_group;"); }
template<int N> __device__ __forceinline__ void cp_wait() {
    asm volatile("cp.async.wait_group %0;" :: "n"(N));
}
__device__ __forceinline__ void ldsm_x4(uint32_t* r, uint32_t a) {
    asm volatile("ldmatrix.sync.aligned.m8n8.x4.shared.b16 {%0,%1,%2,%3}, [%4];"
                 : "=r"(r[0]), "=r"(r[1]), "=r"(r[2]), "=r"(r[3]) : "r"(a));
}
__device__ __forceinline__ void ldsm_x4t(uint32_t* r, uint32_t a) {
    asm volatile("ldmatrix.sync.aligned.m8n8.x4.trans.shared.b16 {%0,%1,%2,%3}, [%4];"
                 : "=r"(r[0]), "=r"(r[1]), "=r"(r[2]), "=r"(r[3]) : "r"(a));
}
__device__ __forceinline__ void mma_f16(float* c, const uint32_t* a, const uint32_t* b) {
    asm volatile(
        "mma.sync.aligned.m16n8k16.row.col.f32.f16.f16.f32 "
        "{%0,%1,%2,%3}, {%4,%5,%6,%7}, {%8,%9}, {%0,%1,%2,%3};"
        : "+f"(c[0]), "+f"(c[1]), "+f"(c[2]), "+f"(c[3])
        : "r"(a[0]), "r"(a[1]), "r"(a[2]), "r"(a[3]), "r"(b[0]), "r"(b[1]));
}
__device__ __forceinline__ uint32_t packh2(float a, float b) {
    __half2 h = __floats2half2_rn(a, b);
    return *(uint32_t*)&h;
}
__device__ __forceinline__ float fexp2(float t) {   // fast 2^t, t<=0
    t = fmaxf(t, -126.0f);
    const float mag = 12582912.0f;
    float r = t + mag;
    uint32_t ui = __float_as_uint(r);
    float f = t - (r - mag);
    float p = 1.3333558146e-3f;
    p = fmaf(p, f, 9.6181291076e-3f);
    p = fmaf(p, f, 5.5504108664e-2f);
    p = fmaf(p, f, 2.4022650696e-1f);
    p = fmaf(p, f, 6.9314718056e-1f);
    p = fmaf(p, f, 1.0f);
    return __uint_as_float(__float_as_uint(p) + (ui << 23));
}

// ==================== fp16 GEMM: 128x256 CTA, 64x64 warp tile =============
// 8 warps (2x4), BK=32, 3-stage cp.async.
// OUT: 0 = fp32 (+res), 2 = single fp16.
#define GT       256
#define GA3      10240               // 128 x 80B
#define GB3      16896               // 32 x 528B
#define GSTG     (GA3 + GB3)         // 27136
#define GEMM_SMEM (3 * GSTG)         // 81408

template<bool BIAS, bool RELU, bool RES, int OUT>
__global__ void __launch_bounds__(GT) gemm16(
    const __half* __restrict__ A, const __half* __restrict__ B,
    const float* __restrict__ bias, const float* __restrict__ res,
    float* __restrict__ Cf, __half* __restrict__ Ch,
    int N, int K)
{
    extern __shared__ char sm[];
    const uint32_t sb = smem_u32(sm);
    const int tid = threadIdx.x, lane = tid & 31, wid = tid >> 5;
    const int wm = (wid >> 2) * 64, wn = (wid & 3) * 64;
    const int m0 = blockIdx.y * 128, n0 = blockIdx.x * 256;

    auto load_stage = [&](int s, int c) {
        const int kc = c << 5;
        const uint32_t st = sb + (uint32_t)s * GSTG;
        const int row = tid >> 1, sg0 = (tid & 1) << 1;
        const size_t g = (size_t)(m0 + row) * K + kc + sg0 * 8;
        const uint32_t so = st + row * 80 + sg0 * 16;
        cp16(so,      A + g);
        cp16(so + 16, A + g + 8);
        #pragma unroll
        for (int i = 0; i < 4; i++) {
            const int idx = tid + (i << 8);
            const int br = idx >> 5, seg = idx & 31;
            const size_t gb = (size_t)(kc + br) * N + n0 + seg * 8;
            cp16(st + GA3 + br * 528 + seg * 16, B + gb);
        }
    };

    float acc[4][8][4];
    #pragma unroll
    for (int a = 0; a < 4; a++)
        #pragma unroll
        for (int b = 0; b < 8; b++)
            #pragma unroll
            for (int d = 0; d < 4; d++) acc[a][b][d] = 0.f;

    const int NC = K >> 5;
    load_stage(0, 0); cp_commit();
    load_stage(1, 1); cp_commit();
    load_stage(2, 2); cp_commit();

    for (int c = 0; c < NC; c++) {
        const int s = c % 3;
        if (c + 2 < NC)      cp_wait<2>();
        else if (c + 1 < NC) cp_wait<1>();
        else                 cp_wait<0>();
        __syncthreads();

        const uint32_t aoff = sb + (uint32_t)s * GSTG;
        const uint32_t boff = aoff + GA3;
        #pragma unroll
        for (int ks = 0; ks < 2; ks++) {
            uint32_t bfr[8][2];
            #pragma unroll
            for (int ntp = 0; ntp < 4; ntp++) {
                uint32_t r[4];
                ldsm_x4t(r, boff + (ks * 16 + (lane & 15)) * 528
                              + (wn + ntp * 16 + ((lane >> 4) << 3)) * 2);
                bfr[2*ntp][0] = r[0]; bfr[2*ntp][1] = r[1];
                bfr[2*ntp+1][0] = r[2]; bfr[2*ntp+1][1] = r[3];
            }
            #pragma unroll
            for (int mt = 0; mt < 4; mt++) {
                uint32_t ah[4];
                ldsm_x4(ah, aoff + (wm + mt * 16 + (lane & 15)) * 80
                              + ks * 32 + ((lane >> 4) << 4));
                #pragma unroll
                for (int nt = 0; nt < 8; nt++)
                    mma_f16(acc[mt][nt], ah, bfr[nt]);
            }
        }
        __syncthreads();
        if (c + 3 < NC) { load_stage(s, c + 3); cp_commit(); }
    }

    #pragma unroll
    for (int mt = 0; mt < 4; mt++)
        #pragma unroll
        for (int nt = 0; nt < 8; nt++)
            #pragma unroll
            for (int hf = 0; hf < 2; hf++) {
                const int row = m0 + wm + mt * 16 + (lane >> 2) + hf * 8;
                const int col = n0 + wn + nt * 8 + (lane & 3) * 2;
                float v0 = acc[mt][nt][hf * 2 + 0];
                float v1 = acc[mt][nt][hf * 2 + 1];
                if (BIAS) { v0 += bias[col]; v1 += bias[col + 1]; }
                if (RELU) { v0 = fmaxf(v0, 0.f); v1 = fmaxf(v1, 0.f); }
                if (RES) {
                    const float2 rr = *(const float2*)&res[(size_t)row * N + col];
                    v0 += rr.x; v1 += rr.y;
                }
                if (OUT == 2) {
                    *(uint32_t*)&Ch[(size_t)row * N + col] = packh2(v0, v1);
                } else {
                    float2 o; o.x = v0; o.y = v1;
                    *(float2*)&Cf[(size_t)row * N + col] = o;
                }
            }
}

// ==================== weight converts ====================
__global__ void __launch_bounds__(256) wconv_kernel(
    const float* __restrict__ w, __half* __restrict__ o, int n4)
{
    for (int i = blockIdx.x * blockDim.x + threadIdx.x; i < n4;
         i += gridDim.x * blockDim.x) {
        const float4 v = ((const float4*)w)[i];
        const __half2 a = __floats2half2_rn(v.x, v.y);
        const __half2 b = __floats2half2_rn(v.z, v.w);
        uint2 u; u.x = *(const uint32_t*)&a; u.y = *(const uint32_t*)&b;
        *(uint2*)&o[(size_t)i * 4] = u;
    }
}
// fused QKV weight convert: z = 0/1/2 selects Wq/Wk/Wv -> columns of Wqkv
__global__ void __launch_bounds__(256) wconv_qkv_kernel(
    const float* __restrict__ Wq, const float* __restrict__ Wk,
    const float* __restrict__ Wv, __half* __restrict__ dst)
{
    const int z = blockIdx.z;
    const float* w = (z == 0) ? Wq : (z == 1) ? Wk : Wv;
    const int coff = z * CDIM;
    const int idx = blockIdx.x * blockDim.x + threadIdx.x;
    const int row = idx >> 7;
    const int g8  = idx & 127;
    const float4 v0 = *(const float4*)&w[(size_t)row * CDIM + g8 * 8];
    const float4 v1 = *(const float4*)&w[(size_t)row * CDIM + g8 * 8 + 4];
    uint4 u;
    u.x = packh2(v0.x, v0.y); u.y = packh2(v0.z, v0.w);
    u.z = packh2(v1.x, v1.y); u.w = packh2(v1.z, v1.w);
    *(uint4*)&dst[(size_t)row * C3 + coff + g8 * 8] = u;
}

// ==================== LayerNorm -> single fp16 ====================
__inline__ __device__ float warp_sum(float v) {
    #pragma unroll
    for (int m = 16; m > 0; m >>= 1) v += __shfl_xor_sync(0xffffffffu, v, m);
    return v;
}
__global__ void __launch_bounds__(256) layernorm_h_kernel(
    const float* __restrict__ x, const float* __restrict__ g,
    const float* __restrict__ bt, __half* __restrict__ y)
{
    const int row = blockIdx.x, tid = threadIdx.x;
    const float4 v = ((const float4*)(x + (size_t)row * CDIM))[tid];
    float s  = v.x + v.y + v.z + v.w;
    float ss = v.x*v.x + v.y*v.y + v.z*v.z + v.w*v.w;
    __shared__ float sh1[8], sh2[8];
    s = warp_sum(s); ss = warp_sum(ss);
    const int w = tid >> 5, l = tid & 31;
    if (l == 0) { sh1[w] = s; sh2[w] = ss; }
    __syncthreads();
    if (w == 0) {
        float a = (l < 8) ? sh1[l] : 0.f;
        float b = (l < 8) ? sh2[l] : 0.f;
        a = warp_sum(a); b = warp_sum(b);
        if (l == 0) { sh1[0] = a; sh2[0] = b; }
    }
    __syncthreads();
    const float mean = sh1[0] * (1.0f / CDIM);
    const float var  = sh2[0] * (1.0f / CDIM) - mean * mean;
    const float inv  = rsqrtf(var + 1e-5f);
    const float4 gv = ((const float4*)g)[tid];
    const float4 bv = ((const float4*)bt)[tid];
    uint2 u;
    u.x = packh2((v.x - mean) * inv * gv.x + bv.x,
                 (v.y - mean) * inv * gv.y + bv.y);
    u.y = packh2((v.z - mean) * inv * gv.z + bv.z,
                 (v.w - mean) * inv * gv.w + bv.w);
    *(uint2*)&y[(size_t)row * CDIM + tid * 4] = u;
}

// ==================== tensor-core flash attention (pure fp16) ============
// qkv fused (stride C3). QK^T: q x k (1 mma). PV: P x v (1 mma).
#define FA_QS     18432                 // 128 x 144B
#define FA_KV     9216                  // 64 x 144B
#define FA_STAGE  18432                 // K, V
#define FA_SMEM   (FA_QS + 2 * FA_STAGE)   // 55296

__global__ void __launch_bounds__(256, 1) flash16_kernel(
    const __half* __restrict__ QKV, __half* __restrict__ O)
{
    extern __shared__ char sm[];
    const uint32_t sb = smem_u32(sm);
    const int tid = threadIdx.x, lane = tid & 31, wid = tid >> 5;
    const int qt = gridDim.x - 1 - blockIdx.x;
    const int hh = blockIdx.y, bb = blockIdx.z;
    const int rowbase = bb * TSEQ + qt * 128;
    const int colC = hh * DHEAD;

    auto loadKV = [&](int s, int kt) {
        #pragma unroll
        for (int i = 0; i < 4; i++) {
            const int c = tid + i * 256;
            const int arr = c >> 9;          // 0 K, 1 V
            const int r = (c >> 3) & 63;
            const int seg = c & 7;
            const __half* src = QKV
                + (size_t)(bb * TSEQ + kt * 64 + r) * C3
                + (arr == 0 ? CDIM : 2 * CDIM) + colC + seg * 8;
            cp16(sb + FA_QS + (uint32_t)s * FA_STAGE + arr * FA_KV
                 + r * 144 + seg * 16, src);
        }
    };

    #pragma unroll
    for (int i = 0; i < 2; i++) {
        const int c = tid + i * 256;
        const int r = c >> 2;
        const int seg = c & 3;
        const __half* src = QKV + (size_t)(rowbase + r) * C3 + colC + seg * 16;
        cp16(sb + r * 144 + seg * 32, src);
        cp16(sb + r * 144 + seg * 32 + 16, src + 8);
    }
    cp_commit();
    loadKV(0, 0);
    cp_commit();
    cp_wait<0>();
    __syncthreads();

    uint32_t qh[4][4];
    #pragma unroll
    for (int kf = 0; kf < 4; kf++) {
        const uint32_t qa = sb + (wid * 16 + (lane & 15)) * 144
                               + (kf * 16 + ((lane >> 4) << 3)) * 2;
        ldsm_x4(qh[kf], qa);
    }

    float o[8][4];
    #pragma unroll
    for (int i = 0; i < 8; i++)
        #pragma unroll
        for (int j = 0; j < 4; j++) o[i][j] = 0.f;
    float m0 = -1e30f, m1 = -1e30f, l0 = 0.f, l1 = 0.f;

    const int ktlast = 2 * qt + 1;
    const float SCALE = 0.18033688011112042f;   // 0.125 * log2(e)

    for (int kt = 0; kt <= ktlast; kt++) {
        const int s = kt & 1;
        if (kt < ktlast) { loadKV(s ^ 1, kt + 1); cp_commit(); cp_wait<1>(); }
        else             cp_wait<0>();
        __syncthreads();

        const uint32_t kb = sb + FA_QS + (uint32_t)s * FA_STAGE;
        const uint32_t vb = kb + FA_KV;

        float c[8][4];
        #pragma unroll
        for (int i = 0; i < 8; i++)
            #pragma unroll
            for (int j = 0; j < 4; j++) c[i][j] = 0.f;

        #pragma unroll
        for (int kf = 0; kf < 4; kf++)
            #pragma unroll
            for (int ntp = 0; ntp < 4; ntp++) {
                uint32_t bh[4];
                const uint32_t ka = (ntp * 16 + (lane & 7) + ((lane >> 4) << 3)) * 144
                                  + (kf * 16 + ((lane >> 3) & 1) * 8) * 2;
                ldsm_x4(bh, kb + ka);
                mma_f16(c[2*ntp],   qh[kf], &bh[0]);
                mma_f16(c[2*ntp+1], qh[kf], &bh[2]);
            }

        if (kt >= 2 * qt) {
            const int rg0 = qt * 128 + wid * 16 + (lane >> 2);
            const int cg0 = kt * 64 + (lane & 3) * 2;
            #pragma unroll
            for (int nt = 0; nt < 8; nt++) {
                const int cg = cg0 + nt * 8;
                #pragma unroll
                for (int j = 0; j < 4; j++) {
                    const int r  = rg0 + ((j >> 1) << 3);
                    const int cc = cg + (j & 1);
                    if (cc > r) c[nt][j] = -1e30f;
                }
            }
        }

        float mx0 = -1e30f, mx1 = -1e30f;
        #pragma unroll
        for (int nt = 0; nt < 8; nt++) {
            mx0 = fmaxf(mx0, fmaxf(c[nt][0], c[nt][1]));
            mx1 = fmaxf(mx1, fmaxf(c[nt][2], c[nt][3]));
        }
        mx0 = fmaxf(mx0, __shfl_xor_sync(0xffffffffu, mx0, 1));
        mx0 = fmaxf(mx0, __shfl_xor_sync(0xffffffffu, mx0, 2));
        mx1 = fmaxf(mx1, __shfl_xor_sync(0xffffffffu, mx1, 1));
        mx1 = fmaxf(mx1, __shfl_xor_sync(0xffffffffu, mx1, 2));

        const float nm0 = fmaxf(m0, mx0 * SCALE);
        const float nm1 = fmaxf(m1, mx1 * SCALE);
        const float al0 = fexp2(m0 - nm0);
        const float al1 = fexp2(m1 - nm1);
        m0 = nm0; m1 = nm1;

        float rs0 = 0.f, rs1 = 0.f;
        #pragma unroll
        for (int nt = 0; nt < 8; nt++) {
            float p0 = fexp2(fmaf(c[nt][0], SCALE, -nm0));
            float p1 = fexp2(fmaf(c[nt][1], SCALE, -nm0));
            float p2 = fexp2(fmaf(c[nt][2], SCALE, -nm1));
            float p3 = fexp2(fmaf(c[nt][3], SCALE, -nm1));
            c[nt][0] = p0; c[nt][1] = p1; c[nt][2] = p2; c[nt][3] = p3;
            rs0 += p0 + p1; rs1 += p2 + p3;
        }
        rs0 += __shfl_xor_sync(0xffffffffu, rs0, 1);
        rs0 += __shfl_xor_sync(0xffffffffu, rs0, 2);
        rs1 += __shfl_xor_sync(0xffffffffu, rs1, 1);
        rs1 += __shfl_xor_sync(0xffffffffu, rs1, 2);
        l0 = l0 * al0 + rs0;
        l1 = l1 * al1 + rs1;
        #pragma unroll
        for (int nt = 0; nt < 8; nt++) {
            o[nt][0] *= al0; o[nt][1] *= al0;
            o[nt][2] *= al1; o[nt][3] *= al1;
        }

        #pragma unroll
        for (int kf = 0; kf < 4; kf++) {
            uint32_t ph[4];
            ph[0] = packh2(c[2*kf][0],   c[2*kf][1]);
            ph[1] = packh2(c[2*kf][2],   c[2*kf][3]);
            ph[2] = packh2(c[2*kf+1][0], c[2*kf+1][1]);
            ph[3] = packh2(c[2*kf+1][2], c[2*kf+1][3]);
            #pragma unroll
            for (int ntp = 0; ntp < 4; ntp++) {
                uint32_t vh[4];
                const uint32_t va = (kf * 16 + (lane & 15)) * 144
                                  + (ntp * 16 + ((lane >> 4) << 3)) * 2;
                ldsm_x4t(vh, vb + va);
                mma_f16(o[2*ntp],   ph, &vh[0]);
                mma_f16(o[2*ntp+1], ph, &vh[2]);
            }
        }
        __syncthreads();
    }

    const float il0 = 1.f / l0, il1 = 1.f / l1;
    const int rg = rowbase + wid * 16 + (lane >> 2);
    #pragma unroll
    for (int nt = 0; nt < 8; nt++) {
        const int col = colC + nt * 8 + (lane & 3) * 2;
        *(uint32_t*)&O[(size_t)rg * CDIM + col] =
            packh2(o[nt][0] * il0, o[nt][1] * il0);
        *(uint32_t*)&O[(size_t)(rg + 8) * CDIM + col] =
            packh2(o[nt][2] * il1, o[nt][3] * il1);
    }
}

// ==================== launch ====================
extern "C" void kernel_launch(void* const* d_in, const int* in_sizes, int n_in,
                              void* d_out, int out_size)
{
    (void)in_sizes; (void)n_in; (void)out_size;
    const float* x    = (const float*)d_in[0];
    const float* Wq   = (const float*)d_in[1];
    const float* Wk   = (const float*)d_in[2];
    const float* Wv   = (const float*)d_in[3];
    const float* Wo   = (const float*)d_in[4];
    const float* bo   = (const float*)d_in[5];
    const float* ln1g = (const float*)d_in[6];
    const float* ln1b = (const float*)d_in[7];
    const float* ln2g = (const float*)d_in[8];
    const float* ln2b = (const float*)d_in[9];
    const float* W1   = (const float*)d_in[10];
    const float* b1   = (const float*)d_in[11];
    const float* W2   = (const float*)d_in[12];
    const float* b2   = (const float*)d_in[13];
    float* out = (float*)d_out;

    __half *h, *qkv, *a, *ff;
    float* x1;
    __half *Wqkvh, *Woh, *W1h, *W2h;
    cudaGetSymbolAddress((void**)&h,     g_h);
    cudaGetSymbolAddress((void**)&qkv,   g_qkv);
    cudaGetSymbolAddress((void**)&a,     g_a);
    cudaGetSymbolAddress((void**)&x1,    g_x1);
    cudaGetSymbolAddress((void**)&ff,    g_ff);
    cudaGetSymbolAddress((void**)&Wqkvh, g_Wqkv);
    cudaGetSymbolAddress((void**)&Woh,   g_Wo);
    cudaGetSymbolAddress((void**)&W1h,   g_W1);
    cudaGetSymbolAddress((void**)&W2h,   g_W2);

    cudaFuncSetAttribute(gemm16<false, false, false, 2>,
                         cudaFuncAttributeMaxDynamicSharedMemorySize, GEMM_SMEM);
    cudaFuncSetAttribute(gemm16<true, false, true, 0>,
                         cudaFuncAttributeMaxDynamicSharedMemorySize, GEMM_SMEM);
    cudaFuncSetAttribute(gemm16<true, true, false, 2>,
                         cudaFuncAttributeMaxDynamicSharedMemorySize, GEMM_SMEM);
    cudaFuncSetAttribute(flash16_kernel,
                         cudaFuncAttributeMaxDynamicSharedMemorySize, FA_SMEM);

    wconv_qkv_kernel<<<dim3(512, 1, 3), 256>>>(Wq, Wk, Wv, Wqkvh);
    wconv_kernel<<<512, 256>>>(Wo, Woh, CDIM * CDIM / 4);
    layernorm_h_kernel<<<MTOT, 256>>>(x, ln1g, ln1b, h);

    // fused QKV GEMM (single fp16 out)
    gemm16<false, false, false, 2><<<dim3(C3 / 256, MTOT / 128), GT, GEMM_SMEM>>>(
        h, Wqkvh, nullptr, nullptr, nullptr, qkv, C3, CDIM);
    // attention (pure fp16 q/k/v)
    flash16_kernel<<<dim3(TSEQ / 128, HEADS, BB), 256, FA_SMEM>>>(qkv, a);
    // FFN weight converts
    wconv_kernel<<<1024, 256>>>(W1, W1h, CDIM * FDIM / 4);
    wconv_kernel<<<1024, 256>>>(W2, W2h, FDIM * CDIM / 4);
    // x1 = x + attn @ Wo + bo
    gemm16<true, false, true, 0><<<dim3(CDIM / 256, MTOT / 128), GT, GEMM_SMEM>>>(
        a, Woh, bo, x, x1, nullptr, CDIM, CDIM);
    // LN2
    layernorm_h_kernel<<<MTOT, 256>>>(x1, ln2g, ln2b, h);
    // ff = relu(h @ W1 + b1)
    gemm16<true, true, false, 2><<<dim3(FDIM / 256, MTOT / 128), GT, GEMM_SMEM>>>(
        h, W1h, b1, nullptr, nullptr, ff, FDIM, CDIM);
    // out = x1 + ff @ W2 + b2
    gemm16<true, false, true, 0><<<dim3(CDIM / 256, MTOT / 128), GT, GEMM_SMEM>>>(
        ff, W2h, b2, x1, out, nullptr, CDIM, FDIM);
}

// round 11
// speedup vs baseline: 3.6090x; 1.0781x over previous
#include <cuda_runtime.h>
#include <cuda_fp16.h>
#include <cstdint>
#include <math.h>

#define BB    4
#define TSEQ  2048
#define CDIM  1024
#define HEADS 16
#define DHEAD 64
#define MTOT  (BB * TSEQ)
#define FDIM  (4 * CDIM)
#define C3    (3 * CDIM)

// -------- scratch (device globals) --------
__device__ __half g_h   [MTOT * CDIM];
__device__ __half g_qkv [MTOT * C3];
__device__ __half g_a   [MTOT * CDIM];
__device__ float  g_x1  [MTOT * CDIM];
__device__ __half g_ff  [MTOT * FDIM];
__device__ __half g_Wqkv[CDIM * C3];
__device__ __half g_Wo[CDIM * CDIM];
__device__ __half g_W1[CDIM * FDIM], g_W2[FDIM * CDIM];

// -------- PTX helpers (plain sm_80+ only) --------
__device__ __forceinline__ uint32_t smem_u32(const void* p) {
    uint32_t a;
    asm("{ .reg .u64 t; cvta.to.shared.u64 t, %1; cvt.u32.u64 %0, t; }" : "=r"(a) : "l"(p));
    return a;
}
__device__ __forceinline__ void cp16(uint32_t dst, const void* src) {
    asm volatile("cp.async.cg.shared.global [%0], [%1], 16;" :: "r"(dst), "l"(src));
}
__device__ __forceinline__ void cp_commit() { asm volatile("cp.async.commit_group;"); }
template<int N> __device__ __forceinline__ void cp_wait() {
    asm volatile("cp.async.wait_group %0;" :: "n"(N));
}
__device__ __forceinline__ void ldsm_x4(uint32_t* r, uint32_t a) {
    asm volatile("ldmatrix.sync.aligned.m8n8.x4.shared.b16 {%0,%1,%2,%3}, [%4];"
                 : "=r"(r[0]), "=r"(r[1]), "=r"(r[2]), "=r"(r[3]) : "r"(a));
}
__device__ __forceinline__ void ldsm_x4t(uint32_t* r, uint32_t a) {
    asm volatile("ldmatrix.sync.aligned.m8n8.x4.trans.shared.b16 {%0,%1,%2,%3}, [%4];"
                 : "=r"(r[0]), "=r"(r[1]), "=r"(r[2]), "=r"(r[3]) : "r"(a));
}
__device__ __forceinline__ void mma_f16(float* c, const uint32_t* a, const uint32_t* b) {
    asm volatile(
        "mma.sync.aligned.m16n8k16.row.col.f32.f16.f16.f32 "
        "{%0,%1,%2,%3}, {%4,%5,%6,%7}, {%8,%9}, {%0,%1,%2,%3};"
        : "+f"(c[0]), "+f"(c[1]), "+f"(c[2]), "+f"(c[3])
        : "r"(a[0]), "r"(a[1]), "r"(a[2]), "r"(a[3]), "r"(b[0]), "r"(b[1]));
}
__device__ __forceinline__ uint32_t packh2(float a, float b) {
    __half2 h = __floats2half2_rn(a, b);
    return *(uint32_t*)&h;
}
__device__ __forceinline__ float fexp2(float t) {   // fast 2^t, t<=0
    t = fmaxf(t, -126.0f);
    const float mag = 12582912.0f;
    float r = t + mag;
    uint32_t ui = __float_as_uint(r);
    float f = t - (r - mag);
    float p = 1.3333558146e-3f;
    p = fmaf(p, f, 9.6181291076e-3f);
    p = fmaf(p, f, 5.5504108664e-2f);
    p = fmaf(p, f, 2.4022650696e-1f);
    p = fmaf(p, f, 6.9314718056e-1f);
    p = fmaf(p, f, 1.0f);
    return __uint_as_float(__float_as_uint(p) + (ui << 23));
}

// ==================== fp16 GEMM: 128x128 CTA, 64x32 warp tile, 2 CTA/SM ===
// 8 warps (2x4), BK=32, 3-stage cp.async, regs capped for 2 CTAs/SM.
// OUT: 0 = fp32 (+res), 2 = single fp16.
#define GT       256
#define GA3      10240               // 128 x 80B
#define GB3      8704                // 32 x 272B
#define GSTG     (GA3 + GB3)         // 18944
#define GEMM_SMEM (3 * GSTG)         // 56832

template<bool BIAS, bool RELU, bool RES, int OUT>
__global__ void __launch_bounds__(GT, 2) gemm16(
    const __half* __restrict__ A, const __half* __restrict__ B,
    const float* __restrict__ bias, const float* __restrict__ res,
    float* __restrict__ Cf, __half* __restrict__ Ch,
    int N, int K)
{
    extern __shared__ char sm[];
    const uint32_t sb = smem_u32(sm);
    const int tid = threadIdx.x, lane = tid & 31, wid = tid >> 5;
    const int wm = (wid >> 2) * 64, wn = (wid & 3) * 32;
    const int m0 = blockIdx.y * 128, n0 = blockIdx.x * 128;

    auto load_stage = [&](int s, int c) {
        const int kc = c << 5;
        const uint32_t st = sb + (uint32_t)s * GSTG;
        // A: 128 rows x 64B = 512 cp16; thread: row=tid/2, segs {2*(tid&1), +1}
        const int row = tid >> 1, sg0 = (tid & 1) << 1;
        const size_t g = (size_t)(m0 + row) * K + kc + sg0 * 8;
        const uint32_t so = st + row * 80 + sg0 * 16;
        cp16(so,      A + g);
        cp16(so + 16, A + g + 8);
        // B: 32 rows x 256B = 512 cp16; thread: rows {tid/16, +16}, seg tid%16
        const int br = tid >> 4, seg = tid & 15;
        const size_t gb = (size_t)(kc + br) * N + n0 + seg * 8;
        const uint32_t sob = st + GA3 + br * 272 + seg * 16;
        cp16(sob, B + gb);
        cp16(sob + 16 * 272, B + gb + (size_t)16 * N);
    };

    float acc[4][4][4];
    #pragma unroll
    for (int a = 0; a < 4; a++)
        #pragma unroll
        for (int b = 0; b < 4; b++)
            #pragma unroll
            for (int d = 0; d < 4; d++) acc[a][b][d] = 0.f;

    const int NC = K >> 5;
    load_stage(0, 0); cp_commit();
    load_stage(1, 1); cp_commit();
    load_stage(2, 2); cp_commit();

    for (int c = 0; c < NC; c++) {
        const int s = c % 3;
        if (c + 2 < NC)      cp_wait<2>();
        else if (c + 1 < NC) cp_wait<1>();
        else                 cp_wait<0>();
        __syncthreads();

        const uint32_t aoff = sb + (uint32_t)s * GSTG;
        const uint32_t boff = aoff + GA3;
        #pragma unroll
        for (int ks = 0; ks < 2; ks++) {
            uint32_t bfr[4][2];
            #pragma unroll
            for (int ntp = 0; ntp < 2; ntp++) {
                uint32_t r[4];
                ldsm_x4t(r, boff + (ks * 16 + (lane & 15)) * 272
                              + (wn + ntp * 16 + ((lane >> 4) << 3)) * 2);
                bfr[2*ntp][0] = r[0]; bfr[2*ntp][1] = r[1];
                bfr[2*ntp+1][0] = r[2]; bfr[2*ntp+1][1] = r[3];
            }
            #pragma unroll
            for (int mt = 0; mt < 4; mt++) {
                uint32_t ah[4];
                ldsm_x4(ah, aoff + (wm + mt * 16 + (lane & 15)) * 80
                              + ks * 32 + ((lane >> 4) << 4));
                #pragma unroll
                for (int nt = 0; nt < 4; nt++)
                    mma_f16(acc[mt][nt], ah, bfr[nt]);
            }
        }
        __syncthreads();
        if (c + 3 < NC) { load_stage(s, c + 3); cp_commit(); }
    }

    #pragma unroll
    for (int mt = 0; mt < 4; mt++)
        #pragma unroll
        for (int nt = 0; nt < 4; nt++)
            #pragma unroll
            for (int hf = 0; hf < 2; hf++) {
                const int row = m0 + wm + mt * 16 + (lane >> 2) + hf * 8;
                const int col = n0 + wn + nt * 8 + (lane & 3) * 2;
                float v0 = acc[mt][nt][hf * 2 + 0];
                float v1 = acc[mt][nt][hf * 2 + 1];
                if (BIAS) { v0 += bias[col]; v1 += bias[col + 1]; }
                if (RELU) { v0 = fmaxf(v0, 0.f); v1 = fmaxf(v1, 0.f); }
                if (RES) {
                    const float2 rr = *(const float2*)&res[(size_t)row * N + col];
                    v0 += rr.x; v1 += rr.y;
                }
                if (OUT == 2) {
                    *(uint32_t*)&Ch[(size_t)row * N + col] = packh2(v0, v1);
                } else {
                    float2 o; o.x = v0; o.y = v1;
                    *(float2*)&Cf[(size_t)row * N + col] = o;
                }
            }
}

// ==================== weight converts ====================
__global__ void __launch_bounds__(256) wconv_kernel(
    const float* __restrict__ w, __half* __restrict__ o, int n4)
{
    for (int i = blockIdx.x * blockDim.x + threadIdx.x; i < n4;
         i += gridDim.x * blockDim.x) {
        const float4 v = ((const float4*)w)[i];
        const __half2 a = __floats2half2_rn(v.x, v.y);
        const __half2 b = __floats2half2_rn(v.z, v.w);
        uint2 u; u.x = *(const uint32_t*)&a; u.y = *(const uint32_t*)&b;
        *(uint2*)&o[(size_t)i * 4] = u;
    }
}
// fused QKV weight convert: z = 0/1/2 selects Wq/Wk/Wv -> columns of Wqkv
__global__ void __launch_bounds__(256) wconv_qkv_kernel(
    const float* __restrict__ Wq, const float* __restrict__ Wk,
    const float* __restrict__ Wv, __half* __restrict__ dst)
{
    const int z = blockIdx.z;
    const float* w = (z == 0) ? Wq : (z == 1) ? Wk : Wv;
    const int coff = z * CDIM;
    const int idx = blockIdx.x * blockDim.x + threadIdx.x;
    const int row = idx >> 7;
    const int g8  = idx & 127;
    const float4 v0 = *(const float4*)&w[(size_t)row * CDIM + g8 * 8];
    const float4 v1 = *(const float4*)&w[(size_t)row * CDIM + g8 * 8 + 4];
    uint4 u;
    u.x = packh2(v0.x, v0.y); u.y = packh2(v0.z, v0.w);
    u.z = packh2(v1.x, v1.y); u.w = packh2(v1.z, v1.w);
    *(uint4*)&dst[(size_t)row * C3 + coff + g8 * 8] = u;
}

// ==================== LayerNorm -> single fp16 ====================
__inline__ __device__ float warp_sum(float v) {
    #pragma unroll
    for (int m = 16; m > 0; m >>= 1) v += __shfl_xor_sync(0xffffffffu, v, m);
    return v;
}
__global__ void __launch_bounds__(256) layernorm_h_kernel(
    const float* __restrict__ x, const float* __restrict__ g,
    const float* __restrict__ bt, __half* __restrict__ y)
{
    const int row = blockIdx.x, tid = threadIdx.x;
    const float4 v = ((const float4*)(x + (size_t)row * CDIM))[tid];
    float s  = v.x + v.y + v.z + v.w;
    float ss = v.x*v.x + v.y*v.y + v.z*v.z + v.w*v.w;
    __shared__ float sh1[8], sh2[8];
    s = warp_sum(s); ss = warp_sum(ss);
    const int w = tid >> 5, l = tid & 31;
    if (l == 0) { sh1[w] = s; sh2[w] = ss; }
    __syncthreads();
    if (w == 0) {
        float a = (l < 8) ? sh1[l] : 0.f;
        float b = (l < 8) ? sh2[l] : 0.f;
        a = warp_sum(a); b = warp_sum(b);
        if (l == 0) { sh1[0] = a; sh2[0] = b; }
    }
    __syncthreads();
    const float mean = sh1[0] * (1.0f / CDIM);
    const float var  = sh2[0] * (1.0f / CDIM) - mean * mean;
    const float inv  = rsqrtf(var + 1e-5f);
    const float4 gv = ((const float4*)g)[tid];
    const float4 bv = ((const float4*)bt)[tid];
    uint2 u;
    u.x = packh2((v.x - mean) * inv * gv.x + bv.x,
                 (v.y - mean) * inv * gv.y + bv.y);
    u.y = packh2((v.z - mean) * inv * gv.z + bv.z,
                 (v.w - mean) * inv * gv.w + bv.w);
    *(uint2*)&y[(size_t)row * CDIM + tid * 4] = u;
}

// ==================== tensor-core flash attention (pure fp16) ============
#define FA_QS     18432                 // 128 x 144B
#define FA_KV     9216                  // 64 x 144B
#define FA_STAGE  18432                 // K, V
#define FA_SMEM   (FA_QS + 2 * FA_STAGE)   // 55296

__global__ void __launch_bounds__(256, 1) flash16_kernel(
    const __half* __restrict__ QKV, __half* __restrict__ O)
{
    extern __shared__ char sm[];
    const uint32_t sb = smem_u32(sm);
    const int tid = threadIdx.x, lane = tid & 31, wid = tid >> 5;
    const int qt = gridDim.x - 1 - blockIdx.x;
    const int hh = blockIdx.y, bb = blockIdx.z;
    const int rowbase = bb * TSEQ + qt * 128;
    const int colC = hh * DHEAD;

    auto loadKV = [&](int s, int kt) {
        #pragma unroll
        for (int i = 0; i < 4; i++) {
            const int c = tid + i * 256;
            const int arr = c >> 9;          // 0 K, 1 V
            const int r = (c >> 3) & 63;
            const int seg = c & 7;
            const __half* src = QKV
                + (size_t)(bb * TSEQ + kt * 64 + r) * C3
                + (arr == 0 ? CDIM : 2 * CDIM) + colC + seg * 8;
            cp16(sb + FA_QS + (uint32_t)s * FA_STAGE + arr * FA_KV
                 + r * 144 + seg * 16, src);
        }
    };

    #pragma unroll
    for (int i = 0; i < 2; i++) {
        const int c = tid + i * 256;
        const int r = c >> 2;
        const int seg = c & 3;
        const __half* src = QKV + (size_t)(rowbase + r) * C3 + colC + seg * 16;
        cp16(sb + r * 144 + seg * 32, src);
        cp16(sb + r * 144 + seg * 32 + 16, src + 8);
    }
    cp_commit();
    loadKV(0, 0);
    cp_commit();
    cp_wait<0>();
    __syncthreads();

    uint32_t qh[4][4];
    #pragma unroll
    for (int kf = 0; kf < 4; kf++) {
        const uint32_t qa = sb + (wid * 16 + (lane & 15)) * 144
                               + (kf * 16 + ((lane >> 4) << 3)) * 2;
        ldsm_x4(qh[kf], qa);
    }

    float o[8][4];
    #pragma unroll
    for (int i = 0; i < 8; i++)
        #pragma unroll
        for (int j = 0; j < 4; j++) o[i][j] = 0.f;
    float m0 = -1e30f, m1 = -1e30f, l0 = 0.f, l1 = 0.f;

    const int ktlast = 2 * qt + 1;
    const float SCALE = 0.18033688011112042f;   // 0.125 * log2(e)

    for (int kt = 0; kt <= ktlast; kt++) {
        const int s = kt & 1;
        if (kt < ktlast) { loadKV(s ^ 1, kt + 1); cp_commit(); cp_wait<1>(); }
        else             cp_wait<0>();
        __syncthreads();

        const uint32_t kb = sb + FA_QS + (uint32_t)s * FA_STAGE;
        const uint32_t vb = kb + FA_KV;

        float c[8][4];
        #pragma unroll
        for (int i = 0; i < 8; i++)
            #pragma unroll
            for (int j = 0; j < 4; j++) c[i][j] = 0.f;

        #pragma unroll
        for (int kf = 0; kf < 4; kf++)
            #pragma unroll
            for (int ntp = 0; ntp < 4; ntp++) {
                uint32_t bh[4];
                const uint32_t ka = (ntp * 16 + (lane & 7) + ((lane >> 4) << 3)) * 144
                                  + (kf * 16 + ((lane >> 3) & 1) * 8) * 2;
                ldsm_x4(bh, kb + ka);
                mma_f16(c[2*ntp],   qh[kf], &bh[0]);
                mma_f16(c[2*ntp+1], qh[kf], &bh[2]);
            }

        if (kt >= 2 * qt) {
            const int rg0 = qt * 128 + wid * 16 + (lane >> 2);
            const int cg0 = kt * 64 + (lane & 3) * 2;
            #pragma unroll
            for (int nt = 0; nt < 8; nt++) {
                const int cg = cg0 + nt * 8;
                #pragma unroll
                for (int j = 0; j < 4; j++) {
                    const int r  = rg0 + ((j >> 1) << 3);
                    const int cc = cg + (j & 1);
                    if (cc > r) c[nt][j] = -1e30f;
                }
            }
        }

        float mx0 = -1e30f, mx1 = -1e30f;
        #pragma unroll
        for (int nt = 0; nt < 8; nt++) {
            mx0 = fmaxf(mx0, fmaxf(c[nt][0], c[nt][1]));
            mx1 = fmaxf(mx1, fmaxf(c[nt][2], c[nt][3]));
        }
        mx0 = fmaxf(mx0, __shfl_xor_sync(0xffffffffu, mx0, 1));
        mx0 = fmaxf(mx0, __shfl_xor_sync(0xffffffffu, mx0, 2));
        mx1 = fmaxf(mx1, __shfl_xor_sync(0xffffffffu, mx1, 1));
        mx1 = fmaxf(mx1, __shfl_xor_sync(0xffffffffu, mx1, 2));

        const float nm0 = fmaxf(m0, mx0 * SCALE);
        const float nm1 = fmaxf(m1, mx1 * SCALE);
        const float al0 = fexp2(m0 - nm0);
        const float al1 = fexp2(m1 - nm1);
        m0 = nm0; m1 = nm1;

        float rs0 = 0.f, rs1 = 0.f;
        #pragma unroll
        for (int nt = 0; nt < 8; nt++) {
            float p0 = fexp2(fmaf(c[nt][0], SCALE, -nm0));
            float p1 = fexp2(fmaf(c[nt][1], SCALE, -nm0));
            float p2 = fexp2(fmaf(c[nt][2], SCALE, -nm1));
            float p3 = fexp2(fmaf(c[nt][3], SCALE, -nm1));
            c[nt][0] = p0; c[nt][1] = p1; c[nt][2] = p2; c[nt][3] = p3;
            rs0 += p0 + p1; rs1 += p2 + p3;
        }
        rs0 += __shfl_xor_sync(0xffffffffu, rs0, 1);
        rs0 += __shfl_xor_sync(0xffffffffu, rs0, 2);
        rs1 += __shfl_xor_sync(0xffffffffu, rs1, 1);
        rs1 += __shfl_xor_sync(0xffffffffu, rs1, 2);
        l0 = l0 * al0 + rs0;
        l1 = l1 * al1 + rs1;
        #pragma unroll
        for (int nt = 0; nt < 8; nt++) {
            o[nt][0] *= al0; o[nt][1] *= al0;
            o[nt][2] *= al1; o[nt][3] *= al1;
        }

        #pragma unroll
        for (int kf = 0; kf < 4; kf++) {
            uint32_t ph[4];
            ph[0] = packh2(c[2*kf][0],   c[2*kf][1]);
            ph[1] = packh2(c[2*kf][2],   c[2*kf][3]);
            ph[2] = packh2(c[2*kf+1][0], c[2*kf+1][1]);
            ph[3] = packh2(c[2*kf+1][2], c[2*kf+1][3]);
            #pragma unroll
            for (int ntp = 0; ntp < 4; ntp++) {
                uint32_t vh[4];
                const uint32_t va = (kf * 16 + (lane & 15)) * 144
                                  + (ntp * 16 + ((lane >> 4) << 3)) * 2;
                ldsm_x4t(vh, vb + va);
                mma_f16(o[2*ntp],   ph, &vh[0]);
                mma_f16(o[2*ntp+1], ph, &vh[2]);
            }
        }
        __syncthreads();
    }

    const float il0 = 1.f / l0, il1 = 1.f / l1;
    const int rg = rowbase + wid * 16 + (lane >> 2);
    #pragma unroll
    for (int nt = 0; nt < 8; nt++) {
        const int col = colC + nt * 8 + (lane & 3) * 2;
        *(uint32_t*)&O[(size_t)rg * CDIM + col] =
            packh2(o[nt][0] * il0, o[nt][1] * il0);
        *(uint32_t*)&O[(size_t)(rg + 8) * CDIM + col] =
            packh2(o[nt][2] * il1, o[nt][3] * il1);
    }
}

// ==================== launch ====================
extern "C" void kernel_launch(void* const* d_in, const int* in_sizes, int n_in,
                              void* d_out, int out_size)
{
    (void)in_sizes; (void)n_in; (void)out_size;
    const float* x    = (const float*)d_in[0];
    const float* Wq   = (const float*)d_in[1];
    const float* Wk   = (const float*)d_in[2];
    const float* Wv   = (const float*)d_in[3];
    const float* Wo   = (const float*)d_in[4];
    const float* bo   = (const float*)d_in[5];
    const float* ln1g = (const float*)d_in[6];
    const float* ln1b = (const float*)d_in[7];
    const float* ln2g = (const float*)d_in[8];
    const float* ln2b = (const float*)d_in[9];
    const float* W1   = (const float*)d_in[10];
    const float* b1   = (const float*)d_in[11];
    const float* W2   = (const float*)d_in[12];
    const float* b2   = (const float*)d_in[13];
    float* out = (float*)d_out;

    __half *h, *qkv, *a, *ff;
    float* x1;
    __half *Wqkvh, *Woh, *W1h, *W2h;
    cudaGetSymbolAddress((void**)&h,     g_h);
    cudaGetSymbolAddress((void**)&qkv,   g_qkv);
    cudaGetSymbolAddress((void**)&a,     g_a);
    cudaGetSymbolAddress((void**)&x1,    g_x1);
    cudaGetSymbolAddress((void**)&ff,    g_ff);
    cudaGetSymbolAddress((void**)&Wqkvh, g_Wqkv);
    cudaGetSymbolAddress((void**)&Woh,   g_Wo);
    cudaGetSymbolAddress((void**)&W1h,   g_W1);
    cudaGetSymbolAddress((void**)&W2h,   g_W2);

    cudaFuncSetAttribute(gemm16<false, false, false, 2>,
                         cudaFuncAttributeMaxDynamicSharedMemorySize, GEMM_SMEM);
    cudaFuncSetAttribute(gemm16<true, false, true, 0>,
                         cudaFuncAttributeMaxDynamicSharedMemorySize, GEMM_SMEM);
    cudaFuncSetAttribute(gemm16<true, true, false, 2>,
                         cudaFuncAttributeMaxDynamicSharedMemorySize, GEMM_SMEM);
    cudaFuncSetAttribute(flash16_kernel,
                         cudaFuncAttributeMaxDynamicSharedMemorySize, FA_SMEM);

    wconv_qkv_kernel<<<dim3(512, 1, 3), 256>>>(Wq, Wk, Wv, Wqkvh);
    wconv_kernel<<<512, 256>>>(Wo, Woh, CDIM * CDIM / 4);
    layernorm_h_kernel<<<MTOT, 256>>>(x, ln1g, ln1b, h);

    // fused QKV GEMM (single fp16 out)
    gemm16<false, false, false, 2><<<dim3(C3 / 128, MTOT / 128), GT, GEMM_SMEM>>>(
        h, Wqkvh, nullptr, nullptr, nullptr, qkv, C3, CDIM);
    // attention (pure fp16 q/k/v)
    flash16_kernel<<<dim3(TSEQ / 128, HEADS, BB), 256, FA_SMEM>>>(qkv, a);
    // FFN weight converts
    wconv_kernel<<<1024, 256>>>(W1, W1h, CDIM * FDIM / 4);
    wconv_kernel<<<1024, 256>>>(W2, W2h, FDIM * CDIM / 4);
    // x1 = x + attn @ Wo + bo
    gemm16<true, false, true, 0><<<dim3(CDIM / 128, MTOT / 128), GT, GEMM_SMEM>>>(
        a, Woh, bo, x, x1, nullptr, CDIM, CDIM);
    // LN2
    layernorm_h_kernel<<<MTOT, 256>>>(x1, ln2g, ln2b, h);
    // ff = relu(h @ W1 + b1)
    gemm16<true, true, false, 2><<<dim3(FDIM / 128, MTOT / 128), GT, GEMM_SMEM>>>(
        h, W1h, b1, nullptr, nullptr, ff, FDIM, CDIM);
    // out = x1 + ff @ W2 + b2
    gemm16<true, false, true, 0><<<dim3(CDIM / 128, MTOT / 128), GT, GEMM_SMEM>>>(
        ff, W2h, b2, x1, out, nullptr, CDIM, FDIM);
}

// round 12
// speedup vs baseline: 3.6954x; 1.0239x over previous
#include <cuda_runtime.h>
#include <cuda_fp16.h>
#include <cstdint>
#include <math.h>

#define BB    4
#define TSEQ  2048
#define CDIM  1024
#define HEADS 16
#define DHEAD 64
#define MTOT  (BB * TSEQ)
#define FDIM  (4 * CDIM)
#define C3    (3 * CDIM)

// -------- scratch (device globals) --------
__device__ __half g_h   [MTOT * CDIM];
__device__ __half g_qkv [MTOT * C3];
__device__ __half g_a   [MTOT * CDIM];
__device__ float  g_x1  [MTOT * CDIM];
__device__ __half g_ff  [MTOT * FDIM];
__device__ __half g_Wqkv[CDIM * C3];
__device__ __half g_Wo[CDIM * CDIM];
__device__ __half g_W1[CDIM * FDIM], g_W2[FDIM * CDIM];

// -------- PTX helpers (plain sm_80+ only) --------
__device__ __forceinline__ uint32_t smem_u32(const void* p) {
    uint32_t a;
    asm("{ .reg .u64 t; cvta.to.shared.u64 t, %1; cvt.u32.u64 %0, t; }" : "=r"(a) : "l"(p));
    return a;
}
__device__ __forceinline__ void cp16(uint32_t dst, const void* src) {
    asm volatile("cp.async.cg.shared.global [%0], [%1], 16;" :: "r"(dst), "l"(src));
}
__device__ __forceinline__ void cp_commit() { asm volatile("cp.async.commit_group;"); }
template<int N> __device__ __forceinline__ void cp_wait() {
    asm volatile("cp.async.wait_group %0;" :: "n"(N));
}
__device__ __forceinline__ void ldsm_x4(uint32_t* r, uint32_t a) {
    asm volatile("ldmatrix.sync.aligned.m8n8.x4.shared.b16 {%0,%1,%2,%3}, [%4];"
                 : "=r"(r[0]), "=r"(r[1]), "=r"(r[2]), "=r"(r[3]) : "r"(a));
}
__device__ __forceinline__ void ldsm_x4t(uint32_t* r, uint32_t a) {
    asm volatile("ldmatrix.sync.aligned.m8n8.x4.trans.shared.b16 {%0,%1,%2,%3}, [%4];"
                 : "=r"(r[0]), "=r"(r[1]), "=r"(r[2]), "=r"(r[3]) : "r"(a));
}
__device__ __forceinline__ void mma_f16(float* c, const uint32_t* a, const uint32_t* b) {
    asm volatile(
        "mma.sync.aligned.m16n8k16.row.col.f32.f16.f16.f32 "
        "{%0,%1,%2,%3}, {%4,%5,%6,%7}, {%8,%9}, {%0,%1,%2,%3};"
        : "+f"(c[0]), "+f"(c[1]), "+f"(c[2]), "+f"(c[3])
        : "r"(a[0]), "r"(a[1]), "r"(a[2]), "r"(a[3]), "r"(b[0]), "r"(b[1]));
}
__device__ __forceinline__ uint32_t packh2(float a, float b) {
    __half2 h = __floats2half2_rn(a, b);
    return *(uint32_t*)&h;
}
__device__ __forceinline__ float fexp2(float t) {   // fast 2^t, t<=0
    t = fmaxf(t, -126.0f);
    const float mag = 12582912.0f;
    float r = t + mag;
    uint32_t ui = __float_as_uint(r);
    float f = t - (r - mag);
    float p = 1.3333558146e-3f;
    p = fmaf(p, f, 9.6181291076e-3f);
    p = fmaf(p, f, 5.5504108664e-2f);
    p = fmaf(p, f, 2.4022650696e-1f);
    p = fmaf(p, f, 6.9314718056e-1f);
    p = fmaf(p, f, 1.0f);
    return __uint_as_float(__float_as_uint(p) + (ui << 23));
}

// ==================== fp16 GEMM: 128x128 CTA, 64x32 warp tile =============
// 8 warps (2x4), BK=32, 4-stage cp.async, 2 CTAs/SM, ONE barrier per chunk.
// OUT: 0 = fp32 (+res), 2 = single fp16.
#define GT       256
#define GA3      10240               // 128 x 80B
#define GB3      8704                // 32 x 272B
#define GSTG     (GA3 + GB3)         // 18944
#define GEMM_SMEM (4 * GSTG)         // 75776

template<bool BIAS, bool RELU, bool RES, int OUT>
__global__ void __launch_bounds__(GT, 2) gemm16(
    const __half* __restrict__ A, const __half* __restrict__ B,
    const float* __restrict__ bias, const float* __restrict__ res,
    float* __restrict__ Cf, __half* __restrict__ Ch,
    int N, int K)
{
    extern __shared__ char sm[];
    const uint32_t sb = smem_u32(sm);
    const int tid = threadIdx.x, lane = tid & 31, wid = tid >> 5;
    const int wm = (wid >> 2) * 64, wn = (wid & 3) * 32;
    const int m0 = blockIdx.y * 128, n0 = blockIdx.x * 128;

    auto load_stage = [&](int s, int c) {
        const int kc = c << 5;
        const uint32_t st = sb + (uint32_t)s * GSTG;
        const int row = tid >> 1, sg0 = (tid & 1) << 1;
        const size_t g = (size_t)(m0 + row) * K + kc + sg0 * 8;
        const uint32_t so = st + row * 80 + sg0 * 16;
        cp16(so,      A + g);
        cp16(so + 16, A + g + 8);
        const int br = tid >> 4, seg = tid & 15;
        const size_t gb = (size_t)(kc + br) * N + n0 + seg * 8;
        const uint32_t sob = st + GA3 + br * 272 + seg * 16;
        cp16(sob, B + gb);
        cp16(sob + 16 * 272, B + gb + (size_t)16 * N);
    };

    float acc[4][4][4];
    #pragma unroll
    for (int a = 0; a < 4; a++)
        #pragma unroll
        for (int b = 0; b < 4; b++)
            #pragma unroll
            for (int d = 0; d < 4; d++) acc[a][b][d] = 0.f;

    const int NC = K >> 5;
    load_stage(0, 0); cp_commit();
    load_stage(1, 1); cp_commit();
    load_stage(2, 2); cp_commit();

    for (int c = 0; c < NC; c++) {
        const int s = c & 3;
        if (c + 2 < NC)      cp_wait<2>();
        else if (c + 1 < NC) cp_wait<1>();
        else                 cp_wait<0>();
        __syncthreads();
        // prefetch into (c+3)&3 — that stage's compute ended at c-1, protected
        // by the barrier above (all warps have passed compute c-1).
        if (c + 3 < NC) { load_stage((c + 3) & 3, c + 3); cp_commit(); }

        const uint32_t aoff = sb + (uint32_t)s * GSTG;
        const uint32_t boff = aoff + GA3;
        #pragma unroll
        for (int ks = 0; ks < 2; ks++) {
            uint32_t bfr[4][2];
            #pragma unroll
            for (int ntp = 0; ntp < 2; ntp++) {
                uint32_t r[4];
                ldsm_x4t(r, boff + (ks * 16 + (lane & 15)) * 272
                              + (wn + ntp * 16 + ((lane >> 4) << 3)) * 2);
                bfr[2*ntp][0] = r[0]; bfr[2*ntp][1] = r[1];
                bfr[2*ntp+1][0] = r[2]; bfr[2*ntp+1][1] = r[3];
            }
            #pragma unroll
            for (int mt = 0; mt < 4; mt++) {
                uint32_t ah[4];
                ldsm_x4(ah, aoff + (wm + mt * 16 + (lane & 15)) * 80
                              + ks * 32 + ((lane >> 4) << 4));
                #pragma unroll
                for (int nt = 0; nt < 4; nt++)
                    mma_f16(acc[mt][nt], ah, bfr[nt]);
            }
        }
    }

    __syncthreads();   // last compute stage done before epilogue reuses nothing; keep for safety
    #pragma unroll
    for (int mt = 0; mt < 4; mt++)
        #pragma unroll
        for (int nt = 0; nt < 4; nt++)
            #pragma unroll
            for (int hf = 0; hf < 2; hf++) {
                const int row = m0 + wm + mt * 16 + (lane >> 2) + hf * 8;
                const int col = n0 + wn + nt * 8 + (lane & 3) * 2;
                float v0 = acc[mt][nt][hf * 2 + 0];
                float v1 = acc[mt][nt][hf * 2 + 1];
                if (BIAS) { v0 += bias[col]; v1 += bias[col + 1]; }
                if (RELU) { v0 = fmaxf(v0, 0.f); v1 = fmaxf(v1, 0.f); }
                if (RES) {
                    const float2 rr = *(const float2*)&res[(size_t)row * N + col];
                    v0 += rr.x; v1 += rr.y;
                }
                if (OUT == 2) {
                    *(uint32_t*)&Ch[(size_t)row * N + col] = packh2(v0, v1);
                } else {
                    float2 o; o.x = v0; o.y = v1;
                    *(float2*)&Cf[(size_t)row * N + col] = o;
                }
            }
}

// ==================== weight converts ====================
__global__ void __launch_bounds__(256) wconv_kernel(
    const float* __restrict__ w, __half* __restrict__ o, int n4)
{
    for (int i = blockIdx.x * blockDim.x + threadIdx.x; i < n4;
         i += gridDim.x * blockDim.x) {
        const float4 v = ((const float4*)w)[i];
        const __half2 a = __floats2half2_rn(v.x, v.y);
        const __half2 b = __floats2half2_rn(v.z, v.w);
        uint2 u; u.x = *(const uint32_t*)&a; u.y = *(const uint32_t*)&b;
        *(uint2*)&o[(size_t)i * 4] = u;
    }
}
__global__ void __launch_bounds__(256) wconv_qkv_kernel(
    const float* __restrict__ Wq, const float* __restrict__ Wk,
    const float* __restrict__ Wv, __half* __restrict__ dst)
{
    const int z = blockIdx.z;
    const float* w = (z == 0) ? Wq : (z == 1) ? Wk : Wv;
    const int coff = z * CDIM;
    const int idx = blockIdx.x * blockDim.x + threadIdx.x;
    const int row = idx >> 7;
    const int g8  = idx & 127;
    const float4 v0 = *(const float4*)&w[(size_t)row * CDIM + g8 * 8];
    const float4 v1 = *(const float4*)&w[(size_t)row * CDIM + g8 * 8 + 4];
    uint4 u;
    u.x = packh2(v0.x, v0.y); u.y = packh2(v0.z, v0.w);
    u.z = packh2(v1.x, v1.y); u.w = packh2(v1.z, v1.w);
    *(uint4*)&dst[(size_t)row * C3 + coff + g8 * 8] = u;
}

// ==================== LayerNorm -> single fp16 ====================
__inline__ __device__ float warp_sum(float v) {
    #pragma unroll
    for (int m = 16; m > 0; m >>= 1) v += __shfl_xor_sync(0xffffffffu, v, m);
    return v;
}
__global__ void __launch_bounds__(256) layernorm_h_kernel(
    const float* __restrict__ x, const float* __restrict__ g,
    const float* __restrict__ bt, __half* __restrict__ y)
{
    const int row = blockIdx.x, tid = threadIdx.x;
    const float4 v = ((const float4*)(x + (size_t)row * CDIM))[tid];
    float s  = v.x + v.y + v.z + v.w;
    float ss = v.x*v.x + v.y*v.y + v.z*v.z + v.w*v.w;
    __shared__ float sh1[8], sh2[8];
    s = warp_sum(s); ss = warp_sum(ss);
    const int w = tid >> 5, l = tid & 31;
    if (l == 0) { sh1[w] = s; sh2[w] = ss; }
    __syncthreads();
    if (w == 0) {
        float a = (l < 8) ? sh1[l] : 0.f;
        float b = (l < 8) ? sh2[l] : 0.f;
        a = warp_sum(a); b = warp_sum(b);
        if (l == 0) { sh1[0] = a; sh2[0] = b; }
    }
    __syncthreads();
    const float mean = sh1[0] * (1.0f / CDIM);
    const float var  = sh2[0] * (1.0f / CDIM) - mean * mean;
    const float inv  = rsqrtf(var + 1e-5f);
    const float4 gv = ((const float4*)g)[tid];
    const float4 bv = ((const float4*)bt)[tid];
    uint2 u;
    u.x = packh2((v.x - mean) * inv * gv.x + bv.x,
                 (v.y - mean) * inv * gv.y + bv.y);
    u.y = packh2((v.z - mean) * inv * gv.z + bv.z,
                 (v.w - mean) * inv * gv.w + bv.w);
    *(uint2*)&y[(size_t)row * CDIM + tid * 4] = u;
}

// ==================== tensor-core flash attention (pure fp16) ============
#define FA_QS     18432                 // 128 x 144B
#define FA_KV     9216                  // 64 x 144B
#define FA_STAGE  18432                 // K, V
#define FA_SMEM   (FA_QS + 2 * FA_STAGE)   // 55296

__global__ void __launch_bounds__(256, 2) flash16_kernel(
    const __half* __restrict__ QKV, __half* __restrict__ O)
{
    extern __shared__ char sm[];
    const uint32_t sb = smem_u32(sm);
    const int tid = threadIdx.x, lane = tid & 31, wid = tid >> 5;
    const int qt = gridDim.x - 1 - blockIdx.x;
    const int hh = blockIdx.y, bb = blockIdx.z;
    const int rowbase = bb * TSEQ + qt * 128;
    const int colC = hh * DHEAD;

    auto loadKV = [&](int s, int kt) {
        #pragma unroll
        for (int i = 0; i < 4; i++) {
            const int c = tid + i * 256;
            const int arr = c >> 9;          // 0 K, 1 V
            const int r = (c >> 3) & 63;
            const int seg = c & 7;
            const __half* src = QKV
                + (size_t)(bb * TSEQ + kt * 64 + r) * C3
                + (arr == 0 ? CDIM : 2 * CDIM) + colC + seg * 8;
            cp16(sb + FA_QS + (uint32_t)s * FA_STAGE + arr * FA_KV
                 + r * 144 + seg * 16, src);
        }
    };

    #pragma unroll
    for (int i = 0; i < 2; i++) {
        const int c = tid + i * 256;
        const int r = c >> 2;
        const int seg = c & 3;
        const __half* src = QKV + (size_t)(rowbase + r) * C3 + colC + seg * 16;
        cp16(sb + r * 144 + seg * 32, src);
        cp16(sb + r * 144 + seg * 32 + 16, src + 8);
    }
    cp_commit();
    loadKV(0, 0);
    cp_commit();
    cp_wait<0>();
    __syncthreads();

    uint32_t qh[4][4];
    #pragma unroll
    for (int kf = 0; kf < 4; kf++) {
        const uint32_t qa = sb + (wid * 16 + (lane & 15)) * 144
                               + (kf * 16 + ((lane >> 4) << 3)) * 2;
        ldsm_x4(qh[kf], qa);
    }

    float o[8][4];
    #pragma unroll
    for (int i = 0; i < 8; i++)
        #pragma unroll
        for (int j = 0; j < 4; j++) o[i][j] = 0.f;
    float m0 = -1e30f, m1 = -1e30f, l0 = 0.f, l1 = 0.f;

    const int ktlast = 2 * qt + 1;
    const float SCALE = 0.18033688011112042f;   // 0.125 * log2(e)

    for (int kt = 0; kt <= ktlast; kt++) {
        const int s = kt & 1;
        if (kt < ktlast) { loadKV(s ^ 1, kt + 1); cp_commit(); cp_wait<1>(); }
        else             cp_wait<0>();
        __syncthreads();

        const uint32_t kb = sb + FA_QS + (uint32_t)s * FA_STAGE;
        const uint32_t vb = kb + FA_KV;

        float c[8][4];
        #pragma unroll
        for (int i = 0; i < 8; i++)
            #pragma unroll
            for (int j = 0; j < 4; j++) c[i][j] = 0.f;

        #pragma unroll
        for (int kf = 0; kf < 4; kf++)
            #pragma unroll
            for (int ntp = 0; ntp < 4; ntp++) {
                uint32_t bh[4];
                const uint32_t ka = (ntp * 16 + (lane & 7) + ((lane >> 4) << 3)) * 144
                                  + (kf * 16 + ((lane >> 3) & 1) * 8) * 2;
                ldsm_x4(bh, kb + ka);
                mma_f16(c[2*ntp],   qh[kf], &bh[0]);
                mma_f16(c[2*ntp+1], qh[kf], &bh[2]);
            }

        if (kt >= 2 * qt) {
            const int rg0 = qt * 128 + wid * 16 + (lane >> 2);
            const int cg0 = kt * 64 + (lane & 3) * 2;
            #pragma unroll
            for (int nt = 0; nt < 8; nt++) {
                const int cg = cg0 + nt * 8;
                #pragma unroll
                for (int j = 0; j < 4; j++) {
                    const int r  = rg0 + ((j >> 1) << 3);
                    const int cc = cg + (j & 1);
                    if (cc > r) c[nt][j] = -1e30f;
                }
            }
        }

        float mx0 = -1e30f, mx1 = -1e30f;
        #pragma unroll
        for (int nt = 0; nt < 8; nt++) {
            mx0 = fmaxf(mx0, fmaxf(c[nt][0], c[nt][1]));
            mx1 = fmaxf(mx1, fmaxf(c[nt][2], c[nt][3]));
        }
        mx0 = fmaxf(mx0, __shfl_xor_sync(0xffffffffu, mx0, 1));
        mx0 = fmaxf(mx0, __shfl_xor_sync(0xffffffffu, mx0, 2));
        mx1 = fmaxf(mx1, __shfl_xor_sync(0xffffffffu, mx1, 1));
        mx1 = fmaxf(mx1, __shfl_xor_sync(0xffffffffu, mx1, 2));

        const float nm0 = fmaxf(m0, mx0 * SCALE);
        const float nm1 = fmaxf(m1, mx1 * SCALE);
        const float al0 = fexp2(m0 - nm0);
        const float al1 = fexp2(m1 - nm1);
        m0 = nm0; m1 = nm1;

        float rs0 = 0.f, rs1 = 0.f;
        #pragma unroll
        for (int nt = 0; nt < 8; nt++) {
            float p0 = fexp2(fmaf(c[nt][0], SCALE, -nm0));
            float p1 = fexp2(fmaf(c[nt][1], SCALE, -nm0));
            float p2 = fexp2(fmaf(c[nt][2], SCALE, -nm1));
            float p3 = fexp2(fmaf(c[nt][3], SCALE, -nm1));
            c[nt][0] = p0; c[nt][1] = p1; c[nt][2] = p2; c[nt][3] = p3;
            rs0 += p0 + p1; rs1 += p2 + p3;
        }
        rs0 += __shfl_xor_sync(0xffffffffu, rs0, 1);
        rs0 += __shfl_xor_sync(0xffffffffu, rs0, 2);
        rs1 += __shfl_xor_sync(0xffffffffu, rs1, 1);
        rs1 += __shfl_xor_sync(0xffffffffu, rs1, 2);
        l0 = l0 * al0 + rs0;
        l1 = l1 * al1 + rs1;
        #pragma unroll
        for (int nt = 0; nt < 8; nt++) {
            o[nt][0] *= al0; o[nt][1] *= al0;
            o[nt][2] *= al1; o[nt][3] *= al1;
        }

        #pragma unroll
        for (int kf = 0; kf < 4; kf++) {
            uint32_t ph[4];
            ph[0] = packh2(c[2*kf][0],   c[2*kf][1]);
            ph[1] = packh2(c[2*kf][2],   c[2*kf][3]);
            ph[2] = packh2(c[2*kf+1][0], c[2*kf+1][1]);
            ph[3] = packh2(c[2*kf+1][2], c[2*kf+1][3]);
            #pragma unroll
            for (int ntp = 0; ntp < 4; ntp++) {
                uint32_t vh[4];
                const uint32_t va = (kf * 16 + (lane & 15)) * 144
                                  + (ntp * 16 + ((lane >> 4) << 3)) * 2;
                ldsm_x4t(vh, vb + va);
                mma_f16(o[2*ntp],   ph, &vh[0]);
                mma_f16(o[2*ntp+1], ph, &vh[2]);
            }
        }
        __syncthreads();
    }

    const float il0 = 1.f / l0, il1 = 1.f / l1;
    const int rg = rowbase + wid * 16 + (lane >> 2);
    #pragma unroll
    for (int nt = 0; nt < 8; nt++) {
        const int col = colC + nt * 8 + (lane & 3) * 2;
        *(uint32_t*)&O[(size_t)rg * CDIM + col] =
            packh2(o[nt][0] * il0, o[nt][1] * il0);
        *(uint32_t*)&O[(size_t)(rg + 8) * CDIM + col] =
            packh2(o[nt][2] * il1, o[nt][3] * il1);
    }
}

// ==================== launch ====================
extern "C" void kernel_launch(void* const* d_in, const int* in_sizes, int n_in,
                              void* d_out, int out_size)
{
    (void)in_sizes; (void)n_in; (void)out_size;
    const float* x    = (const float*)d_in[0];
    const float* Wq   = (const float*)d_in[1];
    const float* Wk   = (const float*)d_in[2];
    const float* Wv   = (const float*)d_in[3];
    const float* Wo   = (const float*)d_in[4];
    const float* bo   = (const float*)d_in[5];
    const float* ln1g = (const float*)d_in[6];
    const float* ln1b = (const float*)d_in[7];
    const float* ln2g = (const float*)d_in[8];
    const float* ln2b = (const float*)d_in[9];
    const float* W1   = (const float*)d_in[10];
    const float* b1   = (const float*)d_in[11];
    const float* W2   = (const float*)d_in[12];
    const float* b2   = (const float*)d_in[13];
    float* out = (float*)d_out;

    __half *h, *qkv, *a, *ff;
    float* x1;
    __half *Wqkvh, *Woh, *W1h, *W2h;
    cudaGetSymbolAddress((void**)&h,     g_h);
    cudaGetSymbolAddress((void**)&qkv,   g_qkv);
    cudaGetSymbolAddress((void**)&a,     g_a);
    cudaGetSymbolAddress((void**)&x1,    g_x1);
    cudaGetSymbolAddress((void**)&ff,    g_ff);
    cudaGetSymbolAddress((void**)&Wqkvh, g_Wqkv);
    cudaGetSymbolAddress((void**)&Woh,   g_Wo);
    cudaGetSymbolAddress((void**)&W1h,   g_W1);
    cudaGetSymbolAddress((void**)&W2h,   g_W2);

    static cudaStream_t sside = nullptr;
    static cudaEvent_t evFork = nullptr, evQkvW = nullptr, evWoW = nullptr, evFFNW = nullptr;
    if (!sside) {
        cudaStreamCreateWithFlags(&sside, cudaStreamNonBlocking);
        cudaEventCreateWithFlags(&evFork, cudaEventDisableTiming);
        cudaEventCreateWithFlags(&evQkvW, cudaEventDisableTiming);
        cudaEventCreateWithFlags(&evWoW,  cudaEventDisableTiming);
        cudaEventCreateWithFlags(&evFFNW, cudaEventDisableTiming);
        cudaFuncSetAttribute(gemm16<false, false, false, 2>,
                             cudaFuncAttributeMaxDynamicSharedMemorySize, GEMM_SMEM);
        cudaFuncSetAttribute(gemm16<true, false, true, 0>,
                             cudaFuncAttributeMaxDynamicSharedMemorySize, GEMM_SMEM);
        cudaFuncSetAttribute(gemm16<true, true, false, 2>,
                             cudaFuncAttributeMaxDynamicSharedMemorySize, GEMM_SMEM);
        cudaFuncSetAttribute(flash16_kernel,
                             cudaFuncAttributeMaxDynamicSharedMemorySize, FA_SMEM);
    }

    // ---- fork: weight converts run on the side stream ----
    cudaEventRecord(evFork, 0);
    cudaStreamWaitEvent(sside, evFork, 0);
    wconv_qkv_kernel<<<dim3(512, 1, 3), 256, 0, sside>>>(Wq, Wk, Wv, Wqkvh);
    cudaEventRecord(evQkvW, sside);
    wconv_kernel<<<512, 256, 0, sside>>>(Wo, Woh, CDIM * CDIM / 4);
    cudaEventRecord(evWoW, sside);
    wconv_kernel<<<1024, 256, 0, sside>>>(W1, W1h, CDIM * FDIM / 4);
    wconv_kernel<<<1024, 256, 0, sside>>>(W2, W2h, FDIM * CDIM / 4);
    cudaEventRecord(evFFNW, sside);

    // ---- main stream ----
    layernorm_h_kernel<<<MTOT, 256>>>(x, ln1g, ln1b, h);

    cudaStreamWaitEvent(0, evQkvW, 0);
    gemm16<false, false, false, 2><<<dim3(C3 / 128, MTOT / 128), GT, GEMM_SMEM>>>(
        h, Wqkvh, nullptr, nullptr, nullptr, qkv, C3, CDIM);
    flash16_kernel<<<dim3(TSEQ / 128, HEADS, BB), 256, FA_SMEM>>>(qkv, a);

    cudaStreamWaitEvent(0, evWoW, 0);
    gemm16<true, false, true, 0><<<dim3(CDIM / 128, MTOT / 128), GT, GEMM_SMEM>>>(
        a, Woh, bo, x, x1, nullptr, CDIM, CDIM);
    layernorm_h_kernel<<<MTOT, 256>>>(x1, ln2g, ln2b, h);

    cudaStreamWaitEvent(0, evFFNW, 0);
    gemm16<true, true, false, 2><<<dim3(FDIM / 128, MTOT / 128), GT, GEMM_SMEM>>>(
        h, W1h, b1, nullptr, nullptr, ff, FDIM, CDIM);
    gemm16<true, false, true, 0><<<dim3(CDIM / 128, MTOT / 128), GT, GEMM_SMEM>>>(
        ff, W2h, b2, x1, out, nullptr, CDIM, FDIM);
}